// round 1
// baseline (speedup 1.0000x reference)
#include <cuda_runtime.h>
#include <math.h>

// ---------------- problem constants ----------------
#define BATCH 8
#define NPTS  2048
#define KNN   32
#define EMB   512
#define MBIG  (BATCH*NPTS*KNN)   // 524288
#define MSML  (BATCH*NPTS)       // 16384
#define BN_EPS 1e-5f

// output layout (reference return order: out, idx_flat, nbrs)
#define OUT_OFF  0
#define IDX_OFF  (BATCH*EMB*NPTS)                 // 8388608
#define NBR_OFF  (IDX_OFF + BATCH*NPTS*KNN)       // 8912896

// ---------------- scratch (device globals; no allocation allowed) ---------
__device__ float g_feat[6u  * MBIG];
__device__ float g_y1  [64u * MBIG];
__device__ float g_y2  [64u * MBIG];
__device__ float g_y3  [128u* MBIG];
__device__ float g_y4  [256u* MBIG];
__device__ float g_cat [512u* MSML];
__device__ float g_y5  [512u* MSML];
__device__ float g_accS[1024];
__device__ float g_accQ[1024];
__device__ float g_scl [1024];
__device__ float g_shf [1024];

#define NEG_BIG (-1e30f)

// ---------------- zero accumulators ----------------
__global__ void zero_acc_k(float* s, float* q) {
    int i = blockIdx.x * blockDim.x + threadIdx.x;
    if (i < 1024) { s[i] = 0.f; q[i] = 0.f; }
}

// ---------------- kNN + gather + feat build ----------------
// grid: (BATCH*NPTS/IPB) blocks of 256 threads; each block handles IPB points.
#define IPB 4
__global__ void knn_kernel(const float* __restrict__ x,
                           float* __restrict__ outIdx,
                           float* __restrict__ outNbr)
{
    __shared__ float px[NPTS], py[NPTS], pz[NPTS], pxx[NPTS], dist[NPTS];
    __shared__ int   sel[KNN];
    __shared__ float wv[8];
    __shared__ int   wi[8];

    int b  = blockIdx.x / (NPTS / IPB);
    int i0 = (blockIdx.x % (NPTS / IPB)) * IPB;
    const float* xb = x + (size_t)b * 3 * NPTS;

    for (int j = threadIdx.x; j < NPTS; j += blockDim.x) {
        float a0 = xb[j], a1 = xb[NPTS + j], a2 = xb[2 * NPTS + j];
        px[j] = a0; py[j] = a1; pz[j] = a2;
        pxx[j] = a0 * a0 + a1 * a1 + a2 * a2;
    }
    __syncthreads();

    for (int ii = 0; ii < IPB; ii++) {
        int i = i0 + ii;
        float q0 = px[i], q1 = py[i], q2 = pz[i], qxx = pxx[i];

        // pairwise = (-xx_i - inner) - xx_j, inner = -2*dot  (match jax formula)
        for (int j = threadIdx.x; j < NPTS; j += blockDim.x) {
            float dot   = q0 * px[j] + q1 * py[j] + q2 * pz[j];
            float inner = -2.f * dot;
            float t     = (-qxx) - inner;
            dist[j]     = t - pxx[j];
        }
        __syncthreads();

        // iterative argmax, 32 times; ties -> smallest index (jax top_k semantics)
        for (int k = 0; k < KNN; k++) {
            float bv = NEG_BIG * 2.f; int bj = NPTS;
            for (int j = threadIdx.x; j < NPTS; j += blockDim.x) {
                float v = dist[j];
                if (v > bv) { bv = v; bj = j; }    // ascending j -> keeps smallest on tie
            }
            #pragma unroll
            for (int off = 16; off; off >>= 1) {
                float ov = __shfl_down_sync(0xffffffffu, bv, off);
                int   oj = __shfl_down_sync(0xffffffffu, bj, off);
                if (ov > bv || (ov == bv && oj < bj)) { bv = ov; bj = oj; }
            }
            if ((threadIdx.x & 31) == 0) { wv[threadIdx.x >> 5] = bv; wi[threadIdx.x >> 5] = bj; }
            __syncthreads();
            if (threadIdx.x == 0) {
                float fv = wv[0]; int fj = wi[0];
                #pragma unroll
                for (int w = 1; w < 8; w++) {
                    float ov = wv[w]; int oj = wi[w];
                    if (ov > fv || (ov == fv && oj < fj)) { fv = ov; fj = oj; }
                }
                sel[k] = fj;
                dist[fj] = NEG_BIG;
            }
            __syncthreads();
        }

        // emit idx_flat (as float), nbrs, feat
        if (threadIdx.x < KNN) {
            int k  = threadIdx.x;
            int j  = sel[k];
            int bn = b * NPTS + i;
            int m  = bn * KNN + k;
            outIdx[m] = (float)(j + b * NPTS);
            float v0 = px[j], v1 = py[j], v2 = pz[j];
            size_t ofs = (size_t)m * 3;
            outNbr[ofs + 0] = v0; outNbr[ofs + 1] = v1; outNbr[ofs + 2] = v2;
            g_feat[0u * MBIG + m] = v0;
            g_feat[1u * MBIG + m] = v1;
            g_feat[2u * MBIG + m] = v2;
            g_feat[3u * MBIG + m] = q0;
            g_feat[4u * MBIG + m] = q1;
            g_feat[5u * MBIG + m] = q2;
        }
        __syncthreads();
    }
}

// ---------------- fused GEMM + (optional) input BN-ReLU + stats epilogue ----
// Y[Cout x M] = W[Cout x Cin] * act(X[Cin x M]);  act = relu(x*sc+sh) if HAS_ACT
// Also accumulates per-output-channel sum / sumsq of Y into accS/accQ.
template <int BO, int BK, bool HAS_ACT>
__global__ __launch_bounds__(256, 2)
void gemm_bn_k(const float* __restrict__ W, const float* __restrict__ X,
               const float* __restrict__ sc, const float* __restrict__ sh,
               float* __restrict__ Y,
               float* __restrict__ accS, float* __restrict__ accQ,
               int Cin, int M)
{
    const int BM = 128;
    const int TO = BO / 16;    // 4 or 8
    const int TM = 8;

    __shared__ float As[BK * BO];
    __shared__ float Bs[BK * BM];
    __shared__ float redS[BO * 16];
    __shared__ float redQ[BO * 16];

    int tid = threadIdx.x;
    int tx  = tid & 15;        // M direction (16 x 8 = 128)
    int ty  = tid >> 4;        // O direction (16 x TO = BO)
    int mBase = blockIdx.x * BM;
    int oBase = blockIdx.y * BO;

    float acc[TO][TM];
    #pragma unroll
    for (int j = 0; j < TO; j++)
        #pragma unroll
        for (int i = 0; i < TM; i++) acc[j][i] = 0.f;

    int nK = (Cin + BK - 1) / BK;
    for (int kt = 0; kt < nK; kt++) {
        int c0 = kt * BK;
        // load weights (transposed: As[c][o])
        for (int idx = tid; idx < BK * BO; idx += 256) {
            int o = idx / BK, c = idx - o * BK;
            float w = (c0 + c < Cin) ? W[(size_t)(oBase + o) * Cin + c0 + c] : 0.f;
            As[c * BO + o] = w;
        }
        // load inputs with optional BN+ReLU
        for (int idx = tid; idx < BK * BM; idx += 256) {
            int c = idx >> 7, m = idx & 127;
            int cg = c0 + c;
            float v = 0.f;
            if (cg < Cin) {
                v = X[(size_t)cg * M + mBase + m];
                if (HAS_ACT) v = fmaxf(fmaf(v, sc[cg], sh[cg]), 0.f);
            }
            Bs[c * BM + m] = v;
        }
        __syncthreads();

        #pragma unroll
        for (int c = 0; c < BK; c++) {
            float a[TO], bb[TM];
            #pragma unroll
            for (int j = 0; j < TO; j += 4) {
                float4 t4 = *(const float4*)&As[c * BO + ty * TO + j];
                a[j] = t4.x; a[j + 1] = t4.y; a[j + 2] = t4.z; a[j + 3] = t4.w;
            }
            #pragma unroll
            for (int i = 0; i < TM; i += 4) {
                float4 t4 = *(const float4*)&Bs[c * BM + tx * TM + i];
                bb[i] = t4.x; bb[i + 1] = t4.y; bb[i + 2] = t4.z; bb[i + 3] = t4.w;
            }
            #pragma unroll
            for (int j = 0; j < TO; j++)
                #pragma unroll
                for (int i = 0; i < TM; i++)
                    acc[j][i] = fmaf(a[j], bb[i], acc[j][i]);
        }
        __syncthreads();
    }

    // store + per-channel partial stats
    #pragma unroll
    for (int j = 0; j < TO; j++) {
        int o = oBase + ty * TO + j;
        float* yp = Y + (size_t)o * M + mBase + tx * TM;
        float4 v0 = make_float4(acc[j][0], acc[j][1], acc[j][2], acc[j][3]);
        float4 v1 = make_float4(acc[j][4], acc[j][5], acc[j][6], acc[j][7]);
        *(float4*)(yp)     = v0;
        *(float4*)(yp + 4) = v1;
        float ps = 0.f, pq = 0.f;
        #pragma unroll
        for (int i = 0; i < TM; i++) { ps += acc[j][i]; pq += acc[j][i] * acc[j][i]; }
        redS[(ty * TO + j) * 16 + tx] = ps;
        redQ[(ty * TO + j) * 16 + tx] = pq;
    }
    __syncthreads();
    if (tid < BO) {
        float s = 0.f, q = 0.f;
        #pragma unroll
        for (int t2 = 0; t2 < 16; t2++) { s += redS[tid * 16 + t2]; q += redQ[tid * 16 + t2]; }
        atomicAdd(&accS[oBase + tid], s);
        atomicAdd(&accQ[oBase + tid], q);
    }
}

// ---------------- finalize BN stats into affine (scale, shift) ----------------
__global__ void finalize_k(const float* __restrict__ accS, const float* __restrict__ accQ,
                           const float* __restrict__ g, const float* __restrict__ bta,
                           float* __restrict__ sc, float* __restrict__ sh,
                           int Cout, float invM)
{
    int o = blockIdx.x * blockDim.x + threadIdx.x;
    if (o < Cout) {
        float mu   = accS[o] * invM;
        float var  = accQ[o] * invM - mu * mu;
        float rstd = 1.f / sqrtf(var + BN_EPS);
        float s    = g[o] * rstd;
        sc[o] = s;
        sh[o] = bta[o] - mu * s;
    }
}

// ---------------- max over K with BN-ReLU applied ----------------
__global__ void maxk_k(const float* __restrict__ Y,
                       const float* __restrict__ sc, const float* __restrict__ sh,
                       float* __restrict__ cat, int Cout, int catOff)
{
    int idx = blockIdx.x * blockDim.x + threadIdx.x;
    if (idx >= Cout * MSML) return;
    int o  = idx / MSML;
    int bn = idx - o * MSML;
    float s = sc[o], t = sh[o];
    const float4* p = (const float4*)(Y + (size_t)o * MBIG + (size_t)bn * KNN);
    float mx = NEG_BIG;
    #pragma unroll
    for (int r = 0; r < 8; r++) {
        float4 v = p[r];
        mx = fmaxf(mx, fmaf(v.x, s, t));
        mx = fmaxf(mx, fmaf(v.y, s, t));
        mx = fmaxf(mx, fmaf(v.z, s, t));
        mx = fmaxf(mx, fmaf(v.w, s, t));
    }
    cat[(size_t)(catOff + o) * MSML + bn] = fmaxf(mx, 0.f);
}

// ---------------- final output epilogue ----------------
__global__ void out_k(const float* __restrict__ y5,
                      const float* __restrict__ sc, const float* __restrict__ sh,
                      float* __restrict__ out)
{
    int i = blockIdx.x * blockDim.x + threadIdx.x;
    if (i >= BATCH * EMB * NPTS) return;
    int n  = i & (NPTS - 1);
    int ch = (i >> 11) & (EMB - 1);
    int b  = i >> 20;          // 11 + 9
    int m  = b * NPTS + n;
    float v = y5[(size_t)ch * MSML + m];
    out[i] = fmaxf(fmaf(v, sc[ch], sh[ch]), 0.f);
}

// ---------------- launcher ----------------
extern "C" void kernel_launch(void* const* d_in, const int* in_sizes, int n_in,
                              void* d_out, int out_size)
{
    const float* x  = (const float*)d_in[0];
    const float* W1 = (const float*)d_in[1];
    const float* g1 = (const float*)d_in[2];
    const float* b1 = (const float*)d_in[3];
    const float* W2 = (const float*)d_in[4];
    const float* g2 = (const float*)d_in[5];
    const float* b2 = (const float*)d_in[6];
    const float* W3 = (const float*)d_in[7];
    const float* g3 = (const float*)d_in[8];
    const float* b3 = (const float*)d_in[9];
    const float* W4 = (const float*)d_in[10];
    const float* g4 = (const float*)d_in[11];
    const float* b4 = (const float*)d_in[12];
    const float* W5 = (const float*)d_in[13];
    const float* g5 = (const float*)d_in[14];
    const float* b5 = (const float*)d_in[15];

    float* out    = (float*)d_out;
    float* outIdx = out + IDX_OFF;
    float* outNbr = out + NBR_OFF;

    float *feat, *y1, *y2, *y3, *y4, *cat, *y5, *accS, *accQ, *scl, *shf;
    cudaGetSymbolAddress((void**)&feat, g_feat);
    cudaGetSymbolAddress((void**)&y1,   g_y1);
    cudaGetSymbolAddress((void**)&y2,   g_y2);
    cudaGetSymbolAddress((void**)&y3,   g_y3);
    cudaGetSymbolAddress((void**)&y4,   g_y4);
    cudaGetSymbolAddress((void**)&cat,  g_cat);
    cudaGetSymbolAddress((void**)&y5,   g_y5);
    cudaGetSymbolAddress((void**)&accS, g_accS);
    cudaGetSymbolAddress((void**)&accQ, g_accQ);
    cudaGetSymbolAddress((void**)&scl,  g_scl);
    cudaGetSymbolAddress((void**)&shf,  g_shf);

    const float invMB = 1.f / (float)MBIG;
    const float invMS = 1.f / (float)MSML;

    zero_acc_k<<<4, 256>>>(accS, accQ);
    knn_kernel<<<BATCH * NPTS / IPB, 256>>>(x, outIdx, outNbr);

    // conv1: 64 x 6 x 524288 (no input activation)
    gemm_bn_k<64, 16, false><<<dim3(MBIG / 128, 1), 256>>>(
        W1, feat, nullptr, nullptr, y1, accS + 0, accQ + 0, 6, MBIG);
    finalize_k<<<1, 64>>>(accS + 0, accQ + 0, g1, b1, scl + 0, shf + 0, 64, invMB);

    // conv2: 64 x 64 x 524288
    gemm_bn_k<64, 16, true><<<dim3(MBIG / 128, 1), 256>>>(
        W2, y1, scl + 0, shf + 0, y2, accS + 64, accQ + 64, 64, MBIG);
    finalize_k<<<1, 64>>>(accS + 64, accQ + 64, g2, b2, scl + 64, shf + 64, 64, invMB);

    // conv3: 128 x 64 x 524288
    gemm_bn_k<128, 16, true><<<dim3(MBIG / 128, 1), 256>>>(
        W3, y2, scl + 64, shf + 64, y3, accS + 128, accQ + 128, 64, MBIG);
    finalize_k<<<1, 128>>>(accS + 128, accQ + 128, g3, b3, scl + 128, shf + 128, 128, invMB);

    // conv4: 256 x 128 x 524288
    gemm_bn_k<128, 16, true><<<dim3(MBIG / 128, 2), 256>>>(
        W4, y3, scl + 128, shf + 128, y4, accS + 256, accQ + 256, 128, MBIG);
    finalize_k<<<1, 256>>>(accS + 256, accQ + 256, g4, b4, scl + 256, shf + 256, 256, invMB);

    // max over K -> cat (512 x 16384)
    maxk_k<<<(64  * MSML + 255) / 256, 256>>>(y1, scl + 0,   shf + 0,   cat, 64,  0);
    maxk_k<<<(64  * MSML + 255) / 256, 256>>>(y2, scl + 64,  shf + 64,  cat, 64,  64);
    maxk_k<<<(128 * MSML + 255) / 256, 256>>>(y3, scl + 128, shf + 128, cat, 128, 128);
    maxk_k<<<(256 * MSML + 255) / 256, 256>>>(y4, scl + 256, shf + 256, cat, 256, 256);

    // conv5: 512 x 512 x 16384 (cat already activated)
    gemm_bn_k<128, 16, false><<<dim3(MSML / 128, 4), 256>>>(
        W5, cat, nullptr, nullptr, y5, accS + 512, accQ + 512, 512, MSML);
    finalize_k<<<1, 512>>>(accS + 512, accQ + 512, g5, b5, scl + 512, shf + 512, 512, invMS);

    out_k<<<(BATCH * EMB * NPTS + 255) / 256, 256>>>(y5, scl + 512, shf + 512, out);
}

// round 5
// speedup vs baseline: 1.8988x; 1.8988x over previous
#include <cuda_runtime.h>
#include <cuda_bf16.h>
#include <cstdint>
#include <math.h>

// ---------------- problem constants ----------------
#define BATCH 8
#define NPTS  2048
#define KNN   32
#define EMB   512
#define MBIG  (BATCH*NPTS*KNN)   // 524288
#define MSML  (BATCH*NPTS)       // 16384
#define BN_EPS 1e-5f

#define IDX_OFF  (BATCH*EMB*NPTS)                 // 8388608
#define NBR_OFF  (IDX_OFF + BATCH*NPTS*KNN)       // 8912896

#define NEG_BIG (-1e30f)

// ---------------- scratch (fp32 intermediates for precision) ---------------
__device__ float g_feat[8u  * MBIG];     // [m][8] (6 used)
__device__ float g_y1 [64u  * MBIG];     // [m][64]
__device__ float g_y2 [64u  * MBIG];
__device__ float g_y3 [128u * MBIG];
__device__ float g_cat[512u * MSML];     // [pt][512]
__device__ float g_y5 [512u * MSML];
// weights split hi/lo bf16
__device__ __nv_bfloat16 g_w2h[64*64],   g_w2l[64*64];
__device__ __nv_bfloat16 g_w3h[128*64],  g_w3l[128*64];
__device__ __nv_bfloat16 g_w4h[256*128], g_w4l[256*128];
__device__ __nv_bfloat16 g_w5h[512*512], g_w5l[512*512];
__device__ float g_accS[1024], g_accQ[1024], g_scl[1024], g_shf[1024];

// ---------------- helpers ----------------
__device__ __forceinline__ uint32_t smem_to_u32(const void* p) {
    uint32_t a;
    asm("{ .reg .u64 t; cvta.to.shared.u64 t, %1; cvt.u32.u64 %0, t; }" : "=r"(a) : "l"(p));
    return a;
}
__device__ __forceinline__ uint32_t packbf(float a, float b) {
    __nv_bfloat162 h = __floats2bfloat162_rn(a, b);
    return *(uint32_t*)&h;
}
__device__ __forceinline__ void ldsm4(uint32_t* r, uint32_t addr) {
    asm volatile("ldmatrix.sync.aligned.m8n8.x4.shared.b16 {%0,%1,%2,%3}, [%4];"
        : "=r"(r[0]), "=r"(r[1]), "=r"(r[2]), "=r"(r[3]) : "r"(addr));
}
__device__ __forceinline__ void mma16816(float* c, const uint32_t* a, uint32_t b0, uint32_t b1) {
    asm volatile("mma.sync.aligned.m16n8k16.row.col.f32.bf16.bf16.f32 "
        "{%0,%1,%2,%3}, {%4,%5,%6,%7}, {%8,%9}, {%0,%1,%2,%3};"
        : "+f"(c[0]), "+f"(c[1]), "+f"(c[2]), "+f"(c[3])
        : "r"(a[0]), "r"(a[1]), "r"(a[2]), "r"(a[3]), "r"(b0), "r"(b1));
}

// ---------------- zero accumulators ----------------
__global__ void zero_acc_k(float* s, float* q) {
    int i = blockIdx.x * blockDim.x + threadIdx.x;
    if (i < 1024) { s[i] = 0.f; q[i] = 0.f; }
}

// ---------------- weight convert fp32 -> split bf16 hi/lo ----------------
__global__ void wconv_k(const float* W2, const float* W3, const float* W4, const float* W5,
                        __nv_bfloat16* w2h, __nv_bfloat16* w2l,
                        __nv_bfloat16* w3h, __nv_bfloat16* w3l,
                        __nv_bfloat16* w4h, __nv_bfloat16* w4l,
                        __nv_bfloat16* w5h, __nv_bfloat16* w5l)
{
    int i = blockIdx.x * blockDim.x + threadIdx.x;
    const float* src; __nv_bfloat16 *dh, *dl; int off;
    if      (i < 4096)   { src = W2; dh = w2h; dl = w2l; off = 0; }
    else if (i < 12288)  { src = W3; dh = w3h; dl = w3l; off = 4096; }
    else if (i < 45056)  { src = W4; dh = w4h; dl = w4l; off = 12288; }
    else if (i < 307200) { src = W5; dh = w5h; dl = w5l; off = 45056; }
    else return;
    int j = i - off;
    float w = src[j];
    __nv_bfloat16 h = __float2bfloat16(w);
    dh[j] = h;
    dl[j] = __float2bfloat16(w - __bfloat162float(h));
}

// ---------------- kNN + gather + feat build (exact jax top_k semantics) ------
#define IPB 4
__global__ void knn_kernel(const float* __restrict__ x,
                           float* __restrict__ outIdx,
                           float* __restrict__ outNbr,
                           float* __restrict__ feat)
{
    __shared__ float px[NPTS], py[NPTS], pz[NPTS], pxx[NPTS], dist[NPTS];
    __shared__ int   sel[KNN];
    __shared__ float wv[8];
    __shared__ int   wi[8];

    int b  = blockIdx.x / (NPTS / IPB);
    int i0 = (blockIdx.x % (NPTS / IPB)) * IPB;
    const float* xb = x + (size_t)b * 3 * NPTS;

    for (int j = threadIdx.x; j < NPTS; j += blockDim.x) {
        float a0 = xb[j], a1 = xb[NPTS + j], a2 = xb[2 * NPTS + j];
        px[j] = a0; py[j] = a1; pz[j] = a2;
        pxx[j] = a0 * a0 + a1 * a1 + a2 * a2;
    }
    __syncthreads();

    for (int ii = 0; ii < IPB; ii++) {
        int i = i0 + ii;
        float q0 = px[i], q1 = py[i], q2 = pz[i], qxx = pxx[i];

        for (int j = threadIdx.x; j < NPTS; j += blockDim.x) {
            float dot   = q0 * px[j] + q1 * py[j] + q2 * pz[j];
            float inner = -2.f * dot;
            float t     = (-qxx) - inner;
            dist[j]     = t - pxx[j];
        }
        __syncthreads();

        for (int k = 0; k < KNN; k++) {
            float bv = NEG_BIG * 2.f; int bj = NPTS;
            for (int j = threadIdx.x; j < NPTS; j += blockDim.x) {
                float v = dist[j];
                if (v > bv) { bv = v; bj = j; }
            }
            #pragma unroll
            for (int off = 16; off; off >>= 1) {
                float ov = __shfl_down_sync(0xffffffffu, bv, off);
                int   oj = __shfl_down_sync(0xffffffffu, bj, off);
                if (ov > bv || (ov == bv && oj < bj)) { bv = ov; bj = oj; }
            }
            if ((threadIdx.x & 31) == 0) { wv[threadIdx.x >> 5] = bv; wi[threadIdx.x >> 5] = bj; }
            __syncthreads();
            if (threadIdx.x == 0) {
                float fv = wv[0]; int fj = wi[0];
                #pragma unroll
                for (int w = 1; w < 8; w++) {
                    float ov = wv[w]; int oj = wi[w];
                    if (ov > fv || (ov == fv && oj < fj)) { fv = ov; fj = oj; }
                }
                sel[k] = fj;
                dist[fj] = NEG_BIG;
            }
            __syncthreads();
        }

        if (threadIdx.x < KNN) {
            int k  = threadIdx.x;
            int j  = sel[k];
            int bn = b * NPTS + i;
            int m  = bn * KNN + k;
            outIdx[m] = (float)(j + b * NPTS);
            float v0 = px[j], v1 = py[j], v2 = pz[j];
            size_t ofs = (size_t)m * 3;
            outNbr[ofs + 0] = v0; outNbr[ofs + 1] = v1; outNbr[ofs + 2] = v2;
            float* fp = feat + (size_t)m * 8;
            fp[0] = v0; fp[1] = v1; fp[2] = v2;
            fp[3] = q0; fp[4] = q1; fp[5] = q2;
        }
        __syncthreads();
    }
}

// ---------------- conv1: Cin=6, Cout=64, fp32 SIMT + stats ----------
__global__ __launch_bounds__(256)
void conv1_k(const float* __restrict__ W1, const float* __restrict__ feat,
             float* __restrict__ y1, float* accS, float* accQ)
{
    __shared__ float w1s[384];
    __shared__ float sS[8 * 64];
    __shared__ float sQ[8 * 64];
    int tid = threadIdx.x, wid = tid >> 5, lane = tid & 31;
    for (int i = tid; i < 384; i += 256) w1s[i] = W1[i];
    __syncthreads();

    int m = blockIdx.x * 256 + tid;
    const float4* fp = (const float4*)(feat + (size_t)m * 8);
    float4 fa = fp[0], fb = fp[1];
    float f0 = fa.x, f1 = fa.y, f2 = fa.z, f3 = fa.w, f4 = fb.x, f5 = fb.y;

    float v[64];
    #pragma unroll
    for (int o = 0; o < 64; o++) {
        const float* w = &w1s[o * 6];
        v[o] = w[0]*f0 + w[1]*f1 + w[2]*f2 + w[3]*f3 + w[4]*f4 + w[5]*f5;
    }
    float4* dst = (float4*)(y1 + (size_t)m * 64);
    #pragma unroll
    for (int i = 0; i < 16; i++) dst[i] = make_float4(v[4*i], v[4*i+1], v[4*i+2], v[4*i+3]);

    #pragma unroll
    for (int o = 0; o < 64; o++) {
        float s = v[o], q = v[o]*v[o];
        #pragma unroll
        for (int off = 16; off; off >>= 1) {
            s += __shfl_down_sync(0xffffffffu, s, off);
            q += __shfl_down_sync(0xffffffffu, q, off);
        }
        if (lane == 0) { sS[wid * 64 + o] = s; sQ[wid * 64 + o] = q; }
    }
    __syncthreads();
    if (tid < 64) {
        float s = 0.f, q = 0.f;
        #pragma unroll
        for (int w = 0; w < 8; w++) { s += sS[w * 64 + tid]; q += sQ[w * 64 + tid]; }
        atomicAdd(&accS[tid], s);
        atomicAdd(&accQ[tid], q);
    }
}

// ---------------- bf16x3 split HMMA GEMM -------------------------------------
// Y[128 pts x 64 couts] = act(X fp32) * W^T, computed as hi*hi + hi*lo + lo*hi
// with fp32 accumulate (~fp32 fidelity). Stats fused. Optional fused max-over-K
// (each warp's 32 rows == one point's K block) for conv4, skipping Y entirely.
#define N_TILE 64
#define NT8    8
template <bool HAS_ACT, bool FUSE_MAX>
__global__ __launch_bounds__(128)
void mma_gemm(const __nv_bfloat16* __restrict__ Wh, const __nv_bfloat16* __restrict__ Wl,
              const float* __restrict__ X,
              const float* __restrict__ sc, const float* __restrict__ sh,
              float* __restrict__ Y, float* __restrict__ catp,
              float* __restrict__ accS, float* __restrict__ accQ,
              int Cin, int Cout)
{
    // 48KB static smem exactly: A hi/lo 16KB each, B hi/lo 8KB each.
    __shared__ __align__(16) uint8_t smem[49152];
    uint8_t* sAh = smem;
    uint8_t* sAl = smem + 16384;
    uint8_t* sBh = smem + 32768;
    uint8_t* sBl = smem + 40960;
    // stats arrays alias sAh (used only after all ldsm reads complete)
    float* sS = (float*)smem;
    float* sQ = sS + 4 * N_TILE;

    const int tid  = threadIdx.x;
    const int wid  = tid >> 5;
    const int lane = tid & 31;
    const int mBase = blockIdx.y * 128;
    const int oBase = blockIdx.x * N_TILE;

    const uint32_t sAh_u = smem_to_u32(sAh);
    const uint32_t sAl_u = smem_to_u32(sAl);
    const uint32_t sBh_u = smem_to_u32(sBh);
    const uint32_t sBl_u = smem_to_u32(sBl);

    float acc[2][NT8][4];
    #pragma unroll
    for (int mt = 0; mt < 2; mt++)
        #pragma unroll
        for (int nt = 0; nt < NT8; nt++)
            #pragma unroll
            for (int i = 0; i < 4; i++) acc[mt][nt][i] = 0.f;

    const float4* Xv = (const float4*)X;
    const uint4* Whv = (const uint4*)Wh;
    const uint4* Wlv = (const uint4*)Wl;
    const int cinV = Cin >> 2;   // float4 per X row
    const int cinW = Cin >> 3;   // uint4 per W row
    const int nkt  = Cin >> 6;

    for (int kt = 0; kt < nkt; kt++) {
        // ---- A tile: 128 rows x 64 cin (fp32 -> act -> split hi/lo) ----
        #pragma unroll
        for (int j = 0; j < 16; j++) {
            int linear = tid + j * 128;
            int row = linear >> 4, ch = linear & 15;
            float4 v = Xv[(size_t)(mBase + row) * cinV + kt * 16 + ch];
            if (HAS_ACT) {
                int cb = kt * 64 + ch * 4;
                float4 s4 = *(const float4*)(sc + cb);
                float4 t4 = *(const float4*)(sh + cb);
                v.x = fmaxf(fmaf(v.x, s4.x, t4.x), 0.f);
                v.y = fmaxf(fmaf(v.y, s4.y, t4.y), 0.f);
                v.z = fmaxf(fmaf(v.z, s4.z, t4.z), 0.f);
                v.w = fmaxf(fmaf(v.w, s4.w, t4.w), 0.f);
            }
            float hx = __bfloat162float(__float2bfloat16(v.x));
            float hy = __bfloat162float(__float2bfloat16(v.y));
            float hz = __bfloat162float(__float2bfloat16(v.z));
            float hw = __bfloat162float(__float2bfloat16(v.w));
            uint32_t hi0 = packbf(v.x, v.y), hi1 = packbf(v.z, v.w);
            uint32_t lo0 = packbf(v.x - hx, v.y - hy), lo1 = packbf(v.z - hz, v.w - hw);
            int c = ch >> 1, sub = ch & 1;
            int addr = row * 128 + ((c ^ (row & 7)) << 4) + sub * 8;
            *(uint2*)(sAh + addr) = make_uint2(hi0, hi1);
            *(uint2*)(sAl + addr) = make_uint2(lo0, lo1);
        }
        // ---- B tiles: 64 rows x 64 cin, hi and lo planes ----
        #pragma unroll
        for (int j = 0; j < 4; j++) {
            int linear = tid + j * 128;
            int row = linear >> 3, ch = linear & 7;
            size_t gofs = (size_t)(oBase + row) * cinW + kt * 8 + ch;
            int addr = row * 128 + ((ch ^ (row & 7)) << 4);
            *(uint4*)(sBh + addr) = Whv[gofs];
            *(uint4*)(sBl + addr) = Wlv[gofs];
        }
        __syncthreads();

        // ---- compute: 3-term split MMA ----
        #pragma unroll
        for (int ks = 0; ks < 4; ks++) {
            uint32_t ah[2][4], al[2][4];
            int chunk = 2 * ks + (lane >> 4);
            #pragma unroll
            for (int mt = 0; mt < 2; mt++) {
                int r = wid * 32 + mt * 16 + (lane & 15);
                int off = r * 128 + ((chunk ^ (r & 7)) << 4);
                ldsm4(ah[mt], sAh_u + off);
                ldsm4(al[mt], sAl_u + off);
            }
            #pragma unroll
            for (int ntp = 0; ntp < 4; ntp++) {
                uint32_t bh[4], bl[4];
                int r = ntp * 16 + (lane & 15);
                int off = r * 128 + ((chunk ^ (r & 7)) << 4);
                ldsm4(bh, sBh_u + off);
                ldsm4(bl, sBl_u + off);
                #pragma unroll
                for (int mt = 0; mt < 2; mt++) {
                    #pragma unroll
                    for (int nb = 0; nb < 2; nb++) {
                        float* c = acc[mt][2 * ntp + nb];
                        mma16816(c, ah[mt], bh[nb], bh[nb + 2]);
                        mma16816(c, ah[mt], bl[nb], bl[nb + 2]);
                        mma16816(c, al[mt], bh[nb], bh[nb + 2]);
                    }
                }
            }
        }
        __syncthreads();
    }

    // ---- epilogue ----
    const int q4 = lane & 3;
    #pragma unroll
    for (int nt = 0; nt < NT8; nt++) {
        int col = oBase + nt * 8 + q4 * 2;
        float se = 0.f, so = 0.f, qe = 0.f, qo = 0.f;
        #pragma unroll
        for (int mt = 0; mt < 2; mt++) {
            float* c = acc[mt][nt];
            if (!FUSE_MAX) {
                int r0 = mBase + wid * 32 + mt * 16 + (lane >> 2);
                *(float2*)(Y + (size_t)r0 * Cout + col)       = make_float2(c[0], c[1]);
                *(float2*)(Y + (size_t)(r0 + 8) * Cout + col) = make_float2(c[2], c[3]);
            }
            se += c[0] + c[2];  so += c[1] + c[3];
            qe += c[0]*c[0] + c[2]*c[2];
            qo += c[1]*c[1] + c[3]*c[3];
        }
        if (FUSE_MAX) {
            // raw max over this warp's 32 rows (one point's K block)
            float m0 = fmaxf(fmaxf(acc[0][nt][0], acc[0][nt][2]),
                             fmaxf(acc[1][nt][0], acc[1][nt][2]));
            float m1 = fmaxf(fmaxf(acc[0][nt][1], acc[0][nt][3]),
                             fmaxf(acc[1][nt][1], acc[1][nt][3]));
            #pragma unroll
            for (int off = 16; off >= 4; off >>= 1) {
                m0 = fmaxf(m0, __shfl_xor_sync(0xffffffffu, m0, off));
                m1 = fmaxf(m1, __shfl_xor_sync(0xffffffffu, m1, off));
            }
            if (lane < 4) {
                int pt = blockIdx.y * 4 + wid;
                int cc = 256 + oBase + nt * 8 + lane * 2;
                catp[(size_t)pt * 512 + cc]     = m0;
                catp[(size_t)pt * 512 + cc + 1] = m1;
            }
        }
        #pragma unroll
        for (int off = 16; off >= 4; off >>= 1) {
            se += __shfl_down_sync(0xffffffffu, se, off);
            so += __shfl_down_sync(0xffffffffu, so, off);
            qe += __shfl_down_sync(0xffffffffu, qe, off);
            qo += __shfl_down_sync(0xffffffffu, qo, off);
        }
        if (lane < 4) {
            int chl = nt * 8 + lane * 2;
            sS[wid * N_TILE + chl]     = se;
            sS[wid * N_TILE + chl + 1] = so;
            sQ[wid * N_TILE + chl]     = qe;
            sQ[wid * N_TILE + chl + 1] = qo;
        }
    }
    __syncthreads();
    if (tid < N_TILE) {
        float s = 0.f, q = 0.f;
        #pragma unroll
        for (int w = 0; w < 4; w++) { s += sS[w * N_TILE + tid]; q += sQ[w * N_TILE + tid]; }
        atomicAdd(&accS[oBase + tid], s);
        atomicAdd(&accQ[oBase + tid], q);
    }
}

// ---------------- finalize BN stats ----------------
__global__ void finalize_k(const float* __restrict__ accS, const float* __restrict__ accQ,
                           const float* __restrict__ g, const float* __restrict__ bta,
                           float* __restrict__ sc, float* __restrict__ sh,
                           int Cout, float invM)
{
    int o = blockIdx.x * blockDim.x + threadIdx.x;
    if (o < Cout) {
        float mu   = accS[o] * invM;
        float var  = accQ[o] * invM - mu * mu;
        float rstd = 1.f / sqrtf(var + BN_EPS);
        float s    = g[o] * rstd;
        sc[o] = s;
        sh[o] = bta[o] - mu * s;
    }
}

// ---------------- max over K with BN-ReLU (scale>0: affine commutes w/ max) --
__global__ void maxk_k(const float* __restrict__ Y,
                       const float* __restrict__ sc, const float* __restrict__ sh,
                       float* __restrict__ cat, int C, int catOff)
{
    int idx = blockIdx.x * blockDim.x + threadIdx.x;
    if (idx >= MSML * C) return;
    int ch = idx % C;
    int pt = idx / C;
    const float* p = Y + (size_t)pt * KNN * C + ch;
    float mx = NEG_BIG;
    #pragma unroll 8
    for (int k = 0; k < KNN; k++) mx = fmaxf(mx, p[(size_t)k * C]);
    cat[(size_t)pt * 512 + catOff + ch] = fmaxf(fmaf(mx, sc[ch], sh[ch]), 0.f);
}

// ---------------- conv4 cat fixup: apply BN affine + relu in place ----------
__global__ void cat4fix_k(float* __restrict__ cat,
                          const float* __restrict__ sc, const float* __restrict__ sh)
{
    int idx = blockIdx.x * blockDim.x + threadIdx.x;
    if (idx >= MSML * 256) return;
    int ch = idx & 255;
    int pt = idx >> 8;
    size_t ofs = (size_t)pt * 512 + 256 + ch;
    cat[ofs] = fmaxf(fmaf(cat[ofs], sc[ch], sh[ch]), 0.f);
}

// ---------------- output transpose + BN-ReLU: y5[pt][512] -> out[b][512][2048]
__global__ void out_t(const float* __restrict__ y5,
                      const float* __restrict__ sc, const float* __restrict__ sh,
                      float* __restrict__ out)
{
    __shared__ float ts[32][33];
    int tx = threadIdx.x, ty = threadIdx.y;
    int n0 = blockIdx.x * 32, ch0 = blockIdx.y * 32, b = blockIdx.z;
    float s = sc[ch0 + tx], t = sh[ch0 + tx];
    #pragma unroll
    for (int r = 0; r < 4; r++) {
        int nl = ty * 4 + r;
        int m = b * NPTS + n0 + nl;
        float v = y5[(size_t)m * 512 + ch0 + tx];
        ts[nl][tx] = fmaxf(fmaf(v, s, t), 0.f);
    }
    __syncthreads();
    #pragma unroll
    for (int r = 0; r < 4; r++) {
        int chl = ty * 4 + r;
        out[(size_t)b * (512 * NPTS) + (size_t)(ch0 + chl) * NPTS + n0 + tx] = ts[tx][chl];
    }
}

// ---------------- launcher ----------------
extern "C" void kernel_launch(void* const* d_in, const int* in_sizes, int n_in,
                              void* d_out, int out_size)
{
    const float* x  = (const float*)d_in[0];
    const float* W1 = (const float*)d_in[1];
    const float* g1 = (const float*)d_in[2];
    const float* b1 = (const float*)d_in[3];
    const float* W2 = (const float*)d_in[4];
    const float* g2 = (const float*)d_in[5];
    const float* b2 = (const float*)d_in[6];
    const float* W3 = (const float*)d_in[7];
    const float* g3 = (const float*)d_in[8];
    const float* b3 = (const float*)d_in[9];
    const float* W4 = (const float*)d_in[10];
    const float* g4 = (const float*)d_in[11];
    const float* b4 = (const float*)d_in[12];
    const float* W5 = (const float*)d_in[13];
    const float* g5 = (const float*)d_in[14];
    const float* b5 = (const float*)d_in[15];

    float* out    = (float*)d_out;
    float* outIdx = out + IDX_OFF;
    float* outNbr = out + NBR_OFF;

    float *feat, *y1, *y2, *y3, *cat, *y5, *accS, *accQ, *scl, *shf;
    __nv_bfloat16 *w2h, *w2l, *w3h, *w3l, *w4h, *w4l, *w5h, *w5l;
    cudaGetSymbolAddress((void**)&feat, g_feat);
    cudaGetSymbolAddress((void**)&y1,   g_y1);
    cudaGetSymbolAddress((void**)&y2,   g_y2);
    cudaGetSymbolAddress((void**)&y3,   g_y3);
    cudaGetSymbolAddress((void**)&cat,  g_cat);
    cudaGetSymbolAddress((void**)&y5,   g_y5);
    cudaGetSymbolAddress((void**)&w2h,  g_w2h);
    cudaGetSymbolAddress((void**)&w2l,  g_w2l);
    cudaGetSymbolAddress((void**)&w3h,  g_w3h);
    cudaGetSymbolAddress((void**)&w3l,  g_w3l);
    cudaGetSymbolAddress((void**)&w4h,  g_w4h);
    cudaGetSymbolAddress((void**)&w4l,  g_w4l);
    cudaGetSymbolAddress((void**)&w5h,  g_w5h);
    cudaGetSymbolAddress((void**)&w5l,  g_w5l);
    cudaGetSymbolAddress((void**)&accS, g_accS);
    cudaGetSymbolAddress((void**)&accQ, g_accQ);
    cudaGetSymbolAddress((void**)&scl,  g_scl);
    cudaGetSymbolAddress((void**)&shf,  g_shf);

    const float invMB = 1.f / (float)MBIG;
    const float invMS = 1.f / (float)MSML;

    zero_acc_k<<<4, 256>>>(accS, accQ);
    wconv_k<<<(307200 + 255) / 256, 256>>>(W2, W3, W4, W5,
                                           w2h, w2l, w3h, w3l, w4h, w4l, w5h, w5l);
    knn_kernel<<<BATCH * NPTS / IPB, 256>>>(x, outIdx, outNbr, feat);

    conv1_k<<<MBIG / 256, 256>>>(W1, feat, y1, accS + 0, accQ + 0);
    finalize_k<<<1, 64>>>(accS + 0, accQ + 0, g1, b1, scl + 0, shf + 0, 64, invMB);

    // conv2: 64 <- 64, act(scl1)
    mma_gemm<true, false><<<dim3(1, MBIG / 128), 128>>>(
        w2h, w2l, y1, scl + 0, shf + 0, y2, nullptr, accS + 64, accQ + 64, 64, 64);
    finalize_k<<<1, 64>>>(accS + 64, accQ + 64, g2, b2, scl + 64, shf + 64, 64, invMB);

    // conv3: 128 <- 64, act(scl2)
    mma_gemm<true, false><<<dim3(2, MBIG / 128), 128>>>(
        w3h, w3l, y2, scl + 64, shf + 64, y3, nullptr, accS + 128, accQ + 128, 64, 128);
    finalize_k<<<1, 128>>>(accS + 128, accQ + 128, g3, b3, scl + 128, shf + 128, 128, invMB);

    // conv4: 256 <- 128, act(scl3), fused raw max-over-K into cat (no y4!)
    mma_gemm<true, true><<<dim3(4, MBIG / 128), 128>>>(
        w4h, w4l, y3, scl + 128, shf + 128, nullptr, cat, accS + 256, accQ + 256, 128, 256);
    finalize_k<<<1, 256>>>(accS + 256, accQ + 256, g4, b4, scl + 256, shf + 256, 256, invMB);

    // maxk for layers 1-3 (+ conv4 fixup after its finalize)
    maxk_k<<<(MSML * 64  + 255) / 256, 256>>>(y1, scl + 0,   shf + 0,   cat, 64,  0);
    maxk_k<<<(MSML * 64  + 255) / 256, 256>>>(y2, scl + 64,  shf + 64,  cat, 64,  64);
    maxk_k<<<(MSML * 128 + 255) / 256, 256>>>(y3, scl + 128, shf + 128, cat, 128, 128);
    cat4fix_k<<<(MSML * 256 + 255) / 256, 256>>>(cat, scl + 256, shf + 256);

    // conv5: 512 <- 512, input already activated
    mma_gemm<false, false><<<dim3(8, MSML / 128), 128>>>(
        w5h, w5l, cat, nullptr, nullptr, y5, nullptr, accS + 512, accQ + 512, 512, 512);
    finalize_k<<<1, 512>>>(accS + 512, accQ + 512, g5, b5, scl + 512, shf + 512, 512, invMS);

    out_t<<<dim3(NPTS / 32, 16, BATCH), dim3(32, 8)>>>(y5, scl + 512, shf + 512, out);
}

// round 6
// speedup vs baseline: 2.9785x; 1.5687x over previous
#include <cuda_runtime.h>
#include <cuda_bf16.h>
#include <cstdint>
#include <math.h>

// ---------------- problem constants ----------------
#define BATCH 8
#define NPTS  2048
#define KNN   32
#define EMB   512
#define MBIG  (BATCH*NPTS*KNN)   // 524288
#define MSML  (BATCH*NPTS)       // 16384
#define BN_EPS 1e-5f

#define IDX_OFF  (BATCH*EMB*NPTS)                 // 8388608
#define NBR_OFF  (IDX_OFF + BATCH*NPTS*KNN)       // 8912896

#define NEG_BIG (-1e30f)

// ---------------- scratch ----------------
__device__ float g_feat[8u  * MBIG];     // [m][8] (6 used)
__device__ float g_y2 [64u  * MBIG];
__device__ float g_y3 [128u * MBIG];
__device__ float g_cat[512u * MSML];     // [pt][512]
__device__ float g_y5 [512u * MSML];
__device__ __nv_bfloat16 g_w2h[64*64],   g_w2l[64*64];
__device__ __nv_bfloat16 g_w3h[128*64],  g_w3l[128*64];
__device__ __nv_bfloat16 g_w4h[256*128], g_w4l[256*128];
__device__ __nv_bfloat16 g_w5h[512*512], g_w5l[512*512];
__device__ float g_accS[1024], g_accQ[1024], g_scl[1024], g_shf[1024];
__device__ float g_M[32];                // feat moments: [0..5]=sum, [6..26]=upper-tri M

// ---------------- helpers ----------------
__device__ __forceinline__ uint32_t smem_to_u32(const void* p) {
    uint32_t a;
    asm("{ .reg .u64 t; cvta.to.shared.u64 t, %1; cvt.u32.u64 %0, t; }" : "=r"(a) : "l"(p));
    return a;
}
__device__ __forceinline__ uint32_t packbf(float a, float b) {
    __nv_bfloat162 h = __floats2bfloat162_rn(a, b);
    return *(uint32_t*)&h;
}
__device__ __forceinline__ void ldsm4(uint32_t* r, uint32_t addr) {
    asm volatile("ldmatrix.sync.aligned.m8n8.x4.shared.b16 {%0,%1,%2,%3}, [%4];"
        : "=r"(r[0]), "=r"(r[1]), "=r"(r[2]), "=r"(r[3]) : "r"(addr));
}
__device__ __forceinline__ void mma16816(float* c, const uint32_t* a, uint32_t b0, uint32_t b1) {
    asm volatile("mma.sync.aligned.m16n8k16.row.col.f32.bf16.bf16.f32 "
        "{%0,%1,%2,%3}, {%4,%5,%6,%7}, {%8,%9}, {%0,%1,%2,%3};"
        : "+f"(c[0]), "+f"(c[1]), "+f"(c[2]), "+f"(c[3])
        : "r"(a[0]), "r"(a[1]), "r"(a[2]), "r"(a[3]), "r"(b0), "r"(b1));
}

// ---------------- zero accumulators ----------------
__global__ void zero_acc_k(float* s, float* q, float* m) {
    int i = blockIdx.x * blockDim.x + threadIdx.x;
    if (i < 1024) { s[i] = 0.f; q[i] = 0.f; }
    if (i < 32) m[i] = 0.f;
}

// ---------------- weight convert fp32 -> split bf16 hi/lo ----------------
__global__ void wconv_k(const float* W2, const float* W3, const float* W4, const float* W5,
                        __nv_bfloat16* w2h, __nv_bfloat16* w2l,
                        __nv_bfloat16* w3h, __nv_bfloat16* w3l,
                        __nv_bfloat16* w4h, __nv_bfloat16* w4l,
                        __nv_bfloat16* w5h, __nv_bfloat16* w5l)
{
    int i = blockIdx.x * blockDim.x + threadIdx.x;
    const float* src; __nv_bfloat16 *dh, *dl; int off;
    if      (i < 4096)   { src = W2; dh = w2h; dl = w2l; off = 0; }
    else if (i < 12288)  { src = W3; dh = w3h; dl = w3l; off = 4096; }
    else if (i < 45056)  { src = W4; dh = w4h; dl = w4l; off = 12288; }
    else if (i < 307200) { src = W5; dh = w5h; dl = w5l; off = 45056; }
    else return;
    int j = i - off;
    float w = src[j];
    __nv_bfloat16 h = __float2bfloat16(w);
    dh[j] = h;
    dl[j] = __float2bfloat16(w - __bfloat162float(h));
}

// ---------------- kNN v2: warp-per-point, chunked argmax ----------------
// smem: px,py,pz,pxx [2048] + per-warp dist [64 chunks x 33 (pad)]
#define KNN_SMEM ((8192 + 8 * 2112) * 4)
__global__ __launch_bounds__(256)
void knn_kernel(const float* __restrict__ x,
                float* __restrict__ outIdx,
                float* __restrict__ outNbr,
                float* __restrict__ feat)
{
    extern __shared__ float km[];
    float* px  = km;
    float* py  = km + 2048;
    float* pz  = km + 4096;
    float* pxx = km + 6144;
    float* sdall = km + 8192;

    int tid = threadIdx.x, wid = tid >> 5, lane = tid & 31;
    int b = blockIdx.x >> 8;
    int i = ((blockIdx.x & 255) << 3) + wid;     // this warp's point
    const float* xb = x + (size_t)b * 3 * NPTS;

    for (int j = tid; j < NPTS; j += 256) {
        float a0 = xb[j], a1 = xb[NPTS + j], a2 = xb[2 * NPTS + j];
        px[j] = a0; py[j] = a1; pz[j] = a2;
        pxx[j] = a0 * a0 + a1 * a1 + a2 * a2;
    }
    __syncthreads();

    float* sd = sdall + wid * 2112;
    float q0 = px[i], q1 = py[i], q2 = pz[i], qxx = pxx[i];

    // distances (identical expression to prior passing version)
    #pragma unroll 4
    for (int c = 0; c < 64; c++) {
        int j = c * 32 + lane;
        float dot   = q0 * px[j] + q1 * py[j] + q2 * pz[j];
        float inner = -2.f * dot;
        float t     = (-qxx) - inner;
        sd[c * 33 + lane] = t - pxx[j];
    }
    __syncwarp();

    // per-lane chunk maxima: lane owns chunks {lane, lane+32}
    float cm0 = -3.4e38f, cm1 = -3.4e38f;
    #pragma unroll 4
    for (int e = 0; e < 32; e++) {
        cm0 = fmaxf(cm0, sd[lane * 33 + e]);
        cm1 = fmaxf(cm1, sd[(lane + 32) * 33 + e]);
    }

    int jsel = 0;
    for (int k = 0; k < KNN; k++) {
        // best chunk (max value, min chunk index)
        float v; int c;
        if (cm0 >= cm1) { v = cm0; c = lane; } else { v = cm1; c = lane + 32; }
        #pragma unroll
        for (int off = 16; off; off >>= 1) {
            float ov = __shfl_down_sync(0xffffffffu, v, off);
            int   oc = __shfl_down_sync(0xffffffffu, c, off);
            if (ov > v || (ov == v && oc < c)) { v = ov; c = oc; }
        }
        c = __shfl_sync(0xffffffffu, c, 0);
        // rescan chunk c: (max value, min lane)
        float dv = sd[c * 33 + lane];
        float mv = dv; int ml = lane;
        #pragma unroll
        for (int off = 16; off; off >>= 1) {
            float omv = __shfl_down_sync(0xffffffffu, mv, off);
            int   oml = __shfl_down_sync(0xffffffffu, ml, off);
            if (omv > mv || (omv == mv && oml < ml)) { mv = omv; ml = oml; }
        }
        ml = __shfl_sync(0xffffffffu, ml, 0);
        int j = c * 32 + ml;
        if (lane == k) jsel = j;
        if (lane == ml) { dv = -3.4e38f; sd[c * 33 + ml] = dv; }
        // refresh this chunk's max
        float nm = dv;
        #pragma unroll
        for (int off = 16; off; off >>= 1)
            nm = fmaxf(nm, __shfl_xor_sync(0xffffffffu, nm, off));
        if (c < 32) { if (lane == c) cm0 = nm; }
        else        { if (lane == c - 32) cm1 = nm; }
        __syncwarp();
    }

    // outputs: lane k holds selection k
    int bn = b * NPTS + i;
    int m  = bn * KNN + lane;
    int j  = jsel;
    outIdx[m] = (float)(j + b * NPTS);
    float v0 = px[j], v1 = py[j], v2 = pz[j];
    size_t ofs = (size_t)m * 3;
    outNbr[ofs + 0] = v0; outNbr[ofs + 1] = v1; outNbr[ofs + 2] = v2;
    float* fp = feat + (size_t)m * 8;
    fp[0] = v0; fp[1] = v1; fp[2] = v2;
    fp[3] = q0; fp[4] = q1; fp[5] = q2;
}

// ---------------- feat moments: s[6] + upper-tri M[21] ----------------
__global__ __launch_bounds__(256)
void fstats_k(const float* __restrict__ feat, float* __restrict__ gM)
{
    __shared__ float red[8][27];
    int tid = threadIdx.x, wid = tid >> 5, lane = tid & 31;
    float a[27];
    #pragma unroll
    for (int t = 0; t < 27; t++) a[t] = 0.f;

    int base = blockIdx.x * 1024 + tid;
    #pragma unroll
    for (int it = 0; it < 4; it++) {
        const float4* fp = (const float4*)(feat + (size_t)(base + it * 256) * 8);
        float4 fa = fp[0], fb = fp[1];
        float f[6] = { fa.x, fa.y, fa.z, fa.w, fb.x, fb.y };
        #pragma unroll
        for (int t = 0; t < 6; t++) a[t] += f[t];
        int idx = 6;
        #pragma unroll
        for (int t = 0; t < 6; t++)
            #pragma unroll
            for (int u = t; u < 6; u++) a[idx++] += f[t] * f[u];
    }
    #pragma unroll
    for (int off = 16; off; off >>= 1)
        #pragma unroll
        for (int t = 0; t < 27; t++)
            a[t] += __shfl_down_sync(0xffffffffu, a[t], off);
    if (lane == 0)
        #pragma unroll
        for (int t = 0; t < 27; t++) red[wid][t] = a[t];
    __syncthreads();
    if (tid < 27) {
        float s = 0.f;
        #pragma unroll
        for (int w = 0; w < 8; w++) s += red[w][tid];
        atomicAdd(&gM[tid], s);
    }
}

// ---------------- layer-1 BN affine from analytic moments ----------------
__global__ void finalize1_k(const float* __restrict__ gM, const float* __restrict__ W1,
                            const float* __restrict__ g, const float* __restrict__ bta,
                            float* __restrict__ sc, float* __restrict__ sh)
{
    int o = threadIdx.x;   // 64
    float w[6];
    #pragma unroll
    for (int t = 0; t < 6; t++) w[t] = W1[o * 6 + t];
    const float invM = 1.f / (float)MBIG;
    float s = 0.f;
    #pragma unroll
    for (int t = 0; t < 6; t++) s += w[t] * gM[t];
    float mu = s * invM;
    float qq = 0.f; int idx = 6;
    #pragma unroll
    for (int t = 0; t < 6; t++)
        #pragma unroll
        for (int u = t; u < 6; u++) {
            float term = w[t] * w[u] * gM[idx++];
            qq += (t == u) ? term : 2.f * term;
        }
    float var  = qq * invM - mu * mu;
    float rstd = 1.f / sqrtf(var + BN_EPS);
    float scale = g[o] * rstd;
    sc[o] = scale;
    sh[o] = bta[o] - mu * scale;
}

// ---------------- bf16x3 split HMMA GEMM, heavily fused ----------------------
// A_FEAT: A rows computed on-the-fly as act(W1 * feat-row) (conv2).
// HAS_ACT: apply BN-relu of prev layer to loaded X rows.
// IN_MAX : per-point max of activated A rows -> catXin (input-side x_l).
// OUT_MAX: per-point raw max of outputs -> catXout (x4, fixed up later).
#define GEMM_SMEM (49152 + 1024 + 1536)
template <bool A_FEAT, bool HAS_ACT, bool IN_MAX, bool OUT_MAX>
__global__ __launch_bounds__(128)
void mma_gemm(const __nv_bfloat16* __restrict__ Wh, const __nv_bfloat16* __restrict__ Wl,
              const float* __restrict__ X, const float* __restrict__ W1,
              const float* __restrict__ sc, const float* __restrict__ sh,
              float* __restrict__ Y, float* __restrict__ catXin, float* __restrict__ catXout,
              float* __restrict__ accS, float* __restrict__ accQ,
              int Cin, int Cout)
{
    extern __shared__ __align__(16) uint8_t smem[];
    uint8_t* sAh = smem;
    uint8_t* sAl = smem + 16384;
    uint8_t* sBh = smem + 32768;
    uint8_t* sBl = smem + 40960;
    int*   xmax = (int*)(smem + 49152);    // 256
    float* w1s  = (float*)(smem + 50176);  // 384
    float* sS   = (float*)smem;            // alias sAh (epilogue only)
    float* sQ   = sS + 256;

    const int tid  = threadIdx.x;
    const int wid  = tid >> 5;
    const int lane = tid & 31;
    const int mBase = blockIdx.y * 128;
    const int oBase = blockIdx.x * 64;

    const uint32_t sAh_u = smem_to_u32(sAh);
    const uint32_t sAl_u = smem_to_u32(sAl);
    const uint32_t sBh_u = smem_to_u32(sBh);
    const uint32_t sBl_u = smem_to_u32(sBl);

    if (A_FEAT) for (int t = tid; t < 384; t += 128) w1s[t] = W1[t];
    if (IN_MAX) for (int t = tid; t < 256; t += 128) xmax[t] = 0;
    if (A_FEAT || IN_MAX) __syncthreads();

    float acc[2][8][4];
    #pragma unroll
    for (int mt = 0; mt < 2; mt++)
        #pragma unroll
        for (int nt = 0; nt < 8; nt++)
            #pragma unroll
            for (int t = 0; t < 4; t++) acc[mt][nt][t] = 0.f;

    const float4* Xv = (const float4*)X;
    const uint4* Whv = (const uint4*)Wh;
    const uint4* Wlv = (const uint4*)Wl;
    const int cinV = Cin >> 2;
    const int cinW = Cin >> 3;
    const int nkt  = Cin >> 6;

    for (int kt = 0; kt < nkt; kt++) {
        // ---- A tile: 128 rows x 64 cin ----
        float4 vmax = make_float4(0.f, 0.f, 0.f, 0.f);
        #pragma unroll
        for (int j = 0; j < 16; j++) {
            int linear = tid + j * 128;
            int row = linear >> 4, ch = linear & 15;
            float4 v;
            if (A_FEAT) {
                const float4* fr = (const float4*)(X + (size_t)(mBase + row) * 8);
                float4 fa = fr[0], fb = fr[1];
                float f0 = fa.x, f1 = fa.y, f2 = fa.z, f3 = fa.w, f4 = fb.x, f5 = fb.y;
                #pragma unroll
                for (int cc = 0; cc < 4; cc++) {
                    const float* w = &w1s[(ch * 4 + cc) * 6];
                    (&v.x)[cc] = w[0]*f0 + w[1]*f1 + w[2]*f2 + w[3]*f3 + w[4]*f4 + w[5]*f5;
                }
            } else {
                v = Xv[(size_t)(mBase + row) * cinV + kt * 16 + ch];
            }
            if (A_FEAT || HAS_ACT) {
                int cb = kt * 64 + ch * 4;
                float4 s4 = *(const float4*)(sc + cb);
                float4 t4 = *(const float4*)(sh + cb);
                v.x = fmaxf(fmaf(v.x, s4.x, t4.x), 0.f);
                v.y = fmaxf(fmaf(v.y, s4.y, t4.y), 0.f);
                v.z = fmaxf(fmaf(v.z, s4.z, t4.z), 0.f);
                v.w = fmaxf(fmaf(v.w, s4.w, t4.w), 0.f);
            }
            if (IN_MAX) {
                vmax.x = fmaxf(vmax.x, v.x); vmax.y = fmaxf(vmax.y, v.y);
                vmax.z = fmaxf(vmax.z, v.z); vmax.w = fmaxf(vmax.w, v.w);
                if ((j & 3) == 3) {
                    int base = (j >> 2) * 64 + (tid & 15) * 4;
                    atomicMax(&xmax[base + 0], __float_as_int(vmax.x));
                    atomicMax(&xmax[base + 1], __float_as_int(vmax.y));
                    atomicMax(&xmax[base + 2], __float_as_int(vmax.z));
                    atomicMax(&xmax[base + 3], __float_as_int(vmax.w));
                    vmax = make_float4(0.f, 0.f, 0.f, 0.f);
                }
            }
            float hx = __bfloat162float(__float2bfloat16(v.x));
            float hy = __bfloat162float(__float2bfloat16(v.y));
            float hz = __bfloat162float(__float2bfloat16(v.z));
            float hw = __bfloat162float(__float2bfloat16(v.w));
            uint32_t hi0 = packbf(v.x, v.y), hi1 = packbf(v.z, v.w);
            uint32_t lo0 = packbf(v.x - hx, v.y - hy), lo1 = packbf(v.z - hz, v.w - hw);
            int c = ch >> 1, sub = ch & 1;
            int addr = row * 128 + ((c ^ (row & 7)) << 4) + sub * 8;
            *(uint2*)(sAh + addr) = make_uint2(hi0, hi1);
            *(uint2*)(sAl + addr) = make_uint2(lo0, lo1);
        }
        // ---- B tiles ----
        #pragma unroll
        for (int j = 0; j < 4; j++) {
            int linear = tid + j * 128;
            int row = linear >> 3, ch = linear & 7;
            size_t gofs = (size_t)(oBase + row) * cinW + kt * 8 + ch;
            int addr = row * 128 + ((ch ^ (row & 7)) << 4);
            *(uint4*)(sBh + addr) = Whv[gofs];
            *(uint4*)(sBl + addr) = Wlv[gofs];
        }
        __syncthreads();

        // input-side max -> cat (one writer block per m-tile)
        if (IN_MAX && blockIdx.x == 0) {
            #pragma unroll
            for (int t = tid; t < 256; t += 128) {
                int p = t >> 6, chl = t & 63;
                catXin[(size_t)(blockIdx.y * 4 + p) * 512 + kt * 64 + chl] =
                    __int_as_float(xmax[t]);
            }
        }

        // ---- compute: 3-term split MMA ----
        #pragma unroll
        for (int ks = 0; ks < 4; ks++) {
            uint32_t ah[2][4], al[2][4];
            int chunk = 2 * ks + (lane >> 4);
            #pragma unroll
            for (int mt = 0; mt < 2; mt++) {
                int r = wid * 32 + mt * 16 + (lane & 15);
                int off = r * 128 + ((chunk ^ (r & 7)) << 4);
                ldsm4(ah[mt], sAh_u + off);
                ldsm4(al[mt], sAl_u + off);
            }
            #pragma unroll
            for (int ntp = 0; ntp < 4; ntp++) {
                uint32_t bh[4], bl[4];
                int r = ntp * 16 + (lane & 15);
                int off = r * 128 + ((chunk ^ (r & 7)) << 4);
                ldsm4(bh, sBh_u + off);
                ldsm4(bl, sBl_u + off);
                #pragma unroll
                for (int mt = 0; mt < 2; mt++) {
                    #pragma unroll
                    for (int nb = 0; nb < 2; nb++) {
                        float* c = acc[mt][2 * ntp + nb];
                        mma16816(c, ah[mt], bh[nb], bh[nb + 2]);
                        mma16816(c, ah[mt], bl[nb], bl[nb + 2]);
                        mma16816(c, al[mt], bh[nb], bh[nb + 2]);
                    }
                }
            }
        }
        // reset xmax for next k-tile (same thread->entries mapping as writes)
        if (IN_MAX && kt + 1 < nkt) {
            #pragma unroll
            for (int t = tid; t < 256; t += 128) xmax[t] = 0;
        }
        __syncthreads();
    }

    // ---- epilogue ----
    const int q4 = lane & 3;
    #pragma unroll
    for (int nt = 0; nt < 8; nt++) {
        int col = oBase + nt * 8 + q4 * 2;
        float se = 0.f, so = 0.f, qe = 0.f, qo = 0.f;
        #pragma unroll
        for (int mt = 0; mt < 2; mt++) {
            float* c = acc[mt][nt];
            if (!OUT_MAX) {
                int r0 = mBase + wid * 32 + mt * 16 + (lane >> 2);
                *(float2*)(Y + (size_t)r0 * Cout + col)       = make_float2(c[0], c[1]);
                *(float2*)(Y + (size_t)(r0 + 8) * Cout + col) = make_float2(c[2], c[3]);
            }
            se += c[0] + c[2];  so += c[1] + c[3];
            qe += c[0]*c[0] + c[2]*c[2];
            qo += c[1]*c[1] + c[3]*c[3];
        }
        if (OUT_MAX) {
            float m0 = fmaxf(fmaxf(acc[0][nt][0], acc[0][nt][2]),
                             fmaxf(acc[1][nt][0], acc[1][nt][2]));
            float m1 = fmaxf(fmaxf(acc[0][nt][1], acc[0][nt][3]),
                             fmaxf(acc[1][nt][1], acc[1][nt][3]));
            #pragma unroll
            for (int off = 16; off >= 4; off >>= 1) {
                m0 = fmaxf(m0, __shfl_xor_sync(0xffffffffu, m0, off));
                m1 = fmaxf(m1, __shfl_xor_sync(0xffffffffu, m1, off));
            }
            if (lane < 4) {
                int pt = blockIdx.y * 4 + wid;
                int cc = oBase + nt * 8 + lane * 2;
                catXout[(size_t)pt * 512 + cc]     = m0;
                catXout[(size_t)pt * 512 + cc + 1] = m1;
            }
        }
        #pragma unroll
        for (int off = 16; off >= 4; off >>= 1) {
            se += __shfl_down_sync(0xffffffffu, se, off);
            so += __shfl_down_sync(0xffffffffu, so, off);
            qe += __shfl_down_sync(0xffffffffu, qe, off);
            qo += __shfl_down_sync(0xffffffffu, qo, off);
        }
        if (lane < 4) {
            int chl = nt * 8 + lane * 2;
            sS[wid * 64 + chl]     = se;
            sS[wid * 64 + chl + 1] = so;
            sQ[wid * 64 + chl]     = qe;
            sQ[wid * 64 + chl + 1] = qo;
        }
    }
    __syncthreads();
    if (tid < 64) {
        float s = 0.f, q = 0.f;
        #pragma unroll
        for (int w = 0; w < 4; w++) { s += sS[w * 64 + tid]; q += sQ[w * 64 + tid]; }
        atomicAdd(&accS[oBase + tid], s);
        atomicAdd(&accQ[oBase + tid], q);
    }
}

// ---------------- finalize BN stats ----------------
__global__ void finalize_k(const float* __restrict__ accS, const float* __restrict__ accQ,
                           const float* __restrict__ g, const float* __restrict__ bta,
                           float* __restrict__ sc, float* __restrict__ sh,
                           int Cout, float invM)
{
    int o = blockIdx.x * blockDim.x + threadIdx.x;
    if (o < Cout) {
        float mu   = accS[o] * invM;
        float var  = accQ[o] * invM - mu * mu;
        float rstd = 1.f / sqrtf(var + BN_EPS);
        float s    = g[o] * rstd;
        sc[o] = s;
        sh[o] = bta[o] - mu * s;
    }
}

// ---------------- conv4 cat fixup: BN affine + relu on x4 section -----------
__global__ void cat4fix_k(float* __restrict__ cat,
                          const float* __restrict__ sc, const float* __restrict__ sh)
{
    int idx = blockIdx.x * blockDim.x + threadIdx.x;
    if (idx >= MSML * 256) return;
    int ch = idx & 255;
    int pt = idx >> 8;
    size_t ofs = (size_t)pt * 512 + 256 + ch;
    cat[ofs] = fmaxf(fmaf(cat[ofs], sc[ch], sh[ch]), 0.f);
}

// ---------------- output transpose + BN-ReLU --------------------------------
__global__ void out_t(const float* __restrict__ y5,
                      const float* __restrict__ sc, const float* __restrict__ sh,
                      float* __restrict__ out)
{
    __shared__ float ts[32][33];
    int tx = threadIdx.x, ty = threadIdx.y;
    int n0 = blockIdx.x * 32, ch0 = blockIdx.y * 32, b = blockIdx.z;
    float s = sc[ch0 + tx], t = sh[ch0 + tx];
    #pragma unroll
    for (int r = 0; r < 4; r++) {
        int nl = ty * 4 + r;
        int m = b * NPTS + n0 + nl;
        float v = y5[(size_t)m * 512 + ch0 + tx];
        ts[nl][tx] = fmaxf(fmaf(v, s, t), 0.f);
    }
    __syncthreads();
    #pragma unroll
    for (int r = 0; r < 4; r++) {
        int chl = ty * 4 + r;
        out[(size_t)b * (512 * NPTS) + (size_t)(ch0 + chl) * NPTS + n0 + tx] = ts[tx][chl];
    }
}

// ---------------- launcher ----------------
extern "C" void kernel_launch(void* const* d_in, const int* in_sizes, int n_in,
                              void* d_out, int out_size)
{
    const float* x  = (const float*)d_in[0];
    const float* W1 = (const float*)d_in[1];
    const float* g1 = (const float*)d_in[2];
    const float* b1 = (const float*)d_in[3];
    const float* W2 = (const float*)d_in[4];
    const float* g2 = (const float*)d_in[5];
    const float* b2 = (const float*)d_in[6];
    const float* W3 = (const float*)d_in[7];
    const float* g3 = (const float*)d_in[8];
    const float* b3 = (const float*)d_in[9];
    const float* W4 = (const float*)d_in[10];
    const float* g4 = (const float*)d_in[11];
    const float* b4 = (const float*)d_in[12];
    const float* W5 = (const float*)d_in[13];
    const float* g5 = (const float*)d_in[14];
    const float* b5 = (const float*)d_in[15];

    float* out    = (float*)d_out;
    float* outIdx = out + IDX_OFF;
    float* outNbr = out + NBR_OFF;

    float *feat, *y2, *y3, *cat, *y5, *accS, *accQ, *scl, *shf, *gM;
    __nv_bfloat16 *w2h, *w2l, *w3h, *w3l, *w4h, *w4l, *w5h, *w5l;
    cudaGetSymbolAddress((void**)&feat, g_feat);
    cudaGetSymbolAddress((void**)&y2,   g_y2);
    cudaGetSymbolAddress((void**)&y3,   g_y3);
    cudaGetSymbolAddress((void**)&cat,  g_cat);
    cudaGetSymbolAddress((void**)&y5,   g_y5);
    cudaGetSymbolAddress((void**)&w2h,  g_w2h);
    cudaGetSymbolAddress((void**)&w2l,  g_w2l);
    cudaGetSymbolAddress((void**)&w3h,  g_w3h);
    cudaGetSymbolAddress((void**)&w3l,  g_w3l);
    cudaGetSymbolAddress((void**)&w4h,  g_w4h);
    cudaGetSymbolAddress((void**)&w4l,  g_w4l);
    cudaGetSymbolAddress((void**)&w5h,  g_w5h);
    cudaGetSymbolAddress((void**)&w5l,  g_w5l);
    cudaGetSymbolAddress((void**)&accS, g_accS);
    cudaGetSymbolAddress((void**)&accQ, g_accQ);
    cudaGetSymbolAddress((void**)&scl,  g_scl);
    cudaGetSymbolAddress((void**)&shf,  g_shf);
    cudaGetSymbolAddress((void**)&gM,   g_M);

    // raise dynamic smem limits (host-side attribute, not a stream op)
    cudaFuncSetAttribute(knn_kernel, cudaFuncAttributeMaxDynamicSharedMemorySize, KNN_SMEM);
    auto* k2 = mma_gemm<true,  true,  true,  false>;
    auto* k3 = mma_gemm<false, true,  true,  false>;
    auto* k4 = mma_gemm<false, true,  true,  true >;
    auto* k5 = mma_gemm<false, false, false, false>;
    cudaFuncSetAttribute(k2, cudaFuncAttributeMaxDynamicSharedMemorySize, GEMM_SMEM);
    cudaFuncSetAttribute(k3, cudaFuncAttributeMaxDynamicSharedMemorySize, GEMM_SMEM);
    cudaFuncSetAttribute(k4, cudaFuncAttributeMaxDynamicSharedMemorySize, GEMM_SMEM);
    cudaFuncSetAttribute(k5, cudaFuncAttributeMaxDynamicSharedMemorySize, GEMM_SMEM);

    const float invMB = 1.f / (float)MBIG;
    const float invMS = 1.f / (float)MSML;

    zero_acc_k<<<4, 256>>>(accS, accQ, gM);                                   // 0
    wconv_k<<<(307200 + 255) / 256, 256>>>(W2, W3, W4, W5,                     // 1
                                           w2h, w2l, w3h, w3l, w4h, w4l, w5h, w5l);
    knn_kernel<<<2048, 256, KNN_SMEM>>>(x, outIdx, outNbr, feat);              // 2
    fstats_k<<<512, 256>>>(feat, gM);                                          // 3
    finalize1_k<<<1, 64>>>(gM, W1, g1, b1, scl + 0, shf + 0);                  // 4

    // conv2: inline conv1 from feat, act(scl1), x1 -> cat[0:64], out y2       // 5
    k2<<<dim3(1, MBIG / 128), 128, GEMM_SMEM>>>(
        w2h, w2l, feat, W1, scl + 0, shf + 0, y2, cat + 0, nullptr,
        accS + 64, accQ + 64, 64, 64);
    finalize_k<<<1, 64>>>(accS + 64, accQ + 64, g2, b2, scl + 64, shf + 64, 64, invMB);

    // conv3: act(scl2), x2 -> cat[64:128], out y3
    k3<<<dim3(2, MBIG / 128), 128, GEMM_SMEM>>>(
        w3h, w3l, y2, nullptr, scl + 64, shf + 64, y3, cat + 64, nullptr,
        accS + 128, accQ + 128, 64, 128);
    finalize_k<<<1, 128>>>(accS + 128, accQ + 128, g3, b3, scl + 128, shf + 128, 128, invMB);

    // conv4: act(scl3), x3 -> cat[128:256], raw x4 -> cat[256:512], no y4
    k4<<<dim3(4, MBIG / 128), 128, GEMM_SMEM>>>(
        w4h, w4l, y3, nullptr, scl + 128, shf + 128, nullptr, cat + 128, cat + 256,
        accS + 256, accQ + 256, 128, 256);
    finalize_k<<<1, 256>>>(accS + 256, accQ + 256, g4, b4, scl + 256, shf + 256, 256, invMB);
    cat4fix_k<<<(MSML * 256 + 255) / 256, 256>>>(cat, scl + 256, shf + 256);

    // conv5: cat already activated
    k5<<<dim3(8, MSML / 128), 128, GEMM_SMEM>>>(
        w5h, w5l, cat, nullptr, nullptr, nullptr, y5, nullptr, nullptr,
        accS + 512, accQ + 512, 512, 512);
    finalize_k<<<1, 512>>>(accS + 512, accQ + 512, g5, b5, scl + 512, shf + 512, 512, invMS);

    out_t<<<dim3(NPTS / 32, 16, BATCH), dim3(32, 8)>>>(y5, scl + 512, shf + 512, out);
}

// round 7
// speedup vs baseline: 3.2660x; 1.0965x over previous
#include <cuda_runtime.h>
#include <cuda_bf16.h>
#include <cstdint>
#include <math.h>

// ---------------- problem constants ----------------
#define BATCH 8
#define NPTS  2048
#define KNN   32
#define EMB   512
#define MBIG  (BATCH*NPTS*KNN)   // 524288
#define MSML  (BATCH*NPTS)       // 16384
#define BN_EPS 1e-5f
#define INV_MBIG (1.f / (float)MBIG)
#define INV_MSML (1.f / (float)MSML)

#define IDX_OFF  (BATCH*EMB*NPTS)                 // 8388608
#define NBR_OFF  (IDX_OFF + BATCH*NPTS*KNN)       // 8912896

// ---------------- scratch ----------------
__device__ float g_feat[8u  * MBIG];     // [m][8] (6 used)
__device__ float g_y2 [64u  * MBIG];
__device__ float g_y3 [128u * MBIG];
__device__ float g_cat[512u * MSML];     // [pt][512]
__device__ float g_y5 [512u * MSML];
__device__ __nv_bfloat16 g_w2h[64*64],   g_w2l[64*64];
__device__ __nv_bfloat16 g_w3h[128*64],  g_w3l[128*64];
__device__ __nv_bfloat16 g_w4h[256*128], g_w4l[256*128];
__device__ __nv_bfloat16 g_w5h[512*512], g_w5l[512*512];
__device__ float g_accS[1024], g_accQ[1024];
__device__ float g_M[32];                // feat moments: [0..5]=sum, [6..26]=upper-tri M

// ---------------- helpers ----------------
__device__ __forceinline__ uint32_t smem_to_u32(const void* p) {
    uint32_t a;
    asm("{ .reg .u64 t; cvta.to.shared.u64 t, %1; cvt.u32.u64 %0, t; }" : "=r"(a) : "l"(p));
    return a;
}
__device__ __forceinline__ uint32_t packbf(float a, float b) {
    __nv_bfloat162 h = __floats2bfloat162_rn(a, b);
    return *(uint32_t*)&h;
}
__device__ __forceinline__ void ldsm4(uint32_t* r, uint32_t addr) {
    asm volatile("ldmatrix.sync.aligned.m8n8.x4.shared.b16 {%0,%1,%2,%3}, [%4];"
        : "=r"(r[0]), "=r"(r[1]), "=r"(r[2]), "=r"(r[3]) : "r"(addr));
}
__device__ __forceinline__ void mma16816(float* c, const uint32_t* a, uint32_t b0, uint32_t b1) {
    asm volatile("mma.sync.aligned.m16n8k16.row.col.f32.bf16.bf16.f32 "
        "{%0,%1,%2,%3}, {%4,%5,%6,%7}, {%8,%9}, {%0,%1,%2,%3};"
        : "+f"(c[0]), "+f"(c[1]), "+f"(c[2]), "+f"(c[3])
        : "r"(a[0]), "r"(a[1]), "r"(a[2]), "r"(a[3]), "r"(b0), "r"(b1));
}
#define CP_COMMIT() asm volatile("cp.async.commit_group;" ::: "memory")
#define CP_WAIT(n)  asm volatile("cp.async.wait_group %0;" :: "n"(n) : "memory")

// BN affine from accumulated stats (same formula/order as prior finalize_k)
__device__ __forceinline__ void bn_affine(float as, float aq, float g, float bta,
                                          float invM, float& sc, float& sh) {
    float mu   = as * invM;
    float var  = aq * invM - mu * mu;
    float rstd = 1.f / sqrtf(var + BN_EPS);
    float s    = g * rstd;
    sc = s;
    sh = bta - mu * s;
}

// ---------------- zero accumulators ----------------
__global__ void zero_acc_k(float* s, float* q, float* m) {
    int i = blockIdx.x * blockDim.x + threadIdx.x;
    if (i < 1024) { s[i] = 0.f; q[i] = 0.f; }
    if (i < 32) m[i] = 0.f;
}

// ---------------- weight convert fp32 -> split bf16 hi/lo ----------------
__global__ void wconv_k(const float* W2, const float* W3, const float* W4, const float* W5,
                        __nv_bfloat16* w2h, __nv_bfloat16* w2l,
                        __nv_bfloat16* w3h, __nv_bfloat16* w3l,
                        __nv_bfloat16* w4h, __nv_bfloat16* w4l,
                        __nv_bfloat16* w5h, __nv_bfloat16* w5l)
{
    int i = blockIdx.x * blockDim.x + threadIdx.x;
    const float* src; __nv_bfloat16 *dh, *dl; int off;
    if      (i < 4096)   { src = W2; dh = w2h; dl = w2l; off = 0; }
    else if (i < 12288)  { src = W3; dh = w3h; dl = w3l; off = 4096; }
    else if (i < 45056)  { src = W4; dh = w4h; dl = w4l; off = 12288; }
    else if (i < 307200) { src = W5; dh = w5h; dl = w5l; off = 45056; }
    else return;
    int j = i - off;
    float w = src[j];
    __nv_bfloat16 h = __float2bfloat16(w);
    dh[j] = h;
    dl[j] = __float2bfloat16(w - __bfloat162float(h));
}

// ---------------- kNN: warp-per-point, chunked argmax ----------------
#define KNN_SMEM ((8192 + 8 * 2112) * 4)
__global__ __launch_bounds__(256)
void knn_kernel(const float* __restrict__ x,
                float* __restrict__ outIdx,
                float* __restrict__ outNbr,
                float* __restrict__ feat)
{
    extern __shared__ float km[];
    float* px  = km;
    float* py  = km + 2048;
    float* pz  = km + 4096;
    float* pxx = km + 6144;
    float* sdall = km + 8192;

    int tid = threadIdx.x, wid = tid >> 5, lane = tid & 31;
    int b = blockIdx.x >> 8;
    int i = ((blockIdx.x & 255) << 3) + wid;
    const float* xb = x + (size_t)b * 3 * NPTS;

    for (int j = tid; j < NPTS; j += 256) {
        float a0 = xb[j], a1 = xb[NPTS + j], a2 = xb[2 * NPTS + j];
        px[j] = a0; py[j] = a1; pz[j] = a2;
        pxx[j] = a0 * a0 + a1 * a1 + a2 * a2;
    }
    __syncthreads();

    float* sd = sdall + wid * 2112;
    float q0 = px[i], q1 = py[i], q2 = pz[i], qxx = pxx[i];

    #pragma unroll 4
    for (int c = 0; c < 64; c++) {
        int j = c * 32 + lane;
        float dot   = q0 * px[j] + q1 * py[j] + q2 * pz[j];
        float inner = -2.f * dot;
        float t     = (-qxx) - inner;
        sd[c * 33 + lane] = t - pxx[j];
    }
    __syncwarp();

    float cm0 = -3.4e38f, cm1 = -3.4e38f;
    #pragma unroll 4
    for (int e = 0; e < 32; e++) {
        cm0 = fmaxf(cm0, sd[lane * 33 + e]);
        cm1 = fmaxf(cm1, sd[(lane + 32) * 33 + e]);
    }

    int jsel = 0;
    for (int k = 0; k < KNN; k++) {
        float v; int c;
        if (cm0 >= cm1) { v = cm0; c = lane; } else { v = cm1; c = lane + 32; }
        #pragma unroll
        for (int off = 16; off; off >>= 1) {
            float ov = __shfl_down_sync(0xffffffffu, v, off);
            int   oc = __shfl_down_sync(0xffffffffu, c, off);
            if (ov > v || (ov == v && oc < c)) { v = ov; c = oc; }
        }
        c = __shfl_sync(0xffffffffu, c, 0);
        float dv = sd[c * 33 + lane];
        float mv = dv; int ml = lane;
        #pragma unroll
        for (int off = 16; off; off >>= 1) {
            float omv = __shfl_down_sync(0xffffffffu, mv, off);
            int   oml = __shfl_down_sync(0xffffffffu, ml, off);
            if (omv > mv || (omv == mv && oml < ml)) { mv = omv; ml = oml; }
        }
        ml = __shfl_sync(0xffffffffu, ml, 0);
        int j = c * 32 + ml;
        if (lane == k) jsel = j;
        if (lane == ml) { dv = -3.4e38f; sd[c * 33 + ml] = dv; }
        float nm = dv;
        #pragma unroll
        for (int off = 16; off; off >>= 1)
            nm = fmaxf(nm, __shfl_xor_sync(0xffffffffu, nm, off));
        if (c < 32) { if (lane == c) cm0 = nm; }
        else        { if (lane == c - 32) cm1 = nm; }
        __syncwarp();
    }

    int bn = b * NPTS + i;
    int m  = bn * KNN + lane;
    int j  = jsel;
    outIdx[m] = (float)(j + b * NPTS);
    float v0 = px[j], v1 = py[j], v2 = pz[j];
    size_t ofs = (size_t)m * 3;
    outNbr[ofs + 0] = v0; outNbr[ofs + 1] = v1; outNbr[ofs + 2] = v2;
    float* fp = feat + (size_t)m * 8;
    fp[0] = v0; fp[1] = v1; fp[2] = v2;
    fp[3] = q0; fp[4] = q1; fp[5] = q2;
}

// ---------------- feat moments ----------------
__global__ __launch_bounds__(256)
void fstats_k(const float* __restrict__ feat, float* __restrict__ gM)
{
    __shared__ float red[8][27];
    int tid = threadIdx.x, wid = tid >> 5, lane = tid & 31;
    float a[27];
    #pragma unroll
    for (int t = 0; t < 27; t++) a[t] = 0.f;

    int base = blockIdx.x * 1024 + tid;
    #pragma unroll
    for (int it = 0; it < 4; it++) {
        const float4* fp = (const float4*)(feat + (size_t)(base + it * 256) * 8);
        float4 fa = fp[0], fb = fp[1];
        float f[6] = { fa.x, fa.y, fa.z, fa.w, fb.x, fb.y };
        #pragma unroll
        for (int t = 0; t < 6; t++) a[t] += f[t];
        int idx = 6;
        #pragma unroll
        for (int t = 0; t < 6; t++)
            #pragma unroll
            for (int u = t; u < 6; u++) a[idx++] += f[t] * f[u];
    }
    #pragma unroll
    for (int off = 16; off; off >>= 1)
        #pragma unroll
        for (int t = 0; t < 27; t++)
            a[t] += __shfl_down_sync(0xffffffffu, a[t], off);
    if (lane == 0)
        #pragma unroll
        for (int t = 0; t < 27; t++) red[wid][t] = a[t];
    __syncthreads();
    if (tid < 27) {
        float s = 0.f;
        #pragma unroll
        for (int w = 0; w < 8; w++) s += red[w][tid];
        atomicAdd(&gM[tid], s);
    }
}

// ---------------- conv2: 128-thread, inline conv1 + affine1, N=64 ------------
// smem: sAh 0, sAl 16384, sBh 32768, sBl 40960, xmax 49152, w1s 50176, aff 51712
#define CONV2_SMEM 52224
__global__ __launch_bounds__(128)
void conv2_k(const __nv_bfloat16* __restrict__ Wh, const __nv_bfloat16* __restrict__ Wl,
             const float* __restrict__ feat, const float* __restrict__ W1,
             const float* __restrict__ gM,
             const float* __restrict__ g1, const float* __restrict__ b1,
             float* __restrict__ Y, float* __restrict__ catXin,
             float* __restrict__ accS, float* __restrict__ accQ)
{
    extern __shared__ __align__(16) uint8_t smem[];
    uint8_t* sAh = smem;
    uint8_t* sAl = smem + 16384;
    uint8_t* sBh = smem + 32768;
    uint8_t* sBl = smem + 40960;
    int*   xmax = (int*)(smem + 49152);
    float* w1s  = (float*)(smem + 50176);
    float* scs  = (float*)(smem + 51712);
    float* shs  = scs + 64;
    float* sS   = (float*)smem;     // epilogue alias
    float* sQ   = sS + 256;

    const int tid  = threadIdx.x;
    const int wid  = tid >> 5;
    const int lane = tid & 31;
    const int mBase = blockIdx.y * 128;

    const uint32_t sAh_u = smem_to_u32(sAh);
    const uint32_t sAl_u = smem_to_u32(sAl);
    const uint32_t sBh_u = smem_to_u32(sBh);
    const uint32_t sBl_u = smem_to_u32(sBl);

    for (int t = tid; t < 384; t += 128) w1s[t] = W1[t];
    for (int t = tid; t < 256; t += 128) xmax[t] = 0;
    // inline finalize1: analytic BN affine for layer 1
    if (tid < 64) {
        int o = tid;
        float w[6];
        #pragma unroll
        for (int t = 0; t < 6; t++) w[t] = W1[o * 6 + t];
        float s = 0.f;
        #pragma unroll
        for (int t = 0; t < 6; t++) s += w[t] * gM[t];
        float mu = s * INV_MBIG;
        float qq = 0.f; int idx = 6;
        #pragma unroll
        for (int t = 0; t < 6; t++)
            #pragma unroll
            for (int u = t; u < 6; u++) {
                float term = w[t] * w[u] * gM[idx++];
                qq += (t == u) ? term : 2.f * term;
            }
        float var  = qq * INV_MBIG - mu * mu;
        float rstd = 1.f / sqrtf(var + BN_EPS);
        float scale = g1[o] * rstd;
        scs[o] = scale;
        shs[o] = b1[o] - mu * scale;
    }
    __syncthreads();

    float acc[2][8][4];
    #pragma unroll
    for (int mt = 0; mt < 2; mt++)
        #pragma unroll
        for (int nt = 0; nt < 8; nt++)
            #pragma unroll
            for (int t = 0; t < 4; t++) acc[mt][nt][t] = 0.f;

    const uint4* Whv = (const uint4*)Wh;
    const uint4* Wlv = (const uint4*)Wl;

    // ---- A tile: inline conv1 + act + split, with input-side max ----
    {
        float4 vmax = make_float4(0.f, 0.f, 0.f, 0.f);
        #pragma unroll
        for (int j = 0; j < 16; j++) {
            int linear = tid + j * 128;
            int row = linear >> 4, ch = linear & 15;
            const float4* fr = (const float4*)(feat + (size_t)(mBase + row) * 8);
            float4 fa = fr[0], fb = fr[1];
            float f0 = fa.x, f1 = fa.y, f2 = fa.z, f3 = fa.w, f4 = fb.x, f5 = fb.y;
            float4 v;
            #pragma unroll
            for (int cc = 0; cc < 4; cc++) {
                const float* w = &w1s[(ch * 4 + cc) * 6];
                (&v.x)[cc] = w[0]*f0 + w[1]*f1 + w[2]*f2 + w[3]*f3 + w[4]*f4 + w[5]*f5;
            }
            int cb = ch * 4;
            float4 s4 = *(const float4*)(scs + cb);
            float4 t4 = *(const float4*)(shs + cb);
            v.x = fmaxf(fmaf(v.x, s4.x, t4.x), 0.f);
            v.y = fmaxf(fmaf(v.y, s4.y, t4.y), 0.f);
            v.z = fmaxf(fmaf(v.z, s4.z, t4.z), 0.f);
            v.w = fmaxf(fmaf(v.w, s4.w, t4.w), 0.f);
            vmax.x = fmaxf(vmax.x, v.x); vmax.y = fmaxf(vmax.y, v.y);
            vmax.z = fmaxf(vmax.z, v.z); vmax.w = fmaxf(vmax.w, v.w);
            if ((j & 3) == 3) {
                int base = (j >> 2) * 64 + (tid & 15) * 4;
                atomicMax(&xmax[base + 0], __float_as_int(vmax.x));
                atomicMax(&xmax[base + 1], __float_as_int(vmax.y));
                atomicMax(&xmax[base + 2], __float_as_int(vmax.z));
                atomicMax(&xmax[base + 3], __float_as_int(vmax.w));
                vmax = make_float4(0.f, 0.f, 0.f, 0.f);
            }
            float hx = __bfloat162float(__float2bfloat16(v.x));
            float hy = __bfloat162float(__float2bfloat16(v.y));
            float hz = __bfloat162float(__float2bfloat16(v.z));
            float hw = __bfloat162float(__float2bfloat16(v.w));
            int c = ch >> 1, sub = ch & 1;
            int addr = row * 128 + ((c ^ (row & 7)) << 4) + sub * 8;
            *(uint2*)(sAh + addr) = make_uint2(packbf(v.x, v.y), packbf(v.z, v.w));
            *(uint2*)(sAl + addr) = make_uint2(packbf(v.x - hx, v.y - hy), packbf(v.z - hz, v.w - hw));
        }
    }
    // ---- B tiles: 64 rows x 64 cin ----
    #pragma unroll
    for (int j = 0; j < 4; j++) {
        int linear = tid + j * 128;
        int row = linear >> 3, ch = linear & 7;
        size_t gofs = (size_t)row * 8 + ch;
        int addr = row * 128 + ((ch ^ (row & 7)) << 4);
        *(uint4*)(sBh + addr) = Whv[gofs];
        *(uint4*)(sBl + addr) = Wlv[gofs];
    }
    __syncthreads();

    // x1 -> cat[0:64]
    #pragma unroll
    for (int t = tid; t < 256; t += 128) {
        int p = t >> 6, chl = t & 63;
        catXin[(size_t)(blockIdx.y * 4 + p) * 512 + chl] = __int_as_float(xmax[t]);
    }

    // ---- compute ----
    #pragma unroll
    for (int ks = 0; ks < 4; ks++) {
        uint32_t ah[2][4], al[2][4];
        int chunk = 2 * ks + (lane >> 4);
        #pragma unroll
        for (int mt = 0; mt < 2; mt++) {
            int r = wid * 32 + mt * 16 + (lane & 15);
            int off = r * 128 + ((chunk ^ (r & 7)) << 4);
            ldsm4(ah[mt], sAh_u + off);
            ldsm4(al[mt], sAl_u + off);
        }
        #pragma unroll
        for (int ntp = 0; ntp < 4; ntp++) {
            uint32_t bh[4], bl[4];
            int r = ntp * 16 + (lane & 15);
            int off = r * 128 + ((chunk ^ (r & 7)) << 4);
            ldsm4(bh, sBh_u + off);
            ldsm4(bl, sBl_u + off);
            #pragma unroll
            for (int mt = 0; mt < 2; mt++) {
                #pragma unroll
                for (int nb = 0; nb < 2; nb++) {
                    float* c = acc[mt][2 * ntp + nb];
                    mma16816(c, ah[mt], bh[nb], bh[nb + 2]);
                    mma16816(c, ah[mt], bl[nb], bl[nb + 2]);
                    mma16816(c, al[mt], bh[nb], bh[nb + 2]);
                }
            }
        }
    }
    __syncthreads();

    // ---- epilogue: y2 + stats ----
    const int q4 = lane & 3;
    #pragma unroll
    for (int nt = 0; nt < 8; nt++) {
        int col = nt * 8 + q4 * 2;
        float se = 0.f, so = 0.f, qe = 0.f, qo = 0.f;
        #pragma unroll
        for (int mt = 0; mt < 2; mt++) {
            float* c = acc[mt][nt];
            int r0 = mBase + wid * 32 + mt * 16 + (lane >> 2);
            *(float2*)(Y + (size_t)r0 * 64 + col)       = make_float2(c[0], c[1]);
            *(float2*)(Y + (size_t)(r0 + 8) * 64 + col) = make_float2(c[2], c[3]);
            se += c[0] + c[2];  so += c[1] + c[3];
            qe += c[0]*c[0] + c[2]*c[2];
            qo += c[1]*c[1] + c[3]*c[3];
        }
        #pragma unroll
        for (int off = 16; off >= 4; off >>= 1) {
            se += __shfl_down_sync(0xffffffffu, se, off);
            so += __shfl_down_sync(0xffffffffu, so, off);
            qe += __shfl_down_sync(0xffffffffu, qe, off);
            qo += __shfl_down_sync(0xffffffffu, qo, off);
        }
        if (lane < 4) {
            int chl = nt * 8 + lane * 2;
            sS[wid * 64 + chl]     = se;
            sS[wid * 64 + chl + 1] = so;
            sQ[wid * 64 + chl]     = qe;
            sQ[wid * 64 + chl + 1] = qo;
        }
    }
    __syncthreads();
    if (tid < 64) {
        float s = 0.f, q = 0.f;
        #pragma unroll
        for (int w = 0; w < 4; w++) { s += sS[w * 64 + tid]; q += sQ[w * 64 + tid]; }
        atomicAdd(&accS[tid], s);
        atomicAdd(&accQ[tid], q);
    }
}

// ---------------- 256-thread 128x128 bf16x3 GEMM, pipelined ------------------
// smem: sAh 0, sAl 16384, sB 32768 (2 stages x 32KB, lo at +16KB),
//       aff 98304 (scs512+shs512), xmax 102400
#define G256_SB    32768
#define G256_AFF   98304
#define G256_XMAX  102400
#define G256_SMEM  103424
template <bool HAS_ACT, bool IN_MAX, bool OUT_MAX, bool WRITE_Y>
__global__ __launch_bounds__(256)
void mma_gemm256(const __nv_bfloat16* __restrict__ Wh, const __nv_bfloat16* __restrict__ Wl,
                 const float* __restrict__ X,
                 const float* __restrict__ accSin, const float* __restrict__ accQin,
                 const float* __restrict__ gIn, const float* __restrict__ bIn,
                 float* __restrict__ Y, float* __restrict__ catXin, float* __restrict__ catXout,
                 float* __restrict__ accS, float* __restrict__ accQ,
                 int Cin, int Cout)
{
    extern __shared__ __align__(16) uint8_t smem[];
    uint8_t* sAh = smem;
    uint8_t* sAl = smem + 16384;
    float* scs  = (float*)(smem + G256_AFF);
    float* shs  = scs + 512;
    int*   xmax = (int*)(smem + G256_XMAX);
    float* sS   = (float*)smem;      // epilogue alias of sAh
    float* sQ   = sS + 512;

    const int tid  = threadIdx.x;
    const int wid  = tid >> 5;
    const int lane = tid & 31;
    const int m_warp = wid & 3;
    const int n_warp = wid >> 2;
    const int mBase = blockIdx.y * 128;
    const int oBase = blockIdx.x * 128;

    const uint32_t smem_u = smem_to_u32(smem);
    const uint32_t sAh_u = smem_u;
    const uint32_t sAl_u = smem_u + 16384;

    const float4* Xv = (const float4*)X;
    const uint4* Whv = (const uint4*)Wh;
    const uint4* Wlv = (const uint4*)Wl;
    const int cinV = Cin >> 2;
    const int cinW = Cin >> 3;
    const int nkt  = Cin >> 6;

    // inline affine of previous layer
    if (HAS_ACT) {
        for (int ch = tid; ch < Cin; ch += 256)
            bn_affine(accSin[ch], accQin[ch], gIn[ch], bIn[ch], INV_MBIG, scs[ch], shs[ch]);
    }
    if (IN_MAX) { if (tid < 256) xmax[tid] = 0; }

    // B(0) via cp.async
    {
        uint32_t sB0 = smem_u + G256_SB;
        #pragma unroll
        for (int j = 0; j < 4; j++) {
            int linear = tid + j * 256;
            int row = linear >> 3, ch = linear & 7;
            uint32_t addr = sB0 + row * 128 + ((ch ^ (row & 7)) << 4);
            const uint4* sh_ = &Whv[(size_t)(oBase + row) * cinW + ch];
            const uint4* sl_ = &Wlv[(size_t)(oBase + row) * cinW + ch];
            asm volatile("cp.async.cg.shared.global [%0], [%1], 16;" :: "r"(addr), "l"(sh_) : "memory");
            asm volatile("cp.async.cg.shared.global [%0], [%1], 16;" :: "r"(addr + 16384), "l"(sl_) : "memory");
        }
        CP_COMMIT();
    }
    // A(0) into registers
    float4 areg[8];
    #pragma unroll
    for (int j = 0; j < 8; j++) {
        int linear = tid + j * 256;
        int row = linear >> 4, ch = linear & 15;
        areg[j] = Xv[(size_t)(mBase + row) * cinV + ch];
    }
    __syncthreads();

    float acc[2][8][4];
    #pragma unroll
    for (int mt = 0; mt < 2; mt++)
        #pragma unroll
        for (int nt = 0; nt < 8; nt++)
            #pragma unroll
            for (int t = 0; t < 4; t++) acc[mt][nt][t] = 0.f;

    for (int kt = 0; kt < nkt; kt++) {
        // prefetch B(kt+1)
        if (kt + 1 < nkt) {
            uint32_t sBn = smem_u + G256_SB + ((kt + 1) & 1) * 32768;
            #pragma unroll
            for (int j = 0; j < 4; j++) {
                int linear = tid + j * 256;
                int row = linear >> 3, ch = linear & 7;
                uint32_t addr = sBn + row * 128 + ((ch ^ (row & 7)) << 4);
                const uint4* sh_ = &Whv[(size_t)(oBase + row) * cinW + (kt + 1) * 8 + ch];
                const uint4* sl_ = &Wlv[(size_t)(oBase + row) * cinW + (kt + 1) * 8 + ch];
                asm volatile("cp.async.cg.shared.global [%0], [%1], 16;" :: "r"(addr), "l"(sh_) : "memory");
                asm volatile("cp.async.cg.shared.global [%0], [%1], 16;" :: "r"(addr + 16384), "l"(sl_) : "memory");
            }
            CP_COMMIT();
        }

        // convert A(kt) from registers -> smem (+ act + in-max)
        {
            float4 vmax = make_float4(0.f, 0.f, 0.f, 0.f);
            #pragma unroll
            for (int j = 0; j < 8; j++) {
                int linear = tid + j * 256;
                int row = linear >> 4, ch = linear & 15;
                float4 v = areg[j];
                if (HAS_ACT) {
                    int cb = kt * 64 + ch * 4;
                    float4 s4 = *(const float4*)(scs + cb);
                    float4 t4 = *(const float4*)(shs + cb);
                    v.x = fmaxf(fmaf(v.x, s4.x, t4.x), 0.f);
                    v.y = fmaxf(fmaf(v.y, s4.y, t4.y), 0.f);
                    v.z = fmaxf(fmaf(v.z, s4.z, t4.z), 0.f);
                    v.w = fmaxf(fmaf(v.w, s4.w, t4.w), 0.f);
                }
                if (IN_MAX) {
                    vmax.x = fmaxf(vmax.x, v.x); vmax.y = fmaxf(vmax.y, v.y);
                    vmax.z = fmaxf(vmax.z, v.z); vmax.w = fmaxf(vmax.w, v.w);
                    if (j & 1) {
                        int pt = j >> 1;
                        int base = pt * 64 + ch * 4;
                        atomicMax(&xmax[base + 0], __float_as_int(vmax.x));
                        atomicMax(&xmax[base + 1], __float_as_int(vmax.y));
                        atomicMax(&xmax[base + 2], __float_as_int(vmax.z));
                        atomicMax(&xmax[base + 3], __float_as_int(vmax.w));
                        vmax = make_float4(0.f, 0.f, 0.f, 0.f);
                    }
                }
                float hx = __bfloat162float(__float2bfloat16(v.x));
                float hy = __bfloat162float(__float2bfloat16(v.y));
                float hz = __bfloat162float(__float2bfloat16(v.z));
                float hw = __bfloat162float(__float2bfloat16(v.w));
                int c = ch >> 1, sub = ch & 1;
                int addr = row * 128 + ((c ^ (row & 7)) << 4) + sub * 8;
                *(uint2*)(sAh + addr) = make_uint2(packbf(v.x, v.y), packbf(v.z, v.w));
                *(uint2*)(sAl + addr) = make_uint2(packbf(v.x - hx, v.y - hy), packbf(v.z - hz, v.w - hw));
            }
        }
        // B(kt) must be resident
        if (kt + 1 < nkt) { CP_WAIT(1); } else { CP_WAIT(0); }
        __syncthreads();

        // input-side max -> cat (one n-block writes), then reset
        if (IN_MAX && tid < 256) {
            if (blockIdx.x == 0) {
                int p = tid >> 6, chl = tid & 63;
                catXin[(size_t)(blockIdx.y * 4 + p) * 512 + kt * 64 + chl] =
                    __int_as_float(xmax[tid]);
            }
            if (kt + 1 < nkt) xmax[tid] = 0;
        }

        // prefetch A(kt+1) into registers (overlaps MMA below)
        if (kt + 1 < nkt) {
            #pragma unroll
            for (int j = 0; j < 8; j++) {
                int linear = tid + j * 256;
                int row = linear >> 4, ch = linear & 15;
                areg[j] = Xv[(size_t)(mBase + row) * cinV + (kt + 1) * 16 + ch];
            }
        }

        // ---- MMA ----
        {
            const uint32_t sBh_u = smem_u + G256_SB + (kt & 1) * 32768;
            const uint32_t sBl_u = sBh_u + 16384;
            #pragma unroll
            for (int ks = 0; ks < 4; ks++) {
                uint32_t ah[2][4], al[2][4];
                int chunk = 2 * ks + (lane >> 4);
                #pragma unroll
                for (int mt = 0; mt < 2; mt++) {
                    int r = m_warp * 32 + mt * 16 + (lane & 15);
                    int off = r * 128 + ((chunk ^ (r & 7)) << 4);
                    ldsm4(ah[mt], sAh_u + off);
                    ldsm4(al[mt], sAl_u + off);
                }
                #pragma unroll
                for (int ntp = 0; ntp < 4; ntp++) {
                    uint32_t bh[4], bl[4];
                    int r = n_warp * 64 + ntp * 16 + (lane & 15);
                    int off = r * 128 + ((chunk ^ (r & 7)) << 4);
                    ldsm4(bh, sBh_u + off);
                    ldsm4(bl, sBl_u + off);
                    #pragma unroll
                    for (int mt = 0; mt < 2; mt++) {
                        #pragma unroll
                        for (int nb = 0; nb < 2; nb++) {
                            float* c = acc[mt][2 * ntp + nb];
                            mma16816(c, ah[mt], bh[nb], bh[nb + 2]);
                            mma16816(c, ah[mt], bl[nb], bl[nb + 2]);
                            mma16816(c, al[mt], bh[nb], bh[nb + 2]);
                        }
                    }
                }
            }
        }
        __syncthreads();
    }

    // ---- epilogue ----
    const int q4 = lane & 3;
    #pragma unroll
    for (int nt = 0; nt < 8; nt++) {
        int col = oBase + n_warp * 64 + nt * 8 + q4 * 2;
        float se = 0.f, so = 0.f, qe = 0.f, qo = 0.f;
        #pragma unroll
        for (int mt = 0; mt < 2; mt++) {
            float* c = acc[mt][nt];
            if (WRITE_Y) {
                int r0 = mBase + m_warp * 32 + mt * 16 + (lane >> 2);
                *(float2*)(Y + (size_t)r0 * Cout + col)       = make_float2(c[0], c[1]);
                *(float2*)(Y + (size_t)(r0 + 8) * Cout + col) = make_float2(c[2], c[3]);
            }
            se += c[0] + c[2];  so += c[1] + c[3];
            qe += c[0]*c[0] + c[2]*c[2];
            qo += c[1]*c[1] + c[3]*c[3];
        }
        if (OUT_MAX) {
            float m0 = fmaxf(fmaxf(acc[0][nt][0], acc[0][nt][2]),
                             fmaxf(acc[1][nt][0], acc[1][nt][2]));
            float m1 = fmaxf(fmaxf(acc[0][nt][1], acc[0][nt][3]),
                             fmaxf(acc[1][nt][1], acc[1][nt][3]));
            #pragma unroll
            for (int off = 16; off >= 4; off >>= 1) {
                m0 = fmaxf(m0, __shfl_xor_sync(0xffffffffu, m0, off));
                m1 = fmaxf(m1, __shfl_xor_sync(0xffffffffu, m1, off));
            }
            if (lane < 4) {
                int pt = blockIdx.y * 4 + m_warp;
                int cc = oBase + n_warp * 64 + nt * 8 + lane * 2;
                catXout[(size_t)pt * 512 + cc]     = m0;
                catXout[(size_t)pt * 512 + cc + 1] = m1;
            }
        }
        #pragma unroll
        for (int off = 16; off >= 4; off >>= 1) {
            se += __shfl_down_sync(0xffffffffu, se, off);
            so += __shfl_down_sync(0xffffffffu, so, off);
            qe += __shfl_down_sync(0xffffffffu, qe, off);
            qo += __shfl_down_sync(0xffffffffu, qo, off);
        }
        if (lane < 4) {
            int chl = n_warp * 64 + nt * 8 + lane * 2;
            sS[m_warp * 128 + chl]     = se;
            sS[m_warp * 128 + chl + 1] = so;
            sQ[m_warp * 128 + chl]     = qe;
            sQ[m_warp * 128 + chl + 1] = qo;
        }
    }
    __syncthreads();
    if (tid < 128) {
        float s = 0.f, q = 0.f;
        #pragma unroll
        for (int w = 0; w < 4; w++) { s += sS[w * 128 + tid]; q += sQ[w * 128 + tid]; }
        atomicAdd(&accS[oBase + tid], s);
        atomicAdd(&accQ[oBase + tid], q);
    }
}

// ---------------- conv4 cat fixup with inline affine4 -----------------------
__global__ void cat4fix_k(float* __restrict__ cat,
                          const float* __restrict__ accS, const float* __restrict__ accQ,
                          const float* __restrict__ g, const float* __restrict__ bta)
{
    int tid = threadIdx.x;           // = channel (blocks are 256-aligned)
    int pt  = blockIdx.x;
    float sc, sh;
    bn_affine(accS[tid], accQ[tid], g[tid], bta[tid], INV_MBIG, sc, sh);
    size_t ofs = (size_t)pt * 512 + 256 + tid;
    cat[ofs] = fmaxf(fmaf(cat[ofs], sc, sh), 0.f);
}

// ---------------- output transpose + inline affine5 + BN-ReLU ---------------
__global__ void out_t(const float* __restrict__ y5,
                      const float* __restrict__ accS, const float* __restrict__ accQ,
                      const float* __restrict__ g, const float* __restrict__ bta,
                      float* __restrict__ out)
{
    __shared__ float ts[32][33];
    int tx = threadIdx.x, ty = threadIdx.y;
    int n0 = blockIdx.x * 32, ch0 = blockIdx.y * 32, b = blockIdx.z;
    int ch = ch0 + tx;
    float s, t;
    bn_affine(accS[ch], accQ[ch], g[ch], bta[ch], INV_MSML, s, t);
    #pragma unroll
    for (int r = 0; r < 4; r++) {
        int nl = ty * 4 + r;
        int m = b * NPTS + n0 + nl;
        float v = y5[(size_t)m * 512 + ch];
        ts[nl][tx] = fmaxf(fmaf(v, s, t), 0.f);
    }
    __syncthreads();
    #pragma unroll
    for (int r = 0; r < 4; r++) {
        int chl = ty * 4 + r;
        out[(size_t)b * (512 * NPTS) + (size_t)(ch0 + chl) * NPTS + n0 + tx] = ts[tx][chl];
    }
}

// ---------------- launcher ----------------
extern "C" void kernel_launch(void* const* d_in, const int* in_sizes, int n_in,
                              void* d_out, int out_size)
{
    const float* x  = (const float*)d_in[0];
    const float* W1 = (const float*)d_in[1];
    const float* g1 = (const float*)d_in[2];
    const float* b1 = (const float*)d_in[3];
    const float* W2 = (const float*)d_in[4];
    const float* g2 = (const float*)d_in[5];
    const float* b2 = (const float*)d_in[6];
    const float* W3 = (const float*)d_in[7];
    const float* g3 = (const float*)d_in[8];
    const float* b3 = (const float*)d_in[9];
    const float* W4 = (const float*)d_in[10];
    const float* g4 = (const float*)d_in[11];
    const float* b4 = (const float*)d_in[12];
    const float* W5 = (const float*)d_in[13];
    const float* g5 = (const float*)d_in[14];
    const float* b5 = (const float*)d_in[15];

    float* out    = (float*)d_out;
    float* outIdx = out + IDX_OFF;
    float* outNbr = out + NBR_OFF;

    float *feat, *y2, *y3, *cat, *y5, *accS, *accQ, *gM;
    __nv_bfloat16 *w2h, *w2l, *w3h, *w3l, *w4h, *w4l, *w5h, *w5l;
    cudaGetSymbolAddress((void**)&feat, g_feat);
    cudaGetSymbolAddress((void**)&y2,   g_y2);
    cudaGetSymbolAddress((void**)&y3,   g_y3);
    cudaGetSymbolAddress((void**)&cat,  g_cat);
    cudaGetSymbolAddress((void**)&y5,   g_y5);
    cudaGetSymbolAddress((void**)&w2h,  g_w2h);
    cudaGetSymbolAddress((void**)&w2l,  g_w2l);
    cudaGetSymbolAddress((void**)&w3h,  g_w3h);
    cudaGetSymbolAddress((void**)&w3l,  g_w3l);
    cudaGetSymbolAddress((void**)&w4h,  g_w4h);
    cudaGetSymbolAddress((void**)&w4l,  g_w4l);
    cudaGetSymbolAddress((void**)&w5h,  g_w5h);
    cudaGetSymbolAddress((void**)&w5l,  g_w5l);
    cudaGetSymbolAddress((void**)&accS, g_accS);
    cudaGetSymbolAddress((void**)&accQ, g_accQ);
    cudaGetSymbolAddress((void**)&gM,   g_M);

    cudaFuncSetAttribute(knn_kernel, cudaFuncAttributeMaxDynamicSharedMemorySize, KNN_SMEM);
    cudaFuncSetAttribute(conv2_k,    cudaFuncAttributeMaxDynamicSharedMemorySize, CONV2_SMEM);
    auto* k3 = mma_gemm256<true,  true,  false, true >;
    auto* k4 = mma_gemm256<true,  true,  true,  false>;
    auto* k5 = mma_gemm256<false, false, false, true >;
    cudaFuncSetAttribute(k3, cudaFuncAttributeMaxDynamicSharedMemorySize, G256_SMEM);
    cudaFuncSetAttribute(k4, cudaFuncAttributeMaxDynamicSharedMemorySize, G256_SMEM);
    cudaFuncSetAttribute(k5, cudaFuncAttributeMaxDynamicSharedMemorySize, G256_SMEM);

    zero_acc_k<<<4, 256>>>(accS, accQ, gM);
    wconv_k<<<(307200 + 255) / 256, 256>>>(W2, W3, W4, W5,
                                           w2h, w2l, w3h, w3l, w4h, w4l, w5h, w5l);
    knn_kernel<<<2048, 256, KNN_SMEM>>>(x, outIdx, outNbr, feat);
    fstats_k<<<512, 256>>>(feat, gM);

    // conv2: inline conv1+affine1, x1 -> cat[0:64], y2, stats -> accS+64
    conv2_k<<<dim3(1, MBIG / 128), 128, CONV2_SMEM>>>(
        w2h, w2l, feat, W1, gM, g1, b1, y2, cat + 0, accS + 64, accQ + 64);

    // conv3: affine2 inline, x2 -> cat[64:128], y3, stats -> accS+128
    k3<<<dim3(1, MBIG / 128), 256, G256_SMEM>>>(
        w3h, w3l, y2, accS + 64, accQ + 64, g2, b2,
        y3, cat + 64, nullptr, accS + 128, accQ + 128, 64, 128);

    // conv4: affine3 inline, x3 -> cat[128:256], raw x4 -> cat[256:512], stats -> accS+256
    k4<<<dim3(2, MBIG / 128), 256, G256_SMEM>>>(
        w4h, w4l, y3, accS + 128, accQ + 128, g3, b3,
        nullptr, cat + 128, cat + 256, accS + 256, accQ + 256, 128, 256);

    // x4 fixup with inline affine4
    cat4fix_k<<<MSML, 256>>>(cat, accS + 256, accQ + 256, g4, b4);

    // conv5: cat already activated, y5, stats -> accS+512
    k5<<<dim3(4, MSML / 128), 256, G256_SMEM>>>(
        w5h, w5l, cat, nullptr, nullptr, nullptr, nullptr,
        y5, nullptr, nullptr, accS + 512, accQ + 512, 512, 512);

    // output transpose with inline affine5
    out_t<<<dim3(NPTS / 32, 16, BATCH), dim3(32, 8)>>>(
        y5, accS + 512, accQ + 512, g5, b5, out);
}

// round 8
// speedup vs baseline: 3.5218x; 1.0783x over previous
#include <cuda_runtime.h>
#include <cuda_bf16.h>
#include <cstdint>
#include <math.h>

// ---------------- problem constants ----------------
#define BATCH 8
#define NPTS  2048
#define KNN   32
#define EMB   512
#define MBIG  (BATCH*NPTS*KNN)   // 524288
#define MSML  (BATCH*NPTS)       // 16384
#define BN_EPS 1e-5f
#define INV_MBIG (1.f / (float)MBIG)
#define INV_MSML (1.f / (float)MSML)

#define IDX_OFF  (BATCH*EMB*NPTS)                 // 8388608
#define NBR_OFF  (IDX_OFF + BATCH*NPTS*KNN)       // 8912896

// ---------------- scratch ----------------
__device__ float g_feat[8u  * MBIG];     // [m][8] (6 used)
__device__ float g_y2 [64u  * MBIG];
__device__ float g_y3 [128u * MBIG];
__device__ float g_cat[512u * MSML];     // [pt][512]
__device__ float g_y5 [512u * MSML];
__device__ __nv_bfloat16 g_w2h[64*64],   g_w2l[64*64];
__device__ __nv_bfloat16 g_w3h[128*64],  g_w3l[128*64];
__device__ __nv_bfloat16 g_w4h[256*128], g_w4l[256*128];
__device__ __nv_bfloat16 g_w5h[512*512], g_w5l[512*512];
__device__ float g_accS[1024], g_accQ[1024];
__device__ float g_M[32];                // feat moments

// ---------------- helpers ----------------
__device__ __forceinline__ uint32_t smem_to_u32(const void* p) {
    uint32_t a;
    asm("{ .reg .u64 t; cvta.to.shared.u64 t, %1; cvt.u32.u64 %0, t; }" : "=r"(a) : "l"(p));
    return a;
}
__device__ __forceinline__ uint32_t packbf(float a, float b) {
    __nv_bfloat162 h = __floats2bfloat162_rn(a, b);
    return *(uint32_t*)&h;
}
__device__ __forceinline__ void ldsm4(uint32_t* r, uint32_t addr) {
    asm volatile("ldmatrix.sync.aligned.m8n8.x4.shared.b16 {%0,%1,%2,%3}, [%4];"
        : "=r"(r[0]), "=r"(r[1]), "=r"(r[2]), "=r"(r[3]) : "r"(addr));
}
__device__ __forceinline__ void mma16816(float* c, const uint32_t* a, uint32_t b0, uint32_t b1) {
    asm volatile("mma.sync.aligned.m16n8k16.row.col.f32.bf16.bf16.f32 "
        "{%0,%1,%2,%3}, {%4,%5,%6,%7}, {%8,%9}, {%0,%1,%2,%3};"
        : "+f"(c[0]), "+f"(c[1]), "+f"(c[2]), "+f"(c[3])
        : "r"(a[0]), "r"(a[1]), "r"(a[2]), "r"(a[3]), "r"(b0), "r"(b1));
}
#define CP_COMMIT() asm volatile("cp.async.commit_group;" ::: "memory")
#define CP_WAIT(n)  asm volatile("cp.async.wait_group %0;" :: "n"(n) : "memory")

__device__ __forceinline__ void bn_affine(float as, float aq, float g, float bta,
                                          float invM, float& sc, float& sh) {
    float mu   = as * invM;
    float var  = aq * invM - mu * mu;
    float rstd = 1.f / sqrtf(var + BN_EPS);
    float s    = g * rstd;
    sc = s;
    sh = bta - mu * s;
}

// ---------------- zero accumulators ----------------
__global__ void zero_acc_k(float* s, float* q, float* m) {
    int i = blockIdx.x * blockDim.x + threadIdx.x;
    if (i < 1024) { s[i] = 0.f; q[i] = 0.f; }
    if (i < 32) m[i] = 0.f;
}

// ---------------- weight convert fp32 -> split bf16 hi/lo ----------------
__global__ void wconv_k(const float* W2, const float* W3, const float* W4, const float* W5,
                        __nv_bfloat16* w2h, __nv_bfloat16* w2l,
                        __nv_bfloat16* w3h, __nv_bfloat16* w3l,
                        __nv_bfloat16* w4h, __nv_bfloat16* w4l,
                        __nv_bfloat16* w5h, __nv_bfloat16* w5l)
{
    int i = blockIdx.x * blockDim.x + threadIdx.x;
    const float* src; __nv_bfloat16 *dh, *dl; int off;
    if      (i < 4096)   { src = W2; dh = w2h; dl = w2l; off = 0; }
    else if (i < 12288)  { src = W3; dh = w3h; dl = w3l; off = 4096; }
    else if (i < 45056)  { src = W4; dh = w4h; dl = w4l; off = 12288; }
    else if (i < 307200) { src = W5; dh = w5h; dl = w5l; off = 45056; }
    else return;
    int j = i - off;
    float w = src[j];
    __nv_bfloat16 h = __float2bfloat16(w);
    dh[j] = h;
    dl[j] = __float2bfloat16(w - __bfloat162float(h));
}

// ---------------- kNN: warp-per-point, chunked argmax ----------------
#define KNN_SMEM ((8192 + 8 * 2112) * 4)
__global__ __launch_bounds__(256)
void knn_kernel(const float* __restrict__ x,
                float* __restrict__ outIdx,
                float* __restrict__ outNbr,
                float* __restrict__ feat)
{
    extern __shared__ float km[];
    float* px  = km;
    float* py  = km + 2048;
    float* pz  = km + 4096;
    float* pxx = km + 6144;
    float* sdall = km + 8192;

    int tid = threadIdx.x, wid = tid >> 5, lane = tid & 31;
    int b = blockIdx.x >> 8;
    int i = ((blockIdx.x & 255) << 3) + wid;
    const float* xb = x + (size_t)b * 3 * NPTS;

    for (int j = tid; j < NPTS; j += 256) {
        float a0 = xb[j], a1 = xb[NPTS + j], a2 = xb[2 * NPTS + j];
        px[j] = a0; py[j] = a1; pz[j] = a2;
        pxx[j] = a0 * a0 + a1 * a1 + a2 * a2;
    }
    __syncthreads();

    float* sd = sdall + wid * 2112;
    float q0 = px[i], q1 = py[i], q2 = pz[i], qxx = pxx[i];

    #pragma unroll 4
    for (int c = 0; c < 64; c++) {
        int j = c * 32 + lane;
        float dot   = q0 * px[j] + q1 * py[j] + q2 * pz[j];
        float inner = -2.f * dot;
        float t     = (-qxx) - inner;
        sd[c * 33 + lane] = t - pxx[j];
    }
    __syncwarp();

    float cm0 = -3.4e38f, cm1 = -3.4e38f;
    #pragma unroll 4
    for (int e = 0; e < 32; e++) {
        cm0 = fmaxf(cm0, sd[lane * 33 + e]);
        cm1 = fmaxf(cm1, sd[(lane + 32) * 33 + e]);
    }

    int jsel = 0;
    for (int k = 0; k < KNN; k++) {
        float v; int c;
        if (cm0 >= cm1) { v = cm0; c = lane; } else { v = cm1; c = lane + 32; }
        #pragma unroll
        for (int off = 16; off; off >>= 1) {
            float ov = __shfl_down_sync(0xffffffffu, v, off);
            int   oc = __shfl_down_sync(0xffffffffu, c, off);
            if (ov > v || (ov == v && oc < c)) { v = ov; c = oc; }
        }
        c = __shfl_sync(0xffffffffu, c, 0);
        float dv = sd[c * 33 + lane];
        float mv = dv; int ml = lane;
        #pragma unroll
        for (int off = 16; off; off >>= 1) {
            float omv = __shfl_down_sync(0xffffffffu, mv, off);
            int   oml = __shfl_down_sync(0xffffffffu, ml, off);
            if (omv > mv || (omv == mv && oml < ml)) { mv = omv; ml = oml; }
        }
        ml = __shfl_sync(0xffffffffu, ml, 0);
        int j = c * 32 + ml;
        if (lane == k) jsel = j;
        if (lane == ml) { dv = -3.4e38f; sd[c * 33 + ml] = dv; }
        float nm = dv;
        #pragma unroll
        for (int off = 16; off; off >>= 1)
            nm = fmaxf(nm, __shfl_xor_sync(0xffffffffu, nm, off));
        if (c < 32) { if (lane == c) cm0 = nm; }
        else        { if (lane == c - 32) cm1 = nm; }
        __syncwarp();
    }

    int bn = b * NPTS + i;
    int m  = bn * KNN + lane;
    int j  = jsel;
    outIdx[m] = (float)(j + b * NPTS);
    float v0 = px[j], v1 = py[j], v2 = pz[j];
    size_t ofs = (size_t)m * 3;
    outNbr[ofs + 0] = v0; outNbr[ofs + 1] = v1; outNbr[ofs + 2] = v2;
    float* fp = feat + (size_t)m * 8;
    fp[0] = v0; fp[1] = v1; fp[2] = v2;
    fp[3] = q0; fp[4] = q1; fp[5] = q2;
}

// ---------------- feat moments ----------------
__global__ __launch_bounds__(256)
void fstats_k(const float* __restrict__ feat, float* __restrict__ gM)
{
    __shared__ float red[8][27];
    int tid = threadIdx.x, wid = tid >> 5, lane = tid & 31;
    float a[27];
    #pragma unroll
    for (int t = 0; t < 27; t++) a[t] = 0.f;

    int base = blockIdx.x * 1024 + tid;
    #pragma unroll
    for (int it = 0; it < 4; it++) {
        const float4* fp = (const float4*)(feat + (size_t)(base + it * 256) * 8);
        float4 fa = fp[0], fb = fp[1];
        float f[6] = { fa.x, fa.y, fa.z, fa.w, fb.x, fb.y };
        #pragma unroll
        for (int t = 0; t < 6; t++) a[t] += f[t];
        int idx = 6;
        #pragma unroll
        for (int t = 0; t < 6; t++)
            #pragma unroll
            for (int u = t; u < 6; u++) a[idx++] += f[t] * f[u];
    }
    #pragma unroll
    for (int off = 16; off; off >>= 1)
        #pragma unroll
        for (int t = 0; t < 27; t++)
            a[t] += __shfl_down_sync(0xffffffffu, a[t], off);
    if (lane == 0)
        #pragma unroll
        for (int t = 0; t < 27; t++) red[wid][t] = a[t];
    __syncthreads();
    if (tid < 27) {
        float s = 0.f;
        #pragma unroll
        for (int w = 0; w < 8; w++) s += red[w][tid];
        atomicAdd(&gM[tid], s);
    }
}

// ---------------- conv2: 128-thread, inline conv1 + affine1, N=64 ------------
#define CONV2_SMEM 52224
__global__ __launch_bounds__(128)
void conv2_k(const __nv_bfloat16* __restrict__ Wh, const __nv_bfloat16* __restrict__ Wl,
             const float* __restrict__ feat, const float* __restrict__ W1,
             const float* __restrict__ gM,
             const float* __restrict__ g1, const float* __restrict__ b1,
             float* __restrict__ Y, float* __restrict__ catXin,
             float* __restrict__ accS, float* __restrict__ accQ)
{
    extern __shared__ __align__(16) uint8_t smem[];
    uint8_t* sAh = smem;
    uint8_t* sAl = smem + 16384;
    uint8_t* sBh = smem + 32768;
    uint8_t* sBl = smem + 40960;
    int*   xmax = (int*)(smem + 49152);
    float* w1s  = (float*)(smem + 50176);
    float* scs  = (float*)(smem + 51712);
    float* shs  = scs + 64;
    float* sS   = (float*)smem;
    float* sQ   = sS + 256;

    const int tid  = threadIdx.x;
    const int wid  = tid >> 5;
    const int lane = tid & 31;
    const int mBase = blockIdx.y * 128;

    const uint32_t sAh_u = smem_to_u32(sAh);
    const uint32_t sAl_u = smem_to_u32(sAl);
    const uint32_t sBh_u = smem_to_u32(sBh);
    const uint32_t sBl_u = smem_to_u32(sBl);

    for (int t = tid; t < 384; t += 128) w1s[t] = W1[t];
    for (int t = tid; t < 256; t += 128) xmax[t] = 0;
    if (tid < 64) {
        int o = tid;
        float w[6];
        #pragma unroll
        for (int t = 0; t < 6; t++) w[t] = W1[o * 6 + t];
        float s = 0.f;
        #pragma unroll
        for (int t = 0; t < 6; t++) s += w[t] * gM[t];
        float mu = s * INV_MBIG;
        float qq = 0.f; int idx = 6;
        #pragma unroll
        for (int t = 0; t < 6; t++)
            #pragma unroll
            for (int u = t; u < 6; u++) {
                float term = w[t] * w[u] * gM[idx++];
                qq += (t == u) ? term : 2.f * term;
            }
        float var  = qq * INV_MBIG - mu * mu;
        float rstd = 1.f / sqrtf(var + BN_EPS);
        float scale = g1[o] * rstd;
        scs[o] = scale;
        shs[o] = b1[o] - mu * scale;
    }
    __syncthreads();

    float acc[2][8][4];
    #pragma unroll
    for (int mt = 0; mt < 2; mt++)
        #pragma unroll
        for (int nt = 0; nt < 8; nt++)
            #pragma unroll
            for (int t = 0; t < 4; t++) acc[mt][nt][t] = 0.f;

    const uint4* Whv = (const uint4*)Wh;
    const uint4* Wlv = (const uint4*)Wl;

    {
        float4 vmax = make_float4(0.f, 0.f, 0.f, 0.f);
        #pragma unroll
        for (int j = 0; j < 16; j++) {
            int linear = tid + j * 128;
            int row = linear >> 4, ch = linear & 15;
            const float4* fr = (const float4*)(feat + (size_t)(mBase + row) * 8);
            float4 fa = fr[0], fb = fr[1];
            float f0 = fa.x, f1 = fa.y, f2 = fa.z, f3 = fa.w, f4 = fb.x, f5 = fb.y;
            float4 v;
            #pragma unroll
            for (int cc = 0; cc < 4; cc++) {
                const float* w = &w1s[(ch * 4 + cc) * 6];
                (&v.x)[cc] = w[0]*f0 + w[1]*f1 + w[2]*f2 + w[3]*f3 + w[4]*f4 + w[5]*f5;
            }
            int cb = ch * 4;
            float4 s4 = *(const float4*)(scs + cb);
            float4 t4 = *(const float4*)(shs + cb);
            v.x = fmaxf(fmaf(v.x, s4.x, t4.x), 0.f);
            v.y = fmaxf(fmaf(v.y, s4.y, t4.y), 0.f);
            v.z = fmaxf(fmaf(v.z, s4.z, t4.z), 0.f);
            v.w = fmaxf(fmaf(v.w, s4.w, t4.w), 0.f);
            vmax.x = fmaxf(vmax.x, v.x); vmax.y = fmaxf(vmax.y, v.y);
            vmax.z = fmaxf(vmax.z, v.z); vmax.w = fmaxf(vmax.w, v.w);
            if ((j & 3) == 3) {
                int base = (j >> 2) * 64 + (tid & 15) * 4;
                atomicMax(&xmax[base + 0], __float_as_int(vmax.x));
                atomicMax(&xmax[base + 1], __float_as_int(vmax.y));
                atomicMax(&xmax[base + 2], __float_as_int(vmax.z));
                atomicMax(&xmax[base + 3], __float_as_int(vmax.w));
                vmax = make_float4(0.f, 0.f, 0.f, 0.f);
            }
            float hx = __bfloat162float(__float2bfloat16(v.x));
            float hy = __bfloat162float(__float2bfloat16(v.y));
            float hz = __bfloat162float(__float2bfloat16(v.z));
            float hw = __bfloat162float(__float2bfloat16(v.w));
            int c = ch >> 1, sub = ch & 1;
            int addr = row * 128 + ((c ^ (row & 7)) << 4) + sub * 8;
            *(uint2*)(sAh + addr) = make_uint2(packbf(v.x, v.y), packbf(v.z, v.w));
            *(uint2*)(sAl + addr) = make_uint2(packbf(v.x - hx, v.y - hy), packbf(v.z - hz, v.w - hw));
        }
    }
    #pragma unroll
    for (int j = 0; j < 4; j++) {
        int linear = tid + j * 128;
        int row = linear >> 3, ch = linear & 7;
        size_t gofs = (size_t)row * 8 + ch;
        int addr = row * 128 + ((ch ^ (row & 7)) << 4);
        *(uint4*)(sBh + addr) = Whv[gofs];
        *(uint4*)(sBl + addr) = Wlv[gofs];
    }
    __syncthreads();

    #pragma unroll
    for (int t = tid; t < 256; t += 128) {
        int p = t >> 6, chl = t & 63;
        catXin[(size_t)(blockIdx.y * 4 + p) * 512 + chl] = __int_as_float(xmax[t]);
    }

    #pragma unroll
    for (int ks = 0; ks < 4; ks++) {
        uint32_t ah[2][4], al[2][4];
        int chunk = 2 * ks + (lane >> 4);
        #pragma unroll
        for (int mt = 0; mt < 2; mt++) {
            int r = wid * 32 + mt * 16 + (lane & 15);
            int off = r * 128 + ((chunk ^ (r & 7)) << 4);
            ldsm4(ah[mt], sAh_u + off);
            ldsm4(al[mt], sAl_u + off);
        }
        #pragma unroll
        for (int ntp = 0; ntp < 4; ntp++) {
            uint32_t bh[4], bl[4];
            int r = ntp * 16 + (lane & 15);
            int off = r * 128 + ((chunk ^ (r & 7)) << 4);
            ldsm4(bh, sBh_u + off);
            ldsm4(bl, sBl_u + off);
            #pragma unroll
            for (int mt = 0; mt < 2; mt++) {
                #pragma unroll
                for (int nb = 0; nb < 2; nb++) {
                    float* c = acc[mt][2 * ntp + nb];
                    mma16816(c, ah[mt], bh[nb], bh[nb + 2]);
                    mma16816(c, ah[mt], bl[nb], bl[nb + 2]);
                    mma16816(c, al[mt], bh[nb], bh[nb + 2]);
                }
            }
        }
    }
    __syncthreads();

    const int q4 = lane & 3;
    #pragma unroll
    for (int nt = 0; nt < 8; nt++) {
        int col = nt * 8 + q4 * 2;
        float se = 0.f, so = 0.f, qe = 0.f, qo = 0.f;
        #pragma unroll
        for (int mt = 0; mt < 2; mt++) {
            float* c = acc[mt][nt];
            int r0 = mBase + wid * 32 + mt * 16 + (lane >> 2);
            *(float2*)(Y + (size_t)r0 * 64 + col)       = make_float2(c[0], c[1]);
            *(float2*)(Y + (size_t)(r0 + 8) * 64 + col) = make_float2(c[2], c[3]);
            se += c[0] + c[2];  so += c[1] + c[3];
            qe += c[0]*c[0] + c[2]*c[2];
            qo += c[1]*c[1] + c[3]*c[3];
        }
        #pragma unroll
        for (int off = 16; off >= 4; off >>= 1) {
            se += __shfl_down_sync(0xffffffffu, se, off);
            so += __shfl_down_sync(0xffffffffu, so, off);
            qe += __shfl_down_sync(0xffffffffu, qe, off);
            qo += __shfl_down_sync(0xffffffffu, qo, off);
        }
        if (lane < 4) {
            int chl = nt * 8 + lane * 2;
            sS[wid * 64 + chl]     = se;
            sS[wid * 64 + chl + 1] = so;
            sQ[wid * 64 + chl]     = qe;
            sQ[wid * 64 + chl + 1] = qo;
        }
    }
    __syncthreads();
    if (tid < 64) {
        float s = 0.f, q = 0.f;
        #pragma unroll
        for (int w = 0; w < 4; w++) { s += sS[w * 64 + tid]; q += sQ[w * 64 + tid]; }
        atomicAdd(&accS[tid], s);
        atomicAdd(&accQ[tid], q);
    }
}

// ---------------- 256-thread 128x128 bf16x3 GEMM (conv3) ---------------------
#define G256_SB    32768
#define G256_AFF   98304
#define G256_XMAX  102400
#define G256_SMEM  103424
template <bool HAS_ACT, bool IN_MAX, bool OUT_MAX, bool WRITE_Y>
__global__ __launch_bounds__(256)
void mma_gemm256(const __nv_bfloat16* __restrict__ Wh, const __nv_bfloat16* __restrict__ Wl,
                 const float* __restrict__ X,
                 const float* __restrict__ accSin, const float* __restrict__ accQin,
                 const float* __restrict__ gIn, const float* __restrict__ bIn,
                 float* __restrict__ Y, float* __restrict__ catXin, float* __restrict__ catXout,
                 float* __restrict__ accS, float* __restrict__ accQ,
                 int Cin, int Cout)
{
    extern __shared__ __align__(16) uint8_t smem[];
    uint8_t* sAh = smem;
    uint8_t* sAl = smem + 16384;
    float* scs  = (float*)(smem + G256_AFF);
    float* shs  = scs + 512;
    int*   xmax = (int*)(smem + G256_XMAX);
    float* sS   = (float*)smem;
    float* sQ   = sS + 512;

    const int tid  = threadIdx.x;
    const int wid  = tid >> 5;
    const int lane = tid & 31;
    const int m_warp = wid & 3;
    const int n_warp = wid >> 2;
    const int mBase = blockIdx.y * 128;
    const int oBase = blockIdx.x * 128;

    const uint32_t smem_u = smem_to_u32(smem);
    const uint32_t sAh_u = smem_u;
    const uint32_t sAl_u = smem_u + 16384;

    const float4* Xv = (const float4*)X;
    const uint4* Whv = (const uint4*)Wh;
    const uint4* Wlv = (const uint4*)Wl;
    const int cinV = Cin >> 2;
    const int cinW = Cin >> 3;
    const int nkt  = Cin >> 6;

    if (HAS_ACT) {
        for (int ch = tid; ch < Cin; ch += 256)
            bn_affine(accSin[ch], accQin[ch], gIn[ch], bIn[ch], INV_MBIG, scs[ch], shs[ch]);
    }
    if (IN_MAX) { if (tid < 256) xmax[tid] = 0; }

    {
        uint32_t sB0 = smem_u + G256_SB;
        #pragma unroll
        for (int j = 0; j < 4; j++) {
            int linear = tid + j * 256;
            int row = linear >> 3, ch = linear & 7;
            uint32_t addr = sB0 + row * 128 + ((ch ^ (row & 7)) << 4);
            const uint4* sh_ = &Whv[(size_t)(oBase + row) * cinW + ch];
            const uint4* sl_ = &Wlv[(size_t)(oBase + row) * cinW + ch];
            asm volatile("cp.async.cg.shared.global [%0], [%1], 16;" :: "r"(addr), "l"(sh_) : "memory");
            asm volatile("cp.async.cg.shared.global [%0], [%1], 16;" :: "r"(addr + 16384), "l"(sl_) : "memory");
        }
        CP_COMMIT();
    }
    float4 areg[8];
    #pragma unroll
    for (int j = 0; j < 8; j++) {
        int linear = tid + j * 256;
        int row = linear >> 4, ch = linear & 15;
        areg[j] = Xv[(size_t)(mBase + row) * cinV + ch];
    }
    __syncthreads();

    float acc[2][8][4];
    #pragma unroll
    for (int mt = 0; mt < 2; mt++)
        #pragma unroll
        for (int nt = 0; nt < 8; nt++)
            #pragma unroll
            for (int t = 0; t < 4; t++) acc[mt][nt][t] = 0.f;

    for (int kt = 0; kt < nkt; kt++) {
        if (kt + 1 < nkt) {
            uint32_t sBn = smem_u + G256_SB + ((kt + 1) & 1) * 32768;
            #pragma unroll
            for (int j = 0; j < 4; j++) {
                int linear = tid + j * 256;
                int row = linear >> 3, ch = linear & 7;
                uint32_t addr = sBn + row * 128 + ((ch ^ (row & 7)) << 4);
                const uint4* sh_ = &Whv[(size_t)(oBase + row) * cinW + (kt + 1) * 8 + ch];
                const uint4* sl_ = &Wlv[(size_t)(oBase + row) * cinW + (kt + 1) * 8 + ch];
                asm volatile("cp.async.cg.shared.global [%0], [%1], 16;" :: "r"(addr), "l"(sh_) : "memory");
                asm volatile("cp.async.cg.shared.global [%0], [%1], 16;" :: "r"(addr + 16384), "l"(sl_) : "memory");
            }
            CP_COMMIT();
        }

        {
            float4 vmax = make_float4(0.f, 0.f, 0.f, 0.f);
            #pragma unroll
            for (int j = 0; j < 8; j++) {
                int linear = tid + j * 256;
                int row = linear >> 4, ch = linear & 15;
                float4 v = areg[j];
                if (HAS_ACT) {
                    int cb = kt * 64 + ch * 4;
                    float4 s4 = *(const float4*)(scs + cb);
                    float4 t4 = *(const float4*)(shs + cb);
                    v.x = fmaxf(fmaf(v.x, s4.x, t4.x), 0.f);
                    v.y = fmaxf(fmaf(v.y, s4.y, t4.y), 0.f);
                    v.z = fmaxf(fmaf(v.z, s4.z, t4.z), 0.f);
                    v.w = fmaxf(fmaf(v.w, s4.w, t4.w), 0.f);
                }
                if (IN_MAX) {
                    vmax.x = fmaxf(vmax.x, v.x); vmax.y = fmaxf(vmax.y, v.y);
                    vmax.z = fmaxf(vmax.z, v.z); vmax.w = fmaxf(vmax.w, v.w);
                    if (j & 1) {
                        int pt = j >> 1;
                        int base = pt * 64 + ch * 4;
                        atomicMax(&xmax[base + 0], __float_as_int(vmax.x));
                        atomicMax(&xmax[base + 1], __float_as_int(vmax.y));
                        atomicMax(&xmax[base + 2], __float_as_int(vmax.z));
                        atomicMax(&xmax[base + 3], __float_as_int(vmax.w));
                        vmax = make_float4(0.f, 0.f, 0.f, 0.f);
                    }
                }
                float hx = __bfloat162float(__float2bfloat16(v.x));
                float hy = __bfloat162float(__float2bfloat16(v.y));
                float hz = __bfloat162float(__float2bfloat16(v.z));
                float hw = __bfloat162float(__float2bfloat16(v.w));
                int c = ch >> 1, sub = ch & 1;
                int addr = row * 128 + ((c ^ (row & 7)) << 4) + sub * 8;
                *(uint2*)(sAh + addr) = make_uint2(packbf(v.x, v.y), packbf(v.z, v.w));
                *(uint2*)(sAl + addr) = make_uint2(packbf(v.x - hx, v.y - hy), packbf(v.z - hz, v.w - hw));
            }
        }
        if (kt + 1 < nkt) { CP_WAIT(1); } else { CP_WAIT(0); }
        __syncthreads();

        if (IN_MAX && tid < 256) {
            if (blockIdx.x == 0) {
                int p = tid >> 6, chl = tid & 63;
                catXin[(size_t)(blockIdx.y * 4 + p) * 512 + kt * 64 + chl] =
                    __int_as_float(xmax[tid]);
            }
            if (kt + 1 < nkt) xmax[tid] = 0;
        }

        if (kt + 1 < nkt) {
            #pragma unroll
            for (int j = 0; j < 8; j++) {
                int linear = tid + j * 256;
                int row = linear >> 4, ch = linear & 15;
                areg[j] = Xv[(size_t)(mBase + row) * cinV + (kt + 1) * 16 + ch];
            }
        }

        {
            const uint32_t sBh_u = smem_u + G256_SB + (kt & 1) * 32768;
            const uint32_t sBl_u = sBh_u + 16384;
            #pragma unroll
            for (int ks = 0; ks < 4; ks++) {
                uint32_t ah[2][4], al[2][4];
                int chunk = 2 * ks + (lane >> 4);
                #pragma unroll
                for (int mt = 0; mt < 2; mt++) {
                    int r = m_warp * 32 + mt * 16 + (lane & 15);
                    int off = r * 128 + ((chunk ^ (r & 7)) << 4);
                    ldsm4(ah[mt], sAh_u + off);
                    ldsm4(al[mt], sAl_u + off);
                }
                #pragma unroll
                for (int ntp = 0; ntp < 4; ntp++) {
                    uint32_t bh[4], bl[4];
                    int r = n_warp * 64 + ntp * 16 + (lane & 15);
                    int off = r * 128 + ((chunk ^ (r & 7)) << 4);
                    ldsm4(bh, sBh_u + off);
                    ldsm4(bl, sBl_u + off);
                    #pragma unroll
                    for (int mt = 0; mt < 2; mt++) {
                        #pragma unroll
                        for (int nb = 0; nb < 2; nb++) {
                            float* c = acc[mt][2 * ntp + nb];
                            mma16816(c, ah[mt], bh[nb], bh[nb + 2]);
                            mma16816(c, ah[mt], bl[nb], bl[nb + 2]);
                            mma16816(c, al[mt], bh[nb], bh[nb + 2]);
                        }
                    }
                }
            }
        }
        __syncthreads();
    }

    const int q4 = lane & 3;
    #pragma unroll
    for (int nt = 0; nt < 8; nt++) {
        int col = oBase + n_warp * 64 + nt * 8 + q4 * 2;
        float se = 0.f, so = 0.f, qe = 0.f, qo = 0.f;
        #pragma unroll
        for (int mt = 0; mt < 2; mt++) {
            float* c = acc[mt][nt];
            if (WRITE_Y) {
                int r0 = mBase + m_warp * 32 + mt * 16 + (lane >> 2);
                *(float2*)(Y + (size_t)r0 * Cout + col)       = make_float2(c[0], c[1]);
                *(float2*)(Y + (size_t)(r0 + 8) * Cout + col) = make_float2(c[2], c[3]);
            }
            se += c[0] + c[2];  so += c[1] + c[3];
            qe += c[0]*c[0] + c[2]*c[2];
            qo += c[1]*c[1] + c[3]*c[3];
        }
        if (OUT_MAX) {
            float m0 = fmaxf(fmaxf(acc[0][nt][0], acc[0][nt][2]),
                             fmaxf(acc[1][nt][0], acc[1][nt][2]));
            float m1 = fmaxf(fmaxf(acc[0][nt][1], acc[0][nt][3]),
                             fmaxf(acc[1][nt][1], acc[1][nt][3]));
            #pragma unroll
            for (int off = 16; off >= 4; off >>= 1) {
                m0 = fmaxf(m0, __shfl_xor_sync(0xffffffffu, m0, off));
                m1 = fmaxf(m1, __shfl_xor_sync(0xffffffffu, m1, off));
            }
            if (lane < 4) {
                int pt = blockIdx.y * 4 + m_warp;
                int cc = oBase + n_warp * 64 + nt * 8 + lane * 2;
                catXout[(size_t)pt * 512 + cc]     = m0;
                catXout[(size_t)pt * 512 + cc + 1] = m1;
            }
        }
        #pragma unroll
        for (int off = 16; off >= 4; off >>= 1) {
            se += __shfl_down_sync(0xffffffffu, se, off);
            so += __shfl_down_sync(0xffffffffu, so, off);
            qe += __shfl_down_sync(0xffffffffu, qe, off);
            qo += __shfl_down_sync(0xffffffffu, qo, off);
        }
        if (lane < 4) {
            int chl = n_warp * 64 + nt * 8 + lane * 2;
            sS[m_warp * 128 + chl]     = se;
            sS[m_warp * 128 + chl + 1] = so;
            sQ[m_warp * 128 + chl]     = qe;
            sQ[m_warp * 128 + chl + 1] = qo;
        }
    }
    __syncthreads();
    if (tid < 128) {
        float s = 0.f, q = 0.f;
        #pragma unroll
        for (int w = 0; w < 4; w++) { s += sS[w * 128 + tid]; q += sQ[w * 128 + tid]; }
        atomicAdd(&accS[oBase + tid], s);
        atomicAdd(&accQ[oBase + tid], q);
    }
}

// ---------------- 512-thread 128x256 bf16x3 GEMM (conv4 / conv5) -------------
// smem: sAh 0 (16K), sAl 16384, B 32768: 2 stages x 64KB (hi 32K + lo 32K),
//       aff 163840 (scs512+shs512 = 4KB), xmax 167936 (1KB). Total 168960.
#define G512_SB    32768
#define G512_AFF   163840
#define G512_XMAX  167936
#define G512_SMEM  168960
template <bool HAS_ACT, bool MIXED_ACT, bool IN_MAX, bool OUT_MAX, bool WRITE_Y>
__global__ __launch_bounds__(512, 1)
void mma_gemm512(const __nv_bfloat16* __restrict__ Wh, const __nv_bfloat16* __restrict__ Wl,
                 const float* __restrict__ X,
                 const float* __restrict__ accSin, const float* __restrict__ accQin,
                 const float* __restrict__ gIn, const float* __restrict__ bIn,
                 float* __restrict__ Y, float* __restrict__ catXin, float* __restrict__ catXout,
                 float* __restrict__ accS, float* __restrict__ accQ,
                 int Cin, int Cout)
{
    extern __shared__ __align__(16) uint8_t smem[];
    uint8_t* sAh = smem;
    uint8_t* sAl = smem + 16384;
    float* scs  = (float*)(smem + G512_AFF);
    float* shs  = scs + 512;
    int*   xmax = (int*)(smem + G512_XMAX);
    float* sS   = (float*)smem;          // epilogue alias: 4 x 256
    float* sQ   = sS + 1024;

    const int tid  = threadIdx.x;
    const int wid  = tid >> 5;
    const int lane = tid & 31;
    const int m_warp = wid & 3;          // 4 x 32 rows
    const int n_warp = wid >> 2;         // 4 x 64 cols
    const int mBase = blockIdx.y * 128;
    const int oBase = blockIdx.x * 256;

    const uint32_t smem_u = smem_to_u32(smem);
    const uint32_t sAh_u = smem_u;
    const uint32_t sAl_u = smem_u + 16384;

    const float4* Xv = (const float4*)X;
    const uint4* Whv = (const uint4*)Wh;
    const uint4* Wlv = (const uint4*)Wl;
    const int cinV = Cin >> 2;
    const int cinW = Cin >> 3;
    const int nkt  = Cin >> 6;

    if (HAS_ACT) {
        for (int ch = tid; ch < Cin; ch += 512)
            bn_affine(accSin[ch], accQin[ch], gIn[ch], bIn[ch], INV_MBIG, scs[ch], shs[ch]);
    }
    if (MIXED_ACT) {
        for (int ch = tid; ch < 512; ch += 512) {
            if (ch < 256) { scs[ch] = 1.f; shs[ch] = 0.f; }
            else bn_affine(accSin[ch - 256], accQin[ch - 256], gIn[ch - 256], bIn[ch - 256],
                           INV_MBIG, scs[ch], shs[ch]);
        }
    }
    if (IN_MAX) { if (tid < 256) xmax[tid] = 0; }

    // B(0): 256 rows x 8 uint4 per plane, 512 threads -> 4 iters x (hi+lo)
    {
        uint32_t sB0 = smem_u + G512_SB;
        #pragma unroll
        for (int j = 0; j < 4; j++) {
            int linear = tid + j * 512;
            int row = linear >> 3, ch = linear & 7;
            uint32_t addr = sB0 + row * 128 + ((ch ^ (row & 7)) << 4);
            const uint4* sh_ = &Whv[(size_t)(oBase + row) * cinW + ch];
            const uint4* sl_ = &Wlv[(size_t)(oBase + row) * cinW + ch];
            asm volatile("cp.async.cg.shared.global [%0], [%1], 16;" :: "r"(addr), "l"(sh_) : "memory");
            asm volatile("cp.async.cg.shared.global [%0], [%1], 16;" :: "r"(addr + 32768), "l"(sl_) : "memory");
        }
        CP_COMMIT();
    }
    // A(0) into registers: 128x64 fp32 = 2048 float4 / 512 thr = 4
    float4 areg[4];
    #pragma unroll
    for (int j = 0; j < 4; j++) {
        int linear = tid + j * 512;
        int row = linear >> 4, ch = linear & 15;
        areg[j] = Xv[(size_t)(mBase + row) * cinV + ch];
    }
    __syncthreads();

    float acc[2][8][4];
    #pragma unroll
    for (int mt = 0; mt < 2; mt++)
        #pragma unroll
        for (int nt = 0; nt < 8; nt++)
            #pragma unroll
            for (int t = 0; t < 4; t++) acc[mt][nt][t] = 0.f;

    for (int kt = 0; kt < nkt; kt++) {
        if (kt + 1 < nkt) {
            uint32_t sBn = smem_u + G512_SB + ((kt + 1) & 1) * 65536;
            #pragma unroll
            for (int j = 0; j < 4; j++) {
                int linear = tid + j * 512;
                int row = linear >> 3, ch = linear & 7;
                uint32_t addr = sBn + row * 128 + ((ch ^ (row & 7)) << 4);
                const uint4* sh_ = &Whv[(size_t)(oBase + row) * cinW + (kt + 1) * 8 + ch];
                const uint4* sl_ = &Wlv[(size_t)(oBase + row) * cinW + (kt + 1) * 8 + ch];
                asm volatile("cp.async.cg.shared.global [%0], [%1], 16;" :: "r"(addr), "l"(sh_) : "memory");
                asm volatile("cp.async.cg.shared.global [%0], [%1], 16;" :: "r"(addr + 32768), "l"(sl_) : "memory");
            }
            CP_COMMIT();
        }

        // convert A(kt): each thread handles 4 rows (row = tid>>4 + j*32)
        {
            #pragma unroll
            for (int j = 0; j < 4; j++) {
                int linear = tid + j * 512;
                int row = linear >> 4, ch = linear & 15;
                float4 v = areg[j];
                if (HAS_ACT || MIXED_ACT) {
                    int cb = kt * 64 + ch * 4;
                    float4 s4 = *(const float4*)(scs + cb);
                    float4 t4 = *(const float4*)(shs + cb);
                    v.x = fmaxf(fmaf(v.x, s4.x, t4.x), 0.f);
                    v.y = fmaxf(fmaf(v.y, s4.y, t4.y), 0.f);
                    v.z = fmaxf(fmaf(v.z, s4.z, t4.z), 0.f);
                    v.w = fmaxf(fmaf(v.w, s4.w, t4.w), 0.f);
                }
                if (IN_MAX) {
                    int pt = row >> 5;
                    int base = pt * 64 + ch * 4;
                    atomicMax(&xmax[base + 0], __float_as_int(v.x));
                    atomicMax(&xmax[base + 1], __float_as_int(v.y));
                    atomicMax(&xmax[base + 2], __float_as_int(v.z));
                    atomicMax(&xmax[base + 3], __float_as_int(v.w));
                }
                float hx = __bfloat162float(__float2bfloat16(v.x));
                float hy = __bfloat162float(__float2bfloat16(v.y));
                float hz = __bfloat162float(__float2bfloat16(v.z));
                float hw = __bfloat162float(__float2bfloat16(v.w));
                int c = ch >> 1, sub = ch & 1;
                int addr = row * 128 + ((c ^ (row & 7)) << 4) + sub * 8;
                *(uint2*)(sAh + addr) = make_uint2(packbf(v.x, v.y), packbf(v.z, v.w));
                *(uint2*)(sAl + addr) = make_uint2(packbf(v.x - hx, v.y - hy), packbf(v.z - hz, v.w - hw));
            }
        }
        if (kt + 1 < nkt) { CP_WAIT(1); } else { CP_WAIT(0); }
        __syncthreads();

        if (IN_MAX && tid < 256) {
            if (blockIdx.x == 0) {
                int p = tid >> 6, chl = tid & 63;
                catXin[(size_t)(blockIdx.y * 4 + p) * 512 + kt * 64 + chl] =
                    __int_as_float(xmax[tid]);
            }
            if (kt + 1 < nkt) xmax[tid] = 0;
        }

        if (kt + 1 < nkt) {
            #pragma unroll
            for (int j = 0; j < 4; j++) {
                int linear = tid + j * 512;
                int row = linear >> 4, ch = linear & 15;
                areg[j] = Xv[(size_t)(mBase + row) * cinV + (kt + 1) * 16 + ch];
            }
        }

        {
            const uint32_t sBh_u = smem_u + G512_SB + (kt & 1) * 65536;
            const uint32_t sBl_u = sBh_u + 32768;
            #pragma unroll
            for (int ks = 0; ks < 4; ks++) {
                uint32_t ah[2][4], al[2][4];
                int chunk = 2 * ks + (lane >> 4);
                #pragma unroll
                for (int mt = 0; mt < 2; mt++) {
                    int r = m_warp * 32 + mt * 16 + (lane & 15);
                    int off = r * 128 + ((chunk ^ (r & 7)) << 4);
                    ldsm4(ah[mt], sAh_u + off);
                    ldsm4(al[mt], sAl_u + off);
                }
                #pragma unroll
                for (int ntp = 0; ntp < 4; ntp++) {
                    uint32_t bh[4], bl[4];
                    int r = n_warp * 64 + ntp * 16 + (lane & 15);
                    int off = r * 128 + ((chunk ^ (r & 7)) << 4);
                    ldsm4(bh, sBh_u + off);
                    ldsm4(bl, sBl_u + off);
                    #pragma unroll
                    for (int mt = 0; mt < 2; mt++) {
                        #pragma unroll
                        for (int nb = 0; nb < 2; nb++) {
                            float* c = acc[mt][2 * ntp + nb];
                            mma16816(c, ah[mt], bh[nb], bh[nb + 2]);
                            mma16816(c, ah[mt], bl[nb], bl[nb + 2]);
                            mma16816(c, al[mt], bh[nb], bh[nb + 2]);
                        }
                    }
                }
            }
        }
        __syncthreads();
    }

    // ---- epilogue ----
    const int q4 = lane & 3;
    #pragma unroll
    for (int nt = 0; nt < 8; nt++) {
        int col = oBase + n_warp * 64 + nt * 8 + q4 * 2;
        float se = 0.f, so = 0.f, qe = 0.f, qo = 0.f;
        #pragma unroll
        for (int mt = 0; mt < 2; mt++) {
            float* c = acc[mt][nt];
            if (WRITE_Y) {
                int r0 = mBase + m_warp * 32 + mt * 16 + (lane >> 2);
                *(float2*)(Y + (size_t)r0 * Cout + col)       = make_float2(c[0], c[1]);
                *(float2*)(Y + (size_t)(r0 + 8) * Cout + col) = make_float2(c[2], c[3]);
            }
            se += c[0] + c[2];  so += c[1] + c[3];
            qe += c[0]*c[0] + c[2]*c[2];
            qo += c[1]*c[1] + c[3]*c[3];
        }
        if (OUT_MAX) {
            float m0 = fmaxf(fmaxf(acc[0][nt][0], acc[0][nt][2]),
                             fmaxf(acc[1][nt][0], acc[1][nt][2]));
            float m1 = fmaxf(fmaxf(acc[0][nt][1], acc[0][nt][3]),
                             fmaxf(acc[1][nt][1], acc[1][nt][3]));
            #pragma unroll
            for (int off = 16; off >= 4; off >>= 1) {
                m0 = fmaxf(m0, __shfl_xor_sync(0xffffffffu, m0, off));
                m1 = fmaxf(m1, __shfl_xor_sync(0xffffffffu, m1, off));
            }
            if (lane < 4) {
                int pt = blockIdx.y * 4 + m_warp;
                int cc = oBase + n_warp * 64 + nt * 8 + lane * 2;
                catXout[(size_t)pt * 512 + cc]     = m0;
                catXout[(size_t)pt * 512 + cc + 1] = m1;
            }
        }
        #pragma unroll
        for (int off = 16; off >= 4; off >>= 1) {
            se += __shfl_down_sync(0xffffffffu, se, off);
            so += __shfl_down_sync(0xffffffffu, so, off);
            qe += __shfl_down_sync(0xffffffffu, qe, off);
            qo += __shfl_down_sync(0xffffffffu, qo, off);
        }
        if (lane < 4) {
            int chl = n_warp * 64 + nt * 8 + lane * 2;
            sS[m_warp * 256 + chl]     = se;
            sS[m_warp * 256 + chl + 1] = so;
            sQ[m_warp * 256 + chl]     = qe;
            sQ[m_warp * 256 + chl + 1] = qo;
        }
    }
    __syncthreads();
    if (tid < 256) {
        float s = 0.f, q = 0.f;
        #pragma unroll
        for (int w = 0; w < 4; w++) { s += sS[w * 256 + tid]; q += sQ[w * 256 + tid]; }
        atomicAdd(&accS[oBase + tid], s);
        atomicAdd(&accQ[oBase + tid], q);
    }
}

// ---------------- output transpose + inline affine5 + BN-ReLU ---------------
__global__ void out_t(const float* __restrict__ y5,
                      const float* __restrict__ accS, const float* __restrict__ accQ,
                      const float* __restrict__ g, const float* __restrict__ bta,
                      float* __restrict__ out)
{
    __shared__ float ts[32][33];
    int tx = threadIdx.x, ty = threadIdx.y;
    int n0 = blockIdx.x * 32, ch0 = blockIdx.y * 32, b = blockIdx.z;
    int ch = ch0 + tx;
    float s, t;
    bn_affine(accS[ch], accQ[ch], g[ch], bta[ch], INV_MSML, s, t);
    #pragma unroll
    for (int r = 0; r < 4; r++) {
        int nl = ty * 4 + r;
        int m = b * NPTS + n0 + nl;
        float v = y5[(size_t)m * 512 + ch];
        ts[nl][tx] = fmaxf(fmaf(v, s, t), 0.f);
    }
    __syncthreads();
    #pragma unroll
    for (int r = 0; r < 4; r++) {
        int chl = ty * 4 + r;
        out[(size_t)b * (512 * NPTS) + (size_t)(ch0 + chl) * NPTS + n0 + tx] = ts[tx][chl];
    }
}

// ---------------- launcher ----------------
extern "C" void kernel_launch(void* const* d_in, const int* in_sizes, int n_in,
                              void* d_out, int out_size)
{
    const float* x  = (const float*)d_in[0];
    const float* W1 = (const float*)d_in[1];
    const float* g1 = (const float*)d_in[2];
    const float* b1 = (const float*)d_in[3];
    const float* W2 = (const float*)d_in[4];
    const float* g2 = (const float*)d_in[5];
    const float* b2 = (const float*)d_in[6];
    const float* W3 = (const float*)d_in[7];
    const float* g3 = (const float*)d_in[8];
    const float* b3 = (const float*)d_in[9];
    const float* W4 = (const float*)d_in[10];
    const float* g4 = (const float*)d_in[11];
    const float* b4 = (const float*)d_in[12];
    const float* W5 = (const float*)d_in[13];
    const float* g5 = (const float*)d_in[14];
    const float* b5 = (const float*)d_in[15];

    float* out    = (float*)d_out;
    float* outIdx = out + IDX_OFF;
    float* outNbr = out + NBR_OFF;

    float *feat, *y2, *y3, *cat, *y5, *accS, *accQ, *gM;
    __nv_bfloat16 *w2h, *w2l, *w3h, *w3l, *w4h, *w4l, *w5h, *w5l;
    cudaGetSymbolAddress((void**)&feat, g_feat);
    cudaGetSymbolAddress((void**)&y2,   g_y2);
    cudaGetSymbolAddress((void**)&y3,   g_y3);
    cudaGetSymbolAddress((void**)&cat,  g_cat);
    cudaGetSymbolAddress((void**)&y5,   g_y5);
    cudaGetSymbolAddress((void**)&w2h,  g_w2h);
    cudaGetSymbolAddress((void**)&w2l,  g_w2l);
    cudaGetSymbolAddress((void**)&w3h,  g_w3h);
    cudaGetSymbolAddress((void**)&w3l,  g_w3l);
    cudaGetSymbolAddress((void**)&w4h,  g_w4h);
    cudaGetSymbolAddress((void**)&w4l,  g_w4l);
    cudaGetSymbolAddress((void**)&w5h,  g_w5h);
    cudaGetSymbolAddress((void**)&w5l,  g_w5l);
    cudaGetSymbolAddress((void**)&accS, g_accS);
    cudaGetSymbolAddress((void**)&accQ, g_accQ);
    cudaGetSymbolAddress((void**)&gM,   g_M);

    cudaFuncSetAttribute(knn_kernel, cudaFuncAttributeMaxDynamicSharedMemorySize, KNN_SMEM);
    cudaFuncSetAttribute(conv2_k,    cudaFuncAttributeMaxDynamicSharedMemorySize, CONV2_SMEM);
    auto* k3 = mma_gemm256<true,  true,  false, true>;
    auto* k4 = mma_gemm512<true,  false, true,  true,  false>;
    auto* k5 = mma_gemm512<false, true,  false, false, true >;
    cudaFuncSetAttribute(k3, cudaFuncAttributeMaxDynamicSharedMemorySize, G256_SMEM);
    cudaFuncSetAttribute(k4, cudaFuncAttributeMaxDynamicSharedMemorySize, G512_SMEM);
    cudaFuncSetAttribute(k5, cudaFuncAttributeMaxDynamicSharedMemorySize, G512_SMEM);

    zero_acc_k<<<4, 256>>>(accS, accQ, gM);
    wconv_k<<<(307200 + 255) / 256, 256>>>(W2, W3, W4, W5,
                                           w2h, w2l, w3h, w3l, w4h, w4l, w5h, w5l);
    knn_kernel<<<2048, 256, KNN_SMEM>>>(x, outIdx, outNbr, feat);
    fstats_k<<<512, 256>>>(feat, gM);

    // conv2: inline conv1+affine1, x1 -> cat[0:64], y2, stats -> accS+64
    conv2_k<<<dim3(1, MBIG / 128), 128, CONV2_SMEM>>>(
        w2h, w2l, feat, W1, gM, g1, b1, y2, cat + 0, accS + 64, accQ + 64);

    // conv3: affine2 inline, x2 -> cat[64:128], y3, stats -> accS+128
    k3<<<dim3(1, MBIG / 128), 256, G256_SMEM>>>(
        w3h, w3l, y2, accS + 64, accQ + 64, g2, b2,
        y3, cat + 64, nullptr, accS + 128, accQ + 128, 64, 128);

    // conv4 (512t, N=256, grid.x=1): affine3 inline, x3 -> cat[128:256],
    // raw x4 -> cat[256:512], stats -> accS+256
    k4<<<dim3(1, MBIG / 128), 512, G512_SMEM>>>(
        w4h, w4l, y3, accS + 128, accQ + 128, g3, b3,
        nullptr, cat + 128, cat + 256, accS + 256, accQ + 256, 128, 256);

    // conv5 (512t, N=256, grid.x=2): MIXED act (identity for ch<256, affine4 else),
    // y5, stats -> accS+512. cat4fix folded in.
    k5<<<dim3(2, MSML / 128), 512, G512_SMEM>>>(
        w5h, w5l, cat, accS + 256, accQ + 256, g4, b4,
        y5, nullptr, nullptr, accS + 512, accQ + 512, 512, 512);

    out_t<<<dim3(NPTS / 32, 16, BATCH), dim3(32, 8)>>>(
        y5, accS + 512, accQ + 512, g5, b5, out);
}

// round 10
// speedup vs baseline: 3.8435x; 1.0913x over previous
#include <cuda_runtime.h>
#include <cuda_bf16.h>
#include <cstdint>
#include <math.h>

// ---------------- problem constants ----------------
#define BATCH 8
#define NPTS  2048
#define KNN   32
#define EMB   512
#define MBIG  (BATCH*NPTS*KNN)   // 524288
#define MSML  (BATCH*NPTS)       // 16384
#define TILES (MBIG/128)         // 4096
#define BN_EPS 1e-5f
#define INV_MBIG (1.f / (float)MBIG)
#define INV_MSML (1.f / (float)MSML)

#define IDX_OFF  (BATCH*EMB*NPTS)                 // 8388608
#define NBR_OFF  (IDX_OFF + BATCH*NPTS*KNN)       // 8912896

// ---------------- scratch ----------------
__device__ float g_feat[8u  * MBIG];
__device__ float g_y2 [64u  * MBIG];
__device__ float g_y3 [128u * MBIG];
__device__ float g_cat[512u * MSML];
__device__ float g_y5 [512u * MSML];
__device__ __nv_bfloat16 g_w2h[64*64],   g_w2l[64*64];
__device__ __nv_bfloat16 g_w3h[128*64],  g_w3l[128*64];
__device__ __nv_bfloat16 g_w4h[256*128], g_w4l[256*128];
__device__ __nv_bfloat16 g_w5h[512*512], g_w5l[512*512];
__device__ float g_accS[1024], g_accQ[1024];
__device__ float g_M[32];

// ---------------- helpers ----------------
__device__ __forceinline__ uint32_t smem_to_u32(const void* p) {
    uint32_t a;
    asm("{ .reg .u64 t; cvta.to.shared.u64 t, %1; cvt.u32.u64 %0, t; }" : "=r"(a) : "l"(p));
    return a;
}
__device__ __forceinline__ uint32_t packbf(float a, float b) {
    __nv_bfloat162 h = __floats2bfloat162_rn(a, b);
    return *(uint32_t*)&h;
}
__device__ __forceinline__ void ldsm4(uint32_t* r, uint32_t addr) {
    asm volatile("ldmatrix.sync.aligned.m8n8.x4.shared.b16 {%0,%1,%2,%3}, [%4];"
        : "=r"(r[0]), "=r"(r[1]), "=r"(r[2]), "=r"(r[3]) : "r"(addr));
}
__device__ __forceinline__ void mma16816(float* c, const uint32_t* a, uint32_t b0, uint32_t b1) {
    asm volatile("mma.sync.aligned.m16n8k16.row.col.f32.bf16.bf16.f32 "
        "{%0,%1,%2,%3}, {%4,%5,%6,%7}, {%8,%9}, {%0,%1,%2,%3};"
        : "+f"(c[0]), "+f"(c[1]), "+f"(c[2]), "+f"(c[3])
        : "r"(a[0]), "r"(a[1]), "r"(a[2]), "r"(a[3]), "r"(b0), "r"(b1));
}
#define CP_COMMIT() asm volatile("cp.async.commit_group;" ::: "memory")
#define CP_WAIT(n)  asm volatile("cp.async.wait_group %0;" :: "n"(n) : "memory")

__device__ __forceinline__ void bn_affine(float as, float aq, float g, float bta,
                                          float invM, float& sc, float& sh) {
    float mu   = as * invM;
    float var  = aq * invM - mu * mu;
    float rstd = 1.f / sqrtf(var + BN_EPS);
    float s    = g * rstd;
    sc = s;
    sh = bta - mu * s;
}

// ---------------- zero accumulators ----------------
__global__ void zero_acc_k(float* s, float* q, float* m) {
    int i = blockIdx.x * blockDim.x + threadIdx.x;
    if (i < 1024) { s[i] = 0.f; q[i] = 0.f; }
    if (i < 32) m[i] = 0.f;
}

// ---------------- weight convert (two halves for launch-order control) ------
__global__ void wconvA_k(const float* W2, const float* W3,
                         __nv_bfloat16* w2h, __nv_bfloat16* w2l,
                         __nv_bfloat16* w3h, __nv_bfloat16* w3l)
{
    int i = blockIdx.x * blockDim.x + threadIdx.x;
    const float* src; __nv_bfloat16 *dh, *dl; int off;
    if      (i < 4096)  { src = W2; dh = w2h; dl = w2l; off = 0; }
    else if (i < 12288) { src = W3; dh = w3h; dl = w3l; off = 4096; }
    else return;
    int j = i - off;
    float w = src[j];
    __nv_bfloat16 h = __float2bfloat16(w);
    dh[j] = h;
    dl[j] = __float2bfloat16(w - __bfloat162float(h));
}
__global__ void wconvB_k(const float* W4, const float* W5,
                         __nv_bfloat16* w4h, __nv_bfloat16* w4l,
                         __nv_bfloat16* w5h, __nv_bfloat16* w5l)
{
    int i = blockIdx.x * blockDim.x + threadIdx.x;
    const float* src; __nv_bfloat16 *dh, *dl; int off;
    if      (i < 32768)  { src = W4; dh = w4h; dl = w4l; off = 0; }
    else if (i < 294912) { src = W5; dh = w5h; dl = w5l; off = 32768; }
    else return;
    int j = i - off;
    float w = src[j];
    __nv_bfloat16 h = __float2bfloat16(w);
    dh[j] = h;
    dl[j] = __float2bfloat16(w - __bfloat162float(h));
}

// ---------------- kNN + fused feat moments ----------------
#define KNN_SMEM ((8192 + 8 * 2112) * 4)
__global__ __launch_bounds__(256)
void knn_kernel(const float* __restrict__ x,
                float* __restrict__ outIdx,
                float* __restrict__ outNbr,
                float* __restrict__ feat,
                float* __restrict__ gM)
{
    extern __shared__ float km[];
    float* px  = km;
    float* py  = km + 2048;
    float* pz  = km + 4096;
    float* pxx = km + 6144;
    float* sdall = km + 8192;

    int tid = threadIdx.x, wid = tid >> 5, lane = tid & 31;
    int b = blockIdx.x >> 8;
    int i = ((blockIdx.x & 255) << 3) + wid;
    const float* xb = x + (size_t)b * 3 * NPTS;

    for (int j = tid; j < NPTS; j += 256) {
        float a0 = xb[j], a1 = xb[NPTS + j], a2 = xb[2 * NPTS + j];
        px[j] = a0; py[j] = a1; pz[j] = a2;
        pxx[j] = a0 * a0 + a1 * a1 + a2 * a2;
    }
    __syncthreads();

    float* sd = sdall + wid * 2112;
    float q0 = px[i], q1 = py[i], q2 = pz[i], qxx = pxx[i];

    #pragma unroll 4
    for (int c = 0; c < 64; c++) {
        int j = c * 32 + lane;
        float dot   = q0 * px[j] + q1 * py[j] + q2 * pz[j];
        float inner = -2.f * dot;
        float t     = (-qxx) - inner;
        sd[c * 33 + lane] = t - pxx[j];
    }
    __syncwarp();

    float cm0 = -3.4e38f, cm1 = -3.4e38f;
    #pragma unroll 4
    for (int e = 0; e < 32; e++) {
        cm0 = fmaxf(cm0, sd[lane * 33 + e]);
        cm1 = fmaxf(cm1, sd[(lane + 32) * 33 + e]);
    }

    int jsel = 0;
    for (int k = 0; k < KNN; k++) {
        float v; int c;
        if (cm0 >= cm1) { v = cm0; c = lane; } else { v = cm1; c = lane + 32; }
        #pragma unroll
        for (int off = 16; off; off >>= 1) {
            float ov = __shfl_down_sync(0xffffffffu, v, off);
            int   oc = __shfl_down_sync(0xffffffffu, c, off);
            if (ov > v || (ov == v && oc < c)) { v = ov; c = oc; }
        }
        c = __shfl_sync(0xffffffffu, c, 0);
        float dv = sd[c * 33 + lane];
        float mv = dv; int ml = lane;
        #pragma unroll
        for (int off = 16; off; off >>= 1) {
            float omv = __shfl_down_sync(0xffffffffu, mv, off);
            int   oml = __shfl_down_sync(0xffffffffu, ml, off);
            if (omv > mv || (omv == mv && oml < ml)) { mv = omv; ml = oml; }
        }
        ml = __shfl_sync(0xffffffffu, ml, 0);
        int j = c * 32 + ml;
        if (lane == k) jsel = j;
        if (lane == ml) { dv = -3.4e38f; sd[c * 33 + ml] = dv; }
        float nm = dv;
        #pragma unroll
        for (int off = 16; off; off >>= 1)
            nm = fmaxf(nm, __shfl_xor_sync(0xffffffffu, nm, off));
        if (c < 32) { if (lane == c) cm0 = nm; }
        else        { if (lane == c - 32) cm1 = nm; }
        __syncwarp();
    }

    int bn = b * NPTS + i;
    int m  = bn * KNN + lane;
    int j  = jsel;
    outIdx[m] = (float)(j + b * NPTS);
    float v0 = px[j], v1 = py[j], v2 = pz[j];
    size_t ofs = (size_t)m * 3;
    outNbr[ofs + 0] = v0; outNbr[ofs + 1] = v1; outNbr[ofs + 2] = v2;
    float* fp = feat + (size_t)m * 8;
    fp[0] = v0; fp[1] = v1; fp[2] = v2;
    fp[3] = q0; fp[4] = q1; fp[5] = q2;

    // ---- fused moments: each thread owns one feat row ----
    float a[27];
    a[0] = v0; a[1] = v1; a[2] = v2; a[3] = q0; a[4] = q1; a[5] = q2;
    {
        int idx = 6;
        #pragma unroll
        for (int t = 0; t < 6; t++)
            #pragma unroll
            for (int u = t; u < 6; u++) a[idx++] = a[t] * a[u];
    }
    #pragma unroll
    for (int off = 16; off; off >>= 1)
        #pragma unroll
        for (int t = 0; t < 27; t++)
            a[t] += __shfl_down_sync(0xffffffffu, a[t], off);
    __syncthreads();                 // all warps done with sd before reuse
    float* red = sdall;              // reuse
    if (lane == 0)
        #pragma unroll
        for (int t = 0; t < 27; t++) red[wid * 27 + t] = a[t];
    __syncthreads();
    if (tid < 27) {
        float s = 0.f;
        #pragma unroll
        for (int w = 0; w < 8; w++) s += red[w * 27 + tid];
        atomicAdd(&gM[tid], s);
    }
}

// ---------------- persistent bf16x3 GEMM (conv2/3/4) -------------------------
// B resident in smem, 2 syncs/tile, stats accumulated in smem across tiles.
template <int NWN, int CIN, bool A_FEAT, bool HAS_ACT, bool IN_MAX, bool OUT_MAX, bool WRITE_Y>
__global__ __launch_bounds__(NWN * 128, NWN == 1 ? 4 : (NWN == 2 ? 2 : 1))
void pg_k(const __nv_bfloat16* __restrict__ Wh, const __nv_bfloat16* __restrict__ Wl,
          const float* __restrict__ X, const float* __restrict__ W1,
          const float* __restrict__ gM,
          const float* __restrict__ accSin, const float* __restrict__ accQin,
          const float* __restrict__ gIn, const float* __restrict__ bIn,
          float* __restrict__ Y, float* __restrict__ catXin, float* __restrict__ catXout,
          float* __restrict__ accS, float* __restrict__ accQ)
{
    constexpr int THREADS = NWN * 128;
    constexpr int NT  = NWN * 64;          // = Cout
    constexpr int NKT = CIN / 64;
    constexpr int AREG = 2048 / THREADS;   // float4 per thread per k-chunk
    constexpr int OFF_SAL = NKT * 16384;
    constexpr int OFF_SBH = 2 * NKT * 16384;
    constexpr int OFF_SBL = OFF_SBH + NKT * NT * 128;
    constexpr int OFF_AFF = OFF_SBL + NKT * NT * 128;
    constexpr int OFF_W1  = OFF_AFF + 2 * CIN * 4;
    constexpr int OFF_XM  = OFF_W1 + (A_FEAT ? 1536 : 0);
    constexpr int OFF_ST  = OFF_XM + NKT * 256 * 4;

    extern __shared__ __align__(16) uint8_t smem[];
    uint8_t* sAh = smem;
    uint8_t* sAl = smem + OFF_SAL;
    uint8_t* sBh = smem + OFF_SBH;
    uint8_t* sBl = smem + OFF_SBL;
    float* scs  = (float*)(smem + OFF_AFF);
    float* shs  = scs + CIN;
    float* w1s  = (float*)(smem + OFF_W1);
    int*   xmax = (int*)(smem + OFF_XM);
    float* sS   = (float*)(smem + OFF_ST);
    float* sQ   = sS + 4 * NT;

    const int tid  = threadIdx.x;
    const int wid  = tid >> 5;
    const int lane = tid & 31;
    const int m_warp = wid & 3;
    const int n_warp = wid >> 2;

    const uint32_t smem_u = smem_to_u32(smem);
    const uint32_t sAh_u = smem_u;
    const uint32_t sAl_u = smem_u + OFF_SAL;
    const uint32_t sBh_u = smem_u + OFF_SBH;
    const uint32_t sBl_u = smem_u + OFF_SBL;

    const float4* Xv = (const float4*)X;
    const uint4* Whv = (const uint4*)Wh;
    const uint4* Wlv = (const uint4*)Wl;
    constexpr int cinV = CIN / 4;
    constexpr int cinW = CIN / 8;

    // ---- setup: B resident, affine, zero stats/xmax ----
    for (int idx = tid; idx < NKT * NT * 8; idx += THREADS) {
        int n = idx / (NKT * 8);
        int rem = idx - n * (NKT * 8);
        int kt = rem >> 3, c8 = rem & 7;
        int addr = kt * NT * 128 + n * 128 + ((c8 ^ (n & 7)) << 4);
        size_t g = (size_t)n * cinW + kt * 8 + c8;
        *(uint4*)(sBh + addr) = Whv[g];
        *(uint4*)(sBl + addr) = Wlv[g];
    }
    if (A_FEAT) {
        for (int t = tid; t < 384; t += THREADS) w1s[t] = W1[t];
        if (tid < 64) {
            int o = tid;
            float w[6];
            #pragma unroll
            for (int t = 0; t < 6; t++) w[t] = W1[o * 6 + t];
            float s = 0.f;
            #pragma unroll
            for (int t = 0; t < 6; t++) s += w[t] * gM[t];
            float mu = s * INV_MBIG;
            float qq = 0.f; int idx = 6;
            #pragma unroll
            for (int t = 0; t < 6; t++)
                #pragma unroll
                for (int u = t; u < 6; u++) {
                    float term = w[t] * w[u] * gM[idx++];
                    qq += (t == u) ? term : 2.f * term;
                }
            float var  = qq * INV_MBIG - mu * mu;
            float rstd = 1.f / sqrtf(var + BN_EPS);
            float scale = gIn[o] * rstd;
            scs[o] = scale;
            shs[o] = bIn[o] - mu * scale;
        }
    }
    if (HAS_ACT) {
        for (int ch = tid; ch < CIN; ch += THREADS)
            bn_affine(accSin[ch], accQin[ch], gIn[ch], bIn[ch], INV_MBIG, scs[ch], shs[ch]);
    }
    for (int t = tid; t < NKT * 256; t += THREADS) xmax[t] = 0;
    for (int t = tid; t < 4 * NT; t += THREADS) { sS[t] = 0.f; sQ[t] = 0.f; }
    __syncthreads();

    float4 areg[A_FEAT ? 1 : AREG];
    if (!A_FEAT) {
        int mb = blockIdx.x * 128;
        #pragma unroll
        for (int j = 0; j < AREG; j++) {
            int linear = tid + j * THREADS;
            int row = linear >> 4, ch = linear & 15;
            areg[j] = Xv[(size_t)(mb + row) * cinV + ch];
        }
    }

    for (int t = blockIdx.x; t < TILES; t += gridDim.x) {
        const int mBase = t * 128;

        // ---- convert A (all k-chunks) ----
        if (A_FEAT) {
            #pragma unroll
            for (int j = 0; j < 16; j++) {
                int linear = tid + j * 128;
                int row = linear >> 4, ch = linear & 15;
                const float4* fr = (const float4*)(X + (size_t)(mBase + row) * 8);
                float4 fa = fr[0], fb = fr[1];
                float f0 = fa.x, f1 = fa.y, f2 = fa.z, f3 = fa.w, f4 = fb.x, f5 = fb.y;
                float4 v;
                #pragma unroll
                for (int cc = 0; cc < 4; cc++) {
                    const float* w = &w1s[(ch * 4 + cc) * 6];
                    (&v.x)[cc] = w[0]*f0 + w[1]*f1 + w[2]*f2 + w[3]*f3 + w[4]*f4 + w[5]*f5;
                }
                int cb = ch * 4;
                float4 s4 = *(const float4*)(scs + cb);
                float4 t4 = *(const float4*)(shs + cb);
                v.x = fmaxf(fmaf(v.x, s4.x, t4.x), 0.f);
                v.y = fmaxf(fmaf(v.y, s4.y, t4.y), 0.f);
                v.z = fmaxf(fmaf(v.z, s4.z, t4.z), 0.f);
                v.w = fmaxf(fmaf(v.w, s4.w, t4.w), 0.f);
                if (IN_MAX) {
                    int base = (row >> 5) * 64 + ch * 4;
                    atomicMax(&xmax[base + 0], __float_as_int(v.x));
                    atomicMax(&xmax[base + 1], __float_as_int(v.y));
                    atomicMax(&xmax[base + 2], __float_as_int(v.z));
                    atomicMax(&xmax[base + 3], __float_as_int(v.w));
                }
                float hx = __bfloat162float(__float2bfloat16(v.x));
                float hy = __bfloat162float(__float2bfloat16(v.y));
                float hz = __bfloat162float(__float2bfloat16(v.z));
                float hw = __bfloat162float(__float2bfloat16(v.w));
                int c = ch >> 1, sub = ch & 1;
                int addr = row * 128 + ((c ^ (row & 7)) << 4) + sub * 8;
                *(uint2*)(sAh + addr) = make_uint2(packbf(v.x, v.y), packbf(v.z, v.w));
                *(uint2*)(sAl + addr) = make_uint2(packbf(v.x - hx, v.y - hy), packbf(v.z - hz, v.w - hw));
            }
        } else {
            #pragma unroll
            for (int kt = 0; kt < NKT; kt++) {
                if (kt > 0) {
                    #pragma unroll
                    for (int j = 0; j < AREG; j++) {
                        int linear = tid + j * THREADS;
                        int row = linear >> 4, ch = linear & 15;
                        areg[j] = Xv[(size_t)(mBase + row) * cinV + kt * 16 + ch];
                    }
                }
                #pragma unroll
                for (int j = 0; j < AREG; j++) {
                    int linear = tid + j * THREADS;
                    int row = linear >> 4, ch = linear & 15;
                    float4 v = areg[j];
                    if (HAS_ACT) {
                        int cb = kt * 64 + ch * 4;
                        float4 s4 = *(const float4*)(scs + cb);
                        float4 t4 = *(const float4*)(shs + cb);
                        v.x = fmaxf(fmaf(v.x, s4.x, t4.x), 0.f);
                        v.y = fmaxf(fmaf(v.y, s4.y, t4.y), 0.f);
                        v.z = fmaxf(fmaf(v.z, s4.z, t4.z), 0.f);
                        v.w = fmaxf(fmaf(v.w, s4.w, t4.w), 0.f);
                    }
                    if (IN_MAX) {
                        int base = kt * 256 + (row >> 5) * 64 + ch * 4;
                        atomicMax(&xmax[base + 0], __float_as_int(v.x));
                        atomicMax(&xmax[base + 1], __float_as_int(v.y));
                        atomicMax(&xmax[base + 2], __float_as_int(v.z));
                        atomicMax(&xmax[base + 3], __float_as_int(v.w));
                    }
                    float hx = __bfloat162float(__float2bfloat16(v.x));
                    float hy = __bfloat162float(__float2bfloat16(v.y));
                    float hz = __bfloat162float(__float2bfloat16(v.z));
                    float hw = __bfloat162float(__float2bfloat16(v.w));
                    int c = ch >> 1, sub = ch & 1;
                    int addr = kt * 16384 + row * 128 + ((c ^ (row & 7)) << 4) + sub * 8;
                    *(uint2*)(sAh + addr) = make_uint2(packbf(v.x, v.y), packbf(v.z, v.w));
                    *(uint2*)(sAl + addr) = make_uint2(packbf(v.x - hx, v.y - hy), packbf(v.z - hz, v.w - hw));
                }
            }
        }
        __syncthreads();

        // ---- input-side max -> cat, reset xmax ----
        if (IN_MAX) {
            for (int e = tid; e < NKT * 256; e += THREADS) {
                int kt = e >> 8, p = (e >> 6) & 3, chl = e & 63;
                catXin[(size_t)(t * 4 + p) * 512 + kt * 64 + chl] = __int_as_float(xmax[e]);
                xmax[e] = 0;
            }
        }

        // ---- prefetch next tile chunk 0 ----
        if (!A_FEAT) {
            int tn = t + gridDim.x;
            if (tn < TILES) {
                int mb = tn * 128;
                #pragma unroll
                for (int j = 0; j < AREG; j++) {
                    int linear = tid + j * THREADS;
                    int row = linear >> 4, ch = linear & 15;
                    areg[j] = Xv[(size_t)(mb + row) * cinV + ch];
                }
            }
        }

        // ---- MMA ----
        float acc[2][8][4];
        #pragma unroll
        for (int mt = 0; mt < 2; mt++)
            #pragma unroll
            for (int nt = 0; nt < 8; nt++)
                #pragma unroll
                for (int v = 0; v < 4; v++) acc[mt][nt][v] = 0.f;

        #pragma unroll
        for (int kt = 0; kt < NKT; kt++) {
            const uint32_t aH = sAh_u + kt * 16384;
            const uint32_t aL = sAl_u + kt * 16384;
            const uint32_t bH = sBh_u + kt * NT * 128;
            const uint32_t bL = sBl_u + kt * NT * 128;
            #pragma unroll
            for (int ks = 0; ks < 4; ks++) {
                uint32_t ah[2][4], al[2][4];
                int chunk = 2 * ks + (lane >> 4);
                #pragma unroll
                for (int mt = 0; mt < 2; mt++) {
                    int r = m_warp * 32 + mt * 16 + (lane & 15);
                    int off = r * 128 + ((chunk ^ (r & 7)) << 4);
                    ldsm4(ah[mt], aH + off);
                    ldsm4(al[mt], aL + off);
                }
                #pragma unroll
                for (int ntp = 0; ntp < 4; ntp++) {
                    uint32_t bh[4], bl[4];
                    int r = n_warp * 64 + ntp * 16 + (lane & 15);
                    int off = r * 128 + ((chunk ^ (r & 7)) << 4);
                    ldsm4(bh, bH + off);
                    ldsm4(bl, bL + off);
                    #pragma unroll
                    for (int mt = 0; mt < 2; mt++) {
                        #pragma unroll
                        for (int nb = 0; nb < 2; nb++) {
                            float* c = acc[mt][2 * ntp + nb];
                            mma16816(c, ah[mt], bh[nb], bh[nb + 2]);
                            mma16816(c, ah[mt], bl[nb], bl[nb + 2]);
                            mma16816(c, al[mt], bh[nb], bh[nb + 2]);
                        }
                    }
                }
            }
        }

        // ---- per-tile epilogue ----
        const int q4 = lane & 3;
        #pragma unroll
        for (int nt = 0; nt < 8; nt++) {
            int col = n_warp * 64 + nt * 8 + q4 * 2;
            float se = 0.f, so = 0.f, qe = 0.f, qo = 0.f;
            #pragma unroll
            for (int mt = 0; mt < 2; mt++) {
                float* c = acc[mt][nt];
                if (WRITE_Y) {
                    int r0 = mBase + m_warp * 32 + mt * 16 + (lane >> 2);
                    *(float2*)(Y + (size_t)r0 * NT + col)       = make_float2(c[0], c[1]);
                    *(float2*)(Y + (size_t)(r0 + 8) * NT + col) = make_float2(c[2], c[3]);
                }
                se += c[0] + c[2];  so += c[1] + c[3];
                qe += c[0]*c[0] + c[2]*c[2];
                qo += c[1]*c[1] + c[3]*c[3];
            }
            if (OUT_MAX) {
                float m0 = fmaxf(fmaxf(acc[0][nt][0], acc[0][nt][2]),
                                 fmaxf(acc[1][nt][0], acc[1][nt][2]));
                float m1 = fmaxf(fmaxf(acc[0][nt][1], acc[0][nt][3]),
                                 fmaxf(acc[1][nt][1], acc[1][nt][3]));
                #pragma unroll
                for (int off = 16; off >= 4; off >>= 1) {
                    m0 = fmaxf(m0, __shfl_xor_sync(0xffffffffu, m0, off));
                    m1 = fmaxf(m1, __shfl_xor_sync(0xffffffffu, m1, off));
                }
                if (lane < 4) {
                    int pt = t * 4 + m_warp;
                    int cc = n_warp * 64 + nt * 8 + lane * 2;
                    catXout[(size_t)pt * 512 + cc]     = m0;
                    catXout[(size_t)pt * 512 + cc + 1] = m1;
                }
            }
            #pragma unroll
            for (int off = 16; off >= 4; off >>= 1) {
                se += __shfl_down_sync(0xffffffffu, se, off);
                so += __shfl_down_sync(0xffffffffu, so, off);
                qe += __shfl_down_sync(0xffffffffu, qe, off);
                qo += __shfl_down_sync(0xffffffffu, qo, off);
            }
            if (lane < 4) {
                int chl = n_warp * 64 + nt * 8 + lane * 2;
                sS[m_warp * NT + chl]     += se;
                sS[m_warp * NT + chl + 1] += so;
                sQ[m_warp * NT + chl]     += qe;
                sQ[m_warp * NT + chl + 1] += qo;
            }
        }
        __syncthreads();
    }

    // ---- final stats reduction (once per CTA) ----
    for (int ch = tid; ch < NT; ch += THREADS) {
        float s = 0.f, q = 0.f;
        #pragma unroll
        for (int w = 0; w < 4; w++) { s += sS[w * NT + ch]; q += sQ[w * NT + ch]; }
        atomicAdd(&accS[ch], s);
        atomicAdd(&accQ[ch], q);
    }
}

// ---------------- 512-thread streaming GEMM (conv5) --------------------------
#define G512_SB    32768
#define G512_AFF   163840
#define G512_SMEM  168960
__global__ __launch_bounds__(512, 1)
void conv5_k(const __nv_bfloat16* __restrict__ Wh, const __nv_bfloat16* __restrict__ Wl,
             const float* __restrict__ X,
             const float* __restrict__ accSin, const float* __restrict__ accQin,
             const float* __restrict__ gIn, const float* __restrict__ bIn,
             float* __restrict__ Y, float* __restrict__ accS, float* __restrict__ accQ)
{
    constexpr int Cin = 512, Cout = 512;
    extern __shared__ __align__(16) uint8_t smem[];
    uint8_t* sAh = smem;
    uint8_t* sAl = smem + 16384;
    float* scs  = (float*)(smem + G512_AFF);
    float* shs  = scs + 512;
    float* sS   = (float*)smem;
    float* sQ   = sS + 1024;

    const int tid  = threadIdx.x;
    const int wid  = tid >> 5;
    const int lane = tid & 31;
    const int m_warp = wid & 3;
    const int n_warp = wid >> 2;
    const int mBase = blockIdx.y * 128;
    const int oBase = blockIdx.x * 256;

    const uint32_t smem_u = smem_to_u32(smem);
    const uint32_t sAh_u = smem_u;
    const uint32_t sAl_u = smem_u + 16384;

    const float4* Xv = (const float4*)X;
    const uint4* Whv = (const uint4*)Wh;
    const uint4* Wlv = (const uint4*)Wl;
    const int cinV = Cin >> 2;
    const int cinW = Cin >> 3;
    const int nkt  = Cin >> 6;

    // MIXED act: identity for ch<256, affine4 for ch>=256
    for (int ch = tid; ch < 512; ch += 512) {
        if (ch < 256) { scs[ch] = 1.f; shs[ch] = 0.f; }
        else bn_affine(accSin[ch - 256], accQin[ch - 256], gIn[ch - 256], bIn[ch - 256],
                       INV_MBIG, scs[ch], shs[ch]);
    }

    {
        uint32_t sB0 = smem_u + G512_SB;
        #pragma unroll
        for (int j = 0; j < 4; j++) {
            int linear = tid + j * 512;
            int row = linear >> 3, ch = linear & 7;
            uint32_t addr = sB0 + row * 128 + ((ch ^ (row & 7)) << 4);
            const uint4* sh_ = &Whv[(size_t)(oBase + row) * cinW + ch];
            const uint4* sl_ = &Wlv[(size_t)(oBase + row) * cinW + ch];
            asm volatile("cp.async.cg.shared.global [%0], [%1], 16;" :: "r"(addr), "l"(sh_) : "memory");
            asm volatile("cp.async.cg.shared.global [%0], [%1], 16;" :: "r"(addr + 32768), "l"(sl_) : "memory");
        }
        CP_COMMIT();
    }
    float4 areg[4];
    #pragma unroll
    for (int j = 0; j < 4; j++) {
        int linear = tid + j * 512;
        int row = linear >> 4, ch = linear & 15;
        areg[j] = Xv[(size_t)(mBase + row) * cinV + ch];
    }
    __syncthreads();

    float acc[2][8][4];
    #pragma unroll
    for (int mt = 0; mt < 2; mt++)
        #pragma unroll
        for (int nt = 0; nt < 8; nt++)
            #pragma unroll
            for (int v = 0; v < 4; v++) acc[mt][nt][v] = 0.f;

    for (int kt = 0; kt < nkt; kt++) {
        if (kt + 1 < nkt) {
            uint32_t sBn = smem_u + G512_SB + ((kt + 1) & 1) * 65536;
            #pragma unroll
            for (int j = 0; j < 4; j++) {
                int linear = tid + j * 512;
                int row = linear >> 3, ch = linear & 7;
                uint32_t addr = sBn + row * 128 + ((ch ^ (row & 7)) << 4);
                const uint4* sh_ = &Whv[(size_t)(oBase + row) * cinW + (kt + 1) * 8 + ch];
                const uint4* sl_ = &Wlv[(size_t)(oBase + row) * cinW + (kt + 1) * 8 + ch];
                asm volatile("cp.async.cg.shared.global [%0], [%1], 16;" :: "r"(addr), "l"(sh_) : "memory");
                asm volatile("cp.async.cg.shared.global [%0], [%1], 16;" :: "r"(addr + 32768), "l"(sl_) : "memory");
            }
            CP_COMMIT();
        }

        #pragma unroll
        for (int j = 0; j < 4; j++) {
            int linear = tid + j * 512;
            int row = linear >> 4, ch = linear & 15;
            float4 v = areg[j];
            {
                int cb = kt * 64 + ch * 4;
                float4 s4 = *(const float4*)(scs + cb);
                float4 t4 = *(const float4*)(shs + cb);
                v.x = fmaxf(fmaf(v.x, s4.x, t4.x), 0.f);
                v.y = fmaxf(fmaf(v.y, s4.y, t4.y), 0.f);
                v.z = fmaxf(fmaf(v.z, s4.z, t4.z), 0.f);
                v.w = fmaxf(fmaf(v.w, s4.w, t4.w), 0.f);
            }
            float hx = __bfloat162float(__float2bfloat16(v.x));
            float hy = __bfloat162float(__float2bfloat16(v.y));
            float hz = __bfloat162float(__float2bfloat16(v.z));
            float hw = __bfloat162float(__float2bfloat16(v.w));
            int c = ch >> 1, sub = ch & 1;
            int addr = row * 128 + ((c ^ (row & 7)) << 4) + sub * 8;
            *(uint2*)(sAh + addr) = make_uint2(packbf(v.x, v.y), packbf(v.z, v.w));
            *(uint2*)(sAl + addr) = make_uint2(packbf(v.x - hx, v.y - hy), packbf(v.z - hz, v.w - hw));
        }
        if (kt + 1 < nkt) { CP_WAIT(1); } else { CP_WAIT(0); }
        __syncthreads();

        if (kt + 1 < nkt) {
            #pragma unroll
            for (int j = 0; j < 4; j++) {
                int linear = tid + j * 512;
                int row = linear >> 4, ch = linear & 15;
                areg[j] = Xv[(size_t)(mBase + row) * cinV + (kt + 1) * 16 + ch];
            }
        }

        {
            const uint32_t sBh_u = smem_u + G512_SB + (kt & 1) * 65536;
            const uint32_t sBl_u = sBh_u + 32768;
            #pragma unroll
            for (int ks = 0; ks < 4; ks++) {
                uint32_t ah[2][4], al[2][4];
                int chunk = 2 * ks + (lane >> 4);
                #pragma unroll
                for (int mt = 0; mt < 2; mt++) {
                    int r = m_warp * 32 + mt * 16 + (lane & 15);
                    int off = r * 128 + ((chunk ^ (r & 7)) << 4);
                    ldsm4(ah[mt], sAh_u + off);
                    ldsm4(al[mt], sAl_u + off);
                }
                #pragma unroll
                for (int ntp = 0; ntp < 4; ntp++) {
                    uint32_t bh[4], bl[4];
                    int r = n_warp * 64 + ntp * 16 + (lane & 15);
                    int off = r * 128 + ((chunk ^ (r & 7)) << 4);
                    ldsm4(bh, sBh_u + off);
                    ldsm4(bl, sBl_u + off);
                    #pragma unroll
                    for (int mt = 0; mt < 2; mt++) {
                        #pragma unroll
                        for (int nb = 0; nb < 2; nb++) {
                            float* c = acc[mt][2 * ntp + nb];
                            mma16816(c, ah[mt], bh[nb], bh[nb + 2]);
                            mma16816(c, ah[mt], bl[nb], bl[nb + 2]);
                            mma16816(c, al[mt], bh[nb], bh[nb + 2]);
                        }
                    }
                }
            }
        }
        __syncthreads();
    }

    const int q4 = lane & 3;
    #pragma unroll
    for (int nt = 0; nt < 8; nt++) {
        int col = oBase + n_warp * 64 + nt * 8 + q4 * 2;
        float se = 0.f, so = 0.f, qe = 0.f, qo = 0.f;
        #pragma unroll
        for (int mt = 0; mt < 2; mt++) {
            float* c = acc[mt][nt];
            int r0 = mBase + m_warp * 32 + mt * 16 + (lane >> 2);
            *(float2*)(Y + (size_t)r0 * Cout + col)       = make_float2(c[0], c[1]);
            *(float2*)(Y + (size_t)(r0 + 8) * Cout + col) = make_float2(c[2], c[3]);
            se += c[0] + c[2];  so += c[1] + c[3];
            qe += c[0]*c[0] + c[2]*c[2];
            qo += c[1]*c[1] + c[3]*c[3];
        }
        #pragma unroll
        for (int off = 16; off >= 4; off >>= 1) {
            se += __shfl_down_sync(0xffffffffu, se, off);
            so += __shfl_down_sync(0xffffffffu, so, off);
            qe += __shfl_down_sync(0xffffffffu, qe, off);
            qo += __shfl_down_sync(0xffffffffu, qo, off);
        }
        if (lane < 4) {
            int chl = n_warp * 64 + nt * 8 + lane * 2;
            sS[m_warp * 256 + chl]     = se;
            sS[m_warp * 256 + chl + 1] = so;
            sQ[m_warp * 256 + chl]     = qe;
            sQ[m_warp * 256 + chl + 1] = qo;
        }
    }
    __syncthreads();
    if (tid < 256) {
        float s = 0.f, q = 0.f;
        #pragma unroll
        for (int w = 0; w < 4; w++) { s += sS[w * 256 + tid]; q += sQ[w * 256 + tid]; }
        atomicAdd(&accS[oBase + tid], s);
        atomicAdd(&accQ[oBase + tid], q);
    }
}

// ---------------- output transpose + inline affine5 --------------------------
__global__ void out_t(const float* __restrict__ y5,
                      const float* __restrict__ accS, const float* __restrict__ accQ,
                      const float* __restrict__ g, const float* __restrict__ bta,
                      float* __restrict__ out)
{
    __shared__ float ts[32][33];
    int tx = threadIdx.x, ty = threadIdx.y;
    int n0 = blockIdx.x * 32, ch0 = blockIdx.y * 32, b = blockIdx.z;
    int ch = ch0 + tx;
    float s, t;
    bn_affine(accS[ch], accQ[ch], g[ch], bta[ch], INV_MSML, s, t);
    #pragma unroll
    for (int r = 0; r < 4; r++) {
        int nl = ty * 4 + r;
        int m = b * NPTS + n0 + nl;
        float v = y5[(size_t)m * 512 + ch];
        ts[nl][tx] = fmaxf(fmaf(v, s, t), 0.f);
    }
    __syncthreads();
    #pragma unroll
    for (int r = 0; r < 4; r++) {
        int chl = ty * 4 + r;
        out[(size_t)b * (512 * NPTS) + (size_t)(ch0 + chl) * NPTS + n0 + tx] = ts[tx][chl];
    }
}

// ---------------- launcher ----------------
extern "C" void kernel_launch(void* const* d_in, const int* in_sizes, int n_in,
                              void* d_out, int out_size)
{
    const float* x  = (const float*)d_in[0];
    const float* W1 = (const float*)d_in[1];
    const float* g1 = (const float*)d_in[2];
    const float* b1 = (const float*)d_in[3];
    const float* W2 = (const float*)d_in[4];
    const float* g2 = (const float*)d_in[5];
    const float* b2 = (const float*)d_in[6];
    const float* W3 = (const float*)d_in[7];
    const float* g3 = (const float*)d_in[8];
    const float* b3 = (const float*)d_in[9];
    const float* W4 = (const float*)d_in[10];
    const float* g4 = (const float*)d_in[11];
    const float* b4 = (const float*)d_in[12];
    const float* W5 = (const float*)d_in[13];
    const float* g5 = (const float*)d_in[14];
    const float* b5 = (const float*)d_in[15];

    float* out    = (float*)d_out;
    float* outIdx = out + IDX_OFF;
    float* outNbr = out + NBR_OFF;

    float *feat, *y2, *y3, *cat, *y5, *accS, *accQ, *gM;
    __nv_bfloat16 *w2h, *w2l, *w3h, *w3l, *w4h, *w4l, *w5h, *w5l;
    cudaGetSymbolAddress((void**)&feat, g_feat);
    cudaGetSymbolAddress((void**)&y2,   g_y2);
    cudaGetSymbolAddress((void**)&y3,   g_y3);
    cudaGetSymbolAddress((void**)&cat,  g_cat);
    cudaGetSymbolAddress((void**)&y5,   g_y5);
    cudaGetSymbolAddress((void**)&w2h,  g_w2h);
    cudaGetSymbolAddress((void**)&w2l,  g_w2l);
    cudaGetSymbolAddress((void**)&w3h,  g_w3h);
    cudaGetSymbolAddress((void**)&w3l,  g_w3l);
    cudaGetSymbolAddress((void**)&w4h,  g_w4h);
    cudaGetSymbolAddress((void**)&w4l,  g_w4l);
    cudaGetSymbolAddress((void**)&w5h,  g_w5h);
    cudaGetSymbolAddress((void**)&w5l,  g_w5l);
    cudaGetSymbolAddress((void**)&accS, g_accS);
    cudaGetSymbolAddress((void**)&accQ, g_accQ);
    cudaGetSymbolAddress((void**)&gM,   g_M);

    auto* p2 = pg_k<1, 64,  true,  false, true,  false, true >;
    auto* p3 = pg_k<2, 64,  false, true,  true,  false, true >;
    auto* p4 = pg_k<4, 128, false, true,  true,  true,  false>;
    const int SM2 = 54272, SM3 = 71168, SM4 = 207872;
    cudaFuncSetAttribute(knn_kernel, cudaFuncAttributeMaxDynamicSharedMemorySize, KNN_SMEM);
    cudaFuncSetAttribute(p2, cudaFuncAttributeMaxDynamicSharedMemorySize, SM2);
    cudaFuncSetAttribute(p3, cudaFuncAttributeMaxDynamicSharedMemorySize, SM3);
    cudaFuncSetAttribute(p4, cudaFuncAttributeMaxDynamicSharedMemorySize, SM4);
    cudaFuncSetAttribute(conv5_k, cudaFuncAttributeMaxDynamicSharedMemorySize, G512_SMEM);

    zero_acc_k<<<4, 256>>>(accS, accQ, gM);                                        // 0
    wconvA_k<<<(12288 + 255) / 256, 256>>>(W2, W3, w2h, w2l, w3h, w3l);            // 1
    wconvB_k<<<(294912 + 255) / 256, 256>>>(W4, W5, w4h, w4l, w5h, w5l);           // 2
    knn_kernel<<<2048, 256, KNN_SMEM>>>(x, outIdx, outNbr, feat, gM);              // 3 (profiled)

    // conv2 (persistent): inline conv1+affine1(gM), x1 -> cat[0:64], y2
    p2<<<592, 128, SM2>>>(w2h, w2l, feat, W1, gM,
                          nullptr, nullptr, g1, b1,
                          y2, cat + 0, nullptr, accS + 64, accQ + 64);

    // conv3 (persistent): affine2, x2 -> cat[64:128], y3
    p3<<<296, 256, SM3>>>(w3h, w3l, y2, nullptr, nullptr,
                          accS + 64, accQ + 64, g2, b2,
                          y3, cat + 64, nullptr, accS + 128, accQ + 128);

    // conv4 (persistent): affine3, x3 -> cat[128:256], raw x4 -> cat[256:512]
    p4<<<148, 512, SM4>>>(w4h, w4l, y3, nullptr, nullptr,
                          accS + 128, accQ + 128, g3, b3,
                          nullptr, cat + 128, cat + 256, accS + 256, accQ + 256);

    // conv5 (streaming, mixed affine4 on x4 half): y5
    conv5_k<<<dim3(2, MSML / 128), 512, G512_SMEM>>>(
        w5h, w5l, cat, accS + 256, accQ + 256, g4, b4,
        y5, accS + 512, accQ + 512);

    out_t<<<dim3(NPTS / 32, 16, BATCH), dim3(32, 8)>>>(
        y5, accS + 512, accQ + 512, g5, b5, out);
}

// round 13
// speedup vs baseline: 3.8990x; 1.0144x over previous
#include <cuda_runtime.h>
#include <cuda_bf16.h>
#include <cstdint>
#include <math.h>

// ---------------- problem constants ----------------
#define BATCH 8
#define NPTS  2048
#define KNN   32
#define EMB   512
#define MBIG  (BATCH*NPTS*KNN)   // 524288
#define MSML  (BATCH*NPTS)       // 16384
#define TILES (MBIG/128)         // 4096
#define BN_EPS 1e-5f
#define INV_MBIG (1.f / (float)MBIG)
#define INV_MSML (1.f / (float)MSML)

#define IDX_OFF  (BATCH*EMB*NPTS)                 // 8388608
#define NBR_OFF  (IDX_OFF + BATCH*NPTS*KNN)       // 8912896

// ---------------- scratch ----------------
__device__ float g_feat[8u  * MBIG];
__device__ float g_y2 [64u  * MBIG];
__device__ float g_y3 [128u * MBIG];
__device__ float g_cat[512u * MSML];
__device__ float g_y5 [512u * MSML];
__device__ __nv_bfloat16 g_w2h[64*64],   g_w2l[64*64];
__device__ __nv_bfloat16 g_w3h[128*64],  g_w3l[128*64];
__device__ __nv_bfloat16 g_w4h[256*128], g_w4l[256*128];
__device__ __nv_bfloat16 g_w5h[512*512], g_w5l[512*512];
__device__ float g_accS[1024], g_accQ[1024];
__device__ float g_M[32];

// ---------------- helpers ----------------
__device__ __forceinline__ uint32_t smem_to_u32(const void* p) {
    uint32_t a;
    asm("{ .reg .u64 t; cvta.to.shared.u64 t, %1; cvt.u32.u64 %0, t; }" : "=r"(a) : "l"(p));
    return a;
}
__device__ __forceinline__ uint32_t packbf(float a, float b) {
    __nv_bfloat162 h = __floats2bfloat162_rn(a, b);
    return *(uint32_t*)&h;
}
__device__ __forceinline__ void ldsm4(uint32_t* r, uint32_t addr) {
    asm volatile("ldmatrix.sync.aligned.m8n8.x4.shared.b16 {%0,%1,%2,%3}, [%4];"
        : "=r"(r[0]), "=r"(r[1]), "=r"(r[2]), "=r"(r[3]) : "r"(addr));
}
__device__ __forceinline__ void mma16816(float* c, const uint32_t* a, uint32_t b0, uint32_t b1) {
    asm volatile("mma.sync.aligned.m16n8k16.row.col.f32.bf16.bf16.f32 "
        "{%0,%1,%2,%3}, {%4,%5,%6,%7}, {%8,%9}, {%0,%1,%2,%3};"
        : "+f"(c[0]), "+f"(c[1]), "+f"(c[2]), "+f"(c[3])
        : "r"(a[0]), "r"(a[1]), "r"(a[2]), "r"(a[3]), "r"(b0), "r"(b1));
}
#define CP_COMMIT() asm volatile("cp.async.commit_group;" ::: "memory")
#define CP_WAIT(n)  asm volatile("cp.async.wait_group %0;" :: "n"(n) : "memory")

__device__ __forceinline__ void bn_affine(float as, float aq, float g, float bta,
                                          float invM, float& sc, float& sh) {
    float mu   = as * invM;
    float var  = aq * invM - mu * mu;
    float rstd = 1.f / sqrtf(var + BN_EPS);
    float s    = g * rstd;
    sc = s;
    sh = bta - mu * s;
}

// ---------------- weight convert A + zero accumulators (fused) --------------
__global__ void wconvA_zero_k(const float* W2, const float* W3,
                              __nv_bfloat16* w2h, __nv_bfloat16* w2l,
                              __nv_bfloat16* w3h, __nv_bfloat16* w3l,
                              float* accS, float* accQ, float* gM)
{
    int i = blockIdx.x * blockDim.x + threadIdx.x;
    if (i < 1024) { accS[i] = 0.f; accQ[i] = 0.f; }
    if (i < 32) gM[i] = 0.f;
    const float* src; __nv_bfloat16 *dh, *dl; int off;
    if      (i < 4096)  { src = W2; dh = w2h; dl = w2l; off = 0; }
    else if (i < 12288) { src = W3; dh = w3h; dl = w3l; off = 4096; }
    else return;
    int j = i - off;
    float w = src[j];
    __nv_bfloat16 h = __float2bfloat16(w);
    dh[j] = h;
    dl[j] = __float2bfloat16(w - __bfloat162float(h));
}
__global__ void wconvB_k(const float* W4, const float* W5,
                         __nv_bfloat16* w4h, __nv_bfloat16* w4l,
                         __nv_bfloat16* w5h, __nv_bfloat16* w5l)
{
    int i = blockIdx.x * blockDim.x + threadIdx.x;
    const float* src; __nv_bfloat16 *dh, *dl; int off;
    if      (i < 32768)  { src = W4; dh = w4h; dl = w4l; off = 0; }
    else if (i < 294912) { src = W5; dh = w5h; dl = w5l; off = 32768; }
    else return;
    int j = i - off;
    float w = src[j];
    __nv_bfloat16 h = __float2bfloat16(w);
    dh[j] = h;
    dl[j] = __float2bfloat16(w - __bfloat162float(h));
}

// ---------------- kNN + fused feat moments ----------------
// Selection v3: per-chunk (max, argLane) tracked in registers; per round only
// 2 dependent shuffle chains (select + refresh) instead of 3.
#define KNN_SMEM ((8192 + 8 * 2112) * 4)
__global__ __launch_bounds__(256)
void knn_kernel(const float* __restrict__ x,
                float* __restrict__ outIdx,
                float* __restrict__ outNbr,
                float* __restrict__ feat,
                float* __restrict__ gM)
{
    extern __shared__ float km[];
    float* px  = km;
    float* py  = km + 2048;
    float* pz  = km + 4096;
    float* pxx = km + 6144;
    float* sdall = km + 8192;

    int tid = threadIdx.x, wid = tid >> 5, lane = tid & 31;
    int b = blockIdx.x >> 8;
    int i = ((blockIdx.x & 255) << 3) + wid;
    const float* xb = x + (size_t)b * 3 * NPTS;

    for (int j = tid; j < NPTS; j += 256) {
        float a0 = xb[j], a1 = xb[NPTS + j], a2 = xb[2 * NPTS + j];
        px[j] = a0; py[j] = a1; pz[j] = a2;
        pxx[j] = a0 * a0 + a1 * a1 + a2 * a2;
    }
    __syncthreads();

    float* sd = sdall + wid * 2112;
    float q0 = px[i], q1 = py[i], q2 = pz[i], qxx = pxx[i];

    #pragma unroll 4
    for (int c = 0; c < 64; c++) {
        int j = c * 32 + lane;
        float dot   = q0 * px[j] + q1 * py[j] + q2 * pz[j];
        float inner = -2.f * dot;
        float t     = (-qxx) - inner;
        sd[c * 33 + lane] = t - pxx[j];
    }
    __syncwarp();

    // per-lane chunk maxima + arg (strict > on ascending e == min-index tie)
    float cm0 = -3.4e38f, cm1 = -3.4e38f;
    int   al0 = 0, al1 = 0;
    #pragma unroll 4
    for (int e = 0; e < 32; e++) {
        float v0 = sd[lane * 33 + e];
        float v1 = sd[(lane + 32) * 33 + e];
        if (v0 > cm0) { cm0 = v0; al0 = e; }
        if (v1 > cm1) { cm1 = v1; al1 = e; }
    }

    int jsel = 0;
    for (int k = 0; k < KNN; k++) {
        // best chunk (max value, min chunk index)
        float v; int c;
        if (cm0 >= cm1) { v = cm0; c = lane; } else { v = cm1; c = lane + 32; }
        #pragma unroll
        for (int off = 16; off; off >>= 1) {
            float ov = __shfl_down_sync(0xffffffffu, v, off);
            int   oc = __shfl_down_sync(0xffffffffu, c, off);
            if (ov > v || (ov == v && oc < c)) { v = ov; c = oc; }
        }
        c = __shfl_sync(0xffffffffu, c, 0);
        // in-chunk argmax lane from the chunk's owner (no rescan)
        int owner = c & 31;
        int alo = (c < 32) ? al0 : al1;
        int ml = __shfl_sync(0xffffffffu, alo, owner);
        int j = c * 32 + ml;
        if (lane == k) jsel = j;
        // remove + cooperative refresh of (max, argLane) for chunk c
        float dv = sd[c * 33 + lane];
        if (lane == ml) { dv = -3.4e38f; sd[c * 33 + ml] = dv; }
        float mv = dv; int mlane = lane;
        #pragma unroll
        for (int off = 16; off; off >>= 1) {
            float omv = __shfl_xor_sync(0xffffffffu, mv, off);
            int   oml = __shfl_xor_sync(0xffffffffu, mlane, off);
            if (omv > mv || (omv == mv && oml < mlane)) { mv = omv; mlane = oml; }
        }
        if (lane == owner) {
            if (c < 32) { cm0 = mv; al0 = mlane; }
            else        { cm1 = mv; al1 = mlane; }
        }
        __syncwarp();
    }

    int bn = b * NPTS + i;
    int m  = bn * KNN + lane;
    int j  = jsel;
    outIdx[m] = (float)(j + b * NPTS);
    float v0 = px[j], v1 = py[j], v2 = pz[j];
    size_t ofs = (size_t)m * 3;
    outNbr[ofs + 0] = v0; outNbr[ofs + 1] = v1; outNbr[ofs + 2] = v2;
    float* fp = feat + (size_t)m * 8;
    fp[0] = v0; fp[1] = v1; fp[2] = v2;
    fp[3] = q0; fp[4] = q1; fp[5] = q2;

    // ---- fused moments ----
    float a[27];
    a[0] = v0; a[1] = v1; a[2] = v2; a[3] = q0; a[4] = q1; a[5] = q2;
    {
        int idx = 6;
        #pragma unroll
        for (int t = 0; t < 6; t++)
            #pragma unroll
            for (int u = t; u < 6; u++) a[idx++] = a[t] * a[u];
    }
    #pragma unroll
    for (int off = 16; off; off >>= 1)
        #pragma unroll
        for (int t = 0; t < 27; t++)
            a[t] += __shfl_down_sync(0xffffffffu, a[t], off);
    __syncthreads();
    float* red = sdall;
    if (lane == 0)
        #pragma unroll
        for (int t = 0; t < 27; t++) red[wid * 27 + t] = a[t];
    __syncthreads();
    if (tid < 27) {
        float s = 0.f;
        #pragma unroll
        for (int w = 0; w < 8; w++) s += red[w * 27 + tid];
        atomicAdd(&gM[tid], s);
    }
}

// ---------------- persistent bf16x3 GEMM (conv2/3/4) -------------------------
template <int NWN, int CIN, bool A_FEAT, bool HAS_ACT, bool IN_MAX, bool OUT_MAX, bool WRITE_Y>
__global__ __launch_bounds__(NWN * 128, NWN == 1 ? 4 : (NWN == 2 ? 2 : 1))
void pg_k(const __nv_bfloat16* __restrict__ Wh, const __nv_bfloat16* __restrict__ Wl,
          const float* __restrict__ X, const float* __restrict__ W1,
          const float* __restrict__ gM,
          const float* __restrict__ accSin, const float* __restrict__ accQin,
          const float* __restrict__ gIn, const float* __restrict__ bIn,
          float* __restrict__ Y, float* __restrict__ catXin, float* __restrict__ catXout,
          float* __restrict__ accS, float* __restrict__ accQ)
{
    constexpr int THREADS = NWN * 128;
    constexpr int NT  = NWN * 64;
    constexpr int NKT = CIN / 64;
    constexpr int AREG = 2048 / THREADS;
    constexpr int OFF_SAL = NKT * 16384;
    constexpr int OFF_SBH = 2 * NKT * 16384;
    constexpr int OFF_SBL = OFF_SBH + NKT * NT * 128;
    constexpr int OFF_AFF = OFF_SBL + NKT * NT * 128;
    constexpr int OFF_W1  = OFF_AFF + 2 * CIN * 4;
    constexpr int OFF_XM  = OFF_W1 + (A_FEAT ? 1536 : 0);
    constexpr int OFF_ST  = OFF_XM + NKT * 256 * 4;

    extern __shared__ __align__(16) uint8_t smem[];
    uint8_t* sAh = smem;
    uint8_t* sAl = smem + OFF_SAL;
    uint8_t* sBh = smem + OFF_SBH;
    uint8_t* sBl = smem + OFF_SBL;
    float* scs  = (float*)(smem + OFF_AFF);
    float* shs  = scs + CIN;
    float* w1s  = (float*)(smem + OFF_W1);
    int*   xmax = (int*)(smem + OFF_XM);
    float* sS   = (float*)(smem + OFF_ST);
    float* sQ   = sS + 4 * NT;

    const int tid  = threadIdx.x;
    const int wid  = tid >> 5;
    const int lane = tid & 31;
    const int m_warp = wid & 3;
    const int n_warp = wid >> 2;

    const uint32_t smem_u = smem_to_u32(smem);
    const uint32_t sAh_u = smem_u;
    const uint32_t sAl_u = smem_u + OFF_SAL;
    const uint32_t sBh_u = smem_u + OFF_SBH;
    const uint32_t sBl_u = smem_u + OFF_SBL;

    const float4* Xv = (const float4*)X;
    const uint4* Whv = (const uint4*)Wh;
    const uint4* Wlv = (const uint4*)Wl;
    constexpr int cinV = CIN / 4;
    constexpr int cinW = CIN / 8;

    for (int idx = tid; idx < NKT * NT * 8; idx += THREADS) {
        int n = idx / (NKT * 8);
        int rem = idx - n * (NKT * 8);
        int kt = rem >> 3, c8 = rem & 7;
        int addr = kt * NT * 128 + n * 128 + ((c8 ^ (n & 7)) << 4);
        size_t g = (size_t)n * cinW + kt * 8 + c8;
        *(uint4*)(sBh + addr) = Whv[g];
        *(uint4*)(sBl + addr) = Wlv[g];
    }
    if (A_FEAT) {
        for (int t = tid; t < 384; t += THREADS) w1s[t] = W1[t];
        if (tid < 64) {
            int o = tid;
            float w[6];
            #pragma unroll
            for (int t = 0; t < 6; t++) w[t] = W1[o * 6 + t];
            float s = 0.f;
            #pragma unroll
            for (int t = 0; t < 6; t++) s += w[t] * gM[t];
            float mu = s * INV_MBIG;
            float qq = 0.f; int idx = 6;
            #pragma unroll
            for (int t = 0; t < 6; t++)
                #pragma unroll
                for (int u = t; u < 6; u++) {
                    float term = w[t] * w[u] * gM[idx++];
                    qq += (t == u) ? term : 2.f * term;
                }
            float var  = qq * INV_MBIG - mu * mu;
            float rstd = 1.f / sqrtf(var + BN_EPS);
            float scale = gIn[o] * rstd;
            scs[o] = scale;
            shs[o] = bIn[o] - mu * scale;
        }
    }
    if (HAS_ACT) {
        for (int ch = tid; ch < CIN; ch += THREADS)
            bn_affine(accSin[ch], accQin[ch], gIn[ch], bIn[ch], INV_MBIG, scs[ch], shs[ch]);
    }
    for (int t = tid; t < NKT * 256; t += THREADS) xmax[t] = 0;
    for (int t = tid; t < 4 * NT; t += THREADS) { sS[t] = 0.f; sQ[t] = 0.f; }
    __syncthreads();

    float4 areg[A_FEAT ? 1 : AREG];
    if (!A_FEAT) {
        int mb = blockIdx.x * 128;
        #pragma unroll
        for (int j = 0; j < AREG; j++) {
            int linear = tid + j * THREADS;
            int row = linear >> 4, ch = linear & 15;
            areg[j] = Xv[(size_t)(mb + row) * cinV + ch];
        }
    }

    for (int t = blockIdx.x; t < TILES; t += gridDim.x) {
        const int mBase = t * 128;

        if (A_FEAT) {
            #pragma unroll
            for (int j = 0; j < 16; j++) {
                int linear = tid + j * 128;
                int row = linear >> 4, ch = linear & 15;
                const float4* fr = (const float4*)(X + (size_t)(mBase + row) * 8);
                float4 fa = fr[0], fb = fr[1];
                float f0 = fa.x, f1 = fa.y, f2 = fa.z, f3 = fa.w, f4 = fb.x, f5 = fb.y;
                float4 v;
                #pragma unroll
                for (int cc = 0; cc < 4; cc++) {
                    const float* w = &w1s[(ch * 4 + cc) * 6];
                    (&v.x)[cc] = w[0]*f0 + w[1]*f1 + w[2]*f2 + w[3]*f3 + w[4]*f4 + w[5]*f5;
                }
                int cb = ch * 4;
                float4 s4 = *(const float4*)(scs + cb);
                float4 t4 = *(const float4*)(shs + cb);
                v.x = fmaxf(fmaf(v.x, s4.x, t4.x), 0.f);
                v.y = fmaxf(fmaf(v.y, s4.y, t4.y), 0.f);
                v.z = fmaxf(fmaf(v.z, s4.z, t4.z), 0.f);
                v.w = fmaxf(fmaf(v.w, s4.w, t4.w), 0.f);
                if (IN_MAX) {
                    int base = (row >> 5) * 64 + ch * 4;
                    atomicMax(&xmax[base + 0], __float_as_int(v.x));
                    atomicMax(&xmax[base + 1], __float_as_int(v.y));
                    atomicMax(&xmax[base + 2], __float_as_int(v.z));
                    atomicMax(&xmax[base + 3], __float_as_int(v.w));
                }
                float hx = __bfloat162float(__float2bfloat16(v.x));
                float hy = __bfloat162float(__float2bfloat16(v.y));
                float hz = __bfloat162float(__float2bfloat16(v.z));
                float hw = __bfloat162float(__float2bfloat16(v.w));
                int c = ch >> 1, sub = ch & 1;
                int addr = row * 128 + ((c ^ (row & 7)) << 4) + sub * 8;
                *(uint2*)(sAh + addr) = make_uint2(packbf(v.x, v.y), packbf(v.z, v.w));
                *(uint2*)(sAl + addr) = make_uint2(packbf(v.x - hx, v.y - hy), packbf(v.z - hz, v.w - hw));
            }
        } else {
            #pragma unroll
            for (int kt = 0; kt < NKT; kt++) {
                if (kt > 0) {
                    #pragma unroll
                    for (int j = 0; j < AREG; j++) {
                        int linear = tid + j * THREADS;
                        int row = linear >> 4, ch = linear & 15;
                        areg[j] = Xv[(size_t)(mBase + row) * cinV + kt * 16 + ch];
                    }
                }
                #pragma unroll
                for (int j = 0; j < AREG; j++) {
                    int linear = tid + j * THREADS;
                    int row = linear >> 4, ch = linear & 15;
                    float4 v = areg[j];
                    if (HAS_ACT) {
                        int cb = kt * 64 + ch * 4;
                        float4 s4 = *(const float4*)(scs + cb);
                        float4 t4 = *(const float4*)(shs + cb);
                        v.x = fmaxf(fmaf(v.x, s4.x, t4.x), 0.f);
                        v.y = fmaxf(fmaf(v.y, s4.y, t4.y), 0.f);
                        v.z = fmaxf(fmaf(v.z, s4.z, t4.z), 0.f);
                        v.w = fmaxf(fmaf(v.w, s4.w, t4.w), 0.f);
                    }
                    if (IN_MAX) {
                        int base = kt * 256 + (row >> 5) * 64 + ch * 4;
                        atomicMax(&xmax[base + 0], __float_as_int(v.x));
                        atomicMax(&xmax[base + 1], __float_as_int(v.y));
                        atomicMax(&xmax[base + 2], __float_as_int(v.z));
                        atomicMax(&xmax[base + 3], __float_as_int(v.w));
                    }
                    float hx = __bfloat162float(__float2bfloat16(v.x));
                    float hy = __bfloat162float(__float2bfloat16(v.y));
                    float hz = __bfloat162float(__float2bfloat16(v.z));
                    float hw = __bfloat162float(__float2bfloat16(v.w));
                    int c = ch >> 1, sub = ch & 1;
                    int addr = kt * 16384 + row * 128 + ((c ^ (row & 7)) << 4) + sub * 8;
                    *(uint2*)(sAh + addr) = make_uint2(packbf(v.x, v.y), packbf(v.z, v.w));
                    *(uint2*)(sAl + addr) = make_uint2(packbf(v.x - hx, v.y - hy), packbf(v.z - hz, v.w - hw));
                }
            }
        }
        __syncthreads();

        if (IN_MAX) {
            for (int e = tid; e < NKT * 256; e += THREADS) {
                int kt = e >> 8, p = (e >> 6) & 3, chl = e & 63;
                catXin[(size_t)(t * 4 + p) * 512 + kt * 64 + chl] = __int_as_float(xmax[e]);
                xmax[e] = 0;
            }
        }

        if (!A_FEAT) {
            int tn = t + gridDim.x;
            if (tn < TILES) {
                int mb = tn * 128;
                #pragma unroll
                for (int j = 0; j < AREG; j++) {
                    int linear = tid + j * THREADS;
                    int row = linear >> 4, ch = linear & 15;
                    areg[j] = Xv[(size_t)(mb + row) * cinV + ch];
                }
            }
        }

        float acc[2][8][4];
        #pragma unroll
        for (int mt = 0; mt < 2; mt++)
            #pragma unroll
            for (int nt = 0; nt < 8; nt++)
                #pragma unroll
                for (int v = 0; v < 4; v++) acc[mt][nt][v] = 0.f;

        #pragma unroll
        for (int kt = 0; kt < NKT; kt++) {
            const uint32_t aH = sAh_u + kt * 16384;
            const uint32_t aL = sAl_u + kt * 16384;
            const uint32_t bH = sBh_u + kt * NT * 128;
            const uint32_t bL = sBl_u + kt * NT * 128;
            #pragma unroll
            for (int ks = 0; ks < 4; ks++) {
                uint32_t ah[2][4], al[2][4];
                int chunk = 2 * ks + (lane >> 4);
                #pragma unroll
                for (int mt = 0; mt < 2; mt++) {
                    int r = m_warp * 32 + mt * 16 + (lane & 15);
                    int off = r * 128 + ((chunk ^ (r & 7)) << 4);
                    ldsm4(ah[mt], aH + off);
                    ldsm4(al[mt], aL + off);
                }
                #pragma unroll
                for (int ntp = 0; ntp < 4; ntp++) {
                    uint32_t bh[4], bl[4];
                    int r = n_warp * 64 + ntp * 16 + (lane & 15);
                    int off = r * 128 + ((chunk ^ (r & 7)) << 4);
                    ldsm4(bh, bH + off);
                    ldsm4(bl, bL + off);
                    #pragma unroll
                    for (int mt = 0; mt < 2; mt++) {
                        #pragma unroll
                        for (int nb = 0; nb < 2; nb++) {
                            float* c = acc[mt][2 * ntp + nb];
                            mma16816(c, ah[mt], bh[nb], bh[nb + 2]);
                            mma16816(c, ah[mt], bl[nb], bl[nb + 2]);
                            mma16816(c, al[mt], bh[nb], bh[nb + 2]);
                        }
                    }
                }
            }
        }

        const int q4 = lane & 3;
        #pragma unroll
        for (int nt = 0; nt < 8; nt++) {
            int col = n_warp * 64 + nt * 8 + q4 * 2;
            float se = 0.f, so = 0.f, qe = 0.f, qo = 0.f;
            #pragma unroll
            for (int mt = 0; mt < 2; mt++) {
                float* c = acc[mt][nt];
                if (WRITE_Y) {
                    int r0 = mBase + m_warp * 32 + mt * 16 + (lane >> 2);
                    *(float2*)(Y + (size_t)r0 * NT + col)       = make_float2(c[0], c[1]);
                    *(float2*)(Y + (size_t)(r0 + 8) * NT + col) = make_float2(c[2], c[3]);
                }
                se += c[0] + c[2];  so += c[1] + c[3];
                qe += c[0]*c[0] + c[2]*c[2];
                qo += c[1]*c[1] + c[3]*c[3];
            }
            if (OUT_MAX) {
                float m0 = fmaxf(fmaxf(acc[0][nt][0], acc[0][nt][2]),
                                 fmaxf(acc[1][nt][0], acc[1][nt][2]));
                float m1 = fmaxf(fmaxf(acc[0][nt][1], acc[0][nt][3]),
                                 fmaxf(acc[1][nt][1], acc[1][nt][3]));
                #pragma unroll
                for (int off = 16; off >= 4; off >>= 1) {
                    m0 = fmaxf(m0, __shfl_xor_sync(0xffffffffu, m0, off));
                    m1 = fmaxf(m1, __shfl_xor_sync(0xffffffffu, m1, off));
                }
                if (lane < 4) {
                    int pt = t * 4 + m_warp;
                    int cc = n_warp * 64 + nt * 8 + lane * 2;
                    catXout[(size_t)pt * 512 + cc]     = m0;
                    catXout[(size_t)pt * 512 + cc + 1] = m1;
                }
            }
            #pragma unroll
            for (int off = 16; off >= 4; off >>= 1) {
                se += __shfl_down_sync(0xffffffffu, se, off);
                so += __shfl_down_sync(0xffffffffu, so, off);
                qe += __shfl_down_sync(0xffffffffu, qe, off);
                qo += __shfl_down_sync(0xffffffffu, qo, off);
            }
            if (lane < 4) {
                int chl = n_warp * 64 + nt * 8 + lane * 2;
                sS[m_warp * NT + chl]     += se;
                sS[m_warp * NT + chl + 1] += so;
                sQ[m_warp * NT + chl]     += qe;
                sQ[m_warp * NT + chl + 1] += qo;
            }
        }
        __syncthreads();
    }

    for (int ch = tid; ch < NT; ch += THREADS) {
        float s = 0.f, q = 0.f;
        #pragma unroll
        for (int w = 0; w < 4; w++) { s += sS[w * NT + ch]; q += sQ[w * NT + ch]; }
        atomicAdd(&accS[ch], s);
        atomicAdd(&accQ[ch], q);
    }
}

// ---------------- 512-thread streaming GEMM (conv5) --------------------------
#define G512_SB    32768
#define G512_AFF   163840
#define G512_SMEM  168960
__global__ __launch_bounds__(512, 1)
void conv5_k(const __nv_bfloat16* __restrict__ Wh, const __nv_bfloat16* __restrict__ Wl,
             const float* __restrict__ X,
             const float* __restrict__ accSin, const float* __restrict__ accQin,
             const float* __restrict__ gIn, const float* __restrict__ bIn,
             float* __restrict__ Y, float* __restrict__ accS, float* __restrict__ accQ)
{
    constexpr int Cin = 512, Cout = 512;
    extern __shared__ __align__(16) uint8_t smem[];
    uint8_t* sAh = smem;
    uint8_t* sAl = smem + 16384;
    float* scs  = (float*)(smem + G512_AFF);
    float* shs  = scs + 512;
    float* sS   = (float*)smem;
    float* sQ   = sS + 1024;

    const int tid  = threadIdx.x;
    const int wid  = tid >> 5;
    const int lane = tid & 31;
    const int m_warp = wid & 3;
    const int n_warp = wid >> 2;
    const int mBase = blockIdx.y * 128;
    const int oBase = blockIdx.x * 256;

    const uint32_t smem_u = smem_to_u32(smem);
    const uint32_t sAh_u = smem_u;
    const uint32_t sAl_u = smem_u + 16384;

    const float4* Xv = (const float4*)X;
    const uint4* Whv = (const uint4*)Wh;
    const uint4* Wlv = (const uint4*)Wl;
    const int cinV = Cin >> 2;
    const int cinW = Cin >> 3;
    const int nkt  = Cin >> 6;

    for (int ch = tid; ch < 512; ch += 512) {
        if (ch < 256) { scs[ch] = 1.f; shs[ch] = 0.f; }
        else bn_affine(accSin[ch - 256], accQin[ch - 256], gIn[ch - 256], bIn[ch - 256],
                       INV_MBIG, scs[ch], shs[ch]);
    }

    {
        uint32_t sB0 = smem_u + G512_SB;
        #pragma unroll
        for (int j = 0; j < 4; j++) {
            int linear = tid + j * 512;
            int row = linear >> 3, ch = linear & 7;
            uint32_t addr = sB0 + row * 128 + ((ch ^ (row & 7)) << 4);
            const uint4* sh_ = &Whv[(size_t)(oBase + row) * cinW + ch];
            const uint4* sl_ = &Wlv[(size_t)(oBase + row) * cinW + ch];
            asm volatile("cp.async.cg.shared.global [%0], [%1], 16;" :: "r"(addr), "l"(sh_) : "memory");
            asm volatile("cp.async.cg.shared.global [%0], [%1], 16;" :: "r"(addr + 32768), "l"(sl_) : "memory");
        }
        CP_COMMIT();
    }
    float4 areg[4];
    #pragma unroll
    for (int j = 0; j < 4; j++) {
        int linear = tid + j * 512;
        int row = linear >> 4, ch = linear & 15;
        areg[j] = Xv[(size_t)(mBase + row) * cinV + ch];
    }
    __syncthreads();

    float acc[2][8][4];
    #pragma unroll
    for (int mt = 0; mt < 2; mt++)
        #pragma unroll
        for (int nt = 0; nt < 8; nt++)
            #pragma unroll
            for (int v = 0; v < 4; v++) acc[mt][nt][v] = 0.f;

    for (int kt = 0; kt < nkt; kt++) {
        if (kt + 1 < nkt) {
            uint32_t sBn = smem_u + G512_SB + ((kt + 1) & 1) * 65536;
            #pragma unroll
            for (int j = 0; j < 4; j++) {
                int linear = tid + j * 512;
                int row = linear >> 3, ch = linear & 7;
                uint32_t addr = sBn + row * 128 + ((ch ^ (row & 7)) << 4);
                const uint4* sh_ = &Whv[(size_t)(oBase + row) * cinW + (kt + 1) * 8 + ch];
                const uint4* sl_ = &Wlv[(size_t)(oBase + row) * cinW + (kt + 1) * 8 + ch];
                asm volatile("cp.async.cg.shared.global [%0], [%1], 16;" :: "r"(addr), "l"(sh_) : "memory");
                asm volatile("cp.async.cg.shared.global [%0], [%1], 16;" :: "r"(addr + 32768), "l"(sl_) : "memory");
            }
            CP_COMMIT();
        }

        #pragma unroll
        for (int j = 0; j < 4; j++) {
            int linear = tid + j * 512;
            int row = linear >> 4, ch = linear & 15;
            float4 v = areg[j];
            {
                int cb = kt * 64 + ch * 4;
                float4 s4 = *(const float4*)(scs + cb);
                float4 t4 = *(const float4*)(shs + cb);
                v.x = fmaxf(fmaf(v.x, s4.x, t4.x), 0.f);
                v.y = fmaxf(fmaf(v.y, s4.y, t4.y), 0.f);
                v.z = fmaxf(fmaf(v.z, s4.z, t4.z), 0.f);
                v.w = fmaxf(fmaf(v.w, s4.w, t4.w), 0.f);
            }
            float hx = __bfloat162float(__float2bfloat16(v.x));
            float hy = __bfloat162float(__float2bfloat16(v.y));
            float hz = __bfloat162float(__float2bfloat16(v.z));
            float hw = __bfloat162float(__float2bfloat16(v.w));
            int c = ch >> 1, sub = ch & 1;
            int addr = row * 128 + ((c ^ (row & 7)) << 4) + sub * 8;
            *(uint2*)(sAh + addr) = make_uint2(packbf(v.x, v.y), packbf(v.z, v.w));
            *(uint2*)(sAl + addr) = make_uint2(packbf(v.x - hx, v.y - hy), packbf(v.z - hz, v.w - hw));
        }
        if (kt + 1 < nkt) { CP_WAIT(1); } else { CP_WAIT(0); }
        __syncthreads();

        if (kt + 1 < nkt) {
            #pragma unroll
            for (int j = 0; j < 4; j++) {
                int linear = tid + j * 512;
                int row = linear >> 4, ch = linear & 15;
                areg[j] = Xv[(size_t)(mBase + row) * cinV + (kt + 1) * 16 + ch];
            }
        }

        {
            const uint32_t sBh_u = smem_u + G512_SB + (kt & 1) * 65536;
            const uint32_t sBl_u = sBh_u + 32768;
            #pragma unroll
            for (int ks = 0; ks < 4; ks++) {
                uint32_t ah[2][4], al[2][4];
                int chunk = 2 * ks + (lane >> 4);
                #pragma unroll
                for (int mt = 0; mt < 2; mt++) {
                    int r = m_warp * 32 + mt * 16 + (lane & 15);
                    int off = r * 128 + ((chunk ^ (r & 7)) << 4);
                    ldsm4(ah[mt], sAh_u + off);
                    ldsm4(al[mt], sAl_u + off);
                }
                #pragma unroll
                for (int ntp = 0; ntp < 4; ntp++) {
                    uint32_t bh[4], bl[4];
                    int r = n_warp * 64 + ntp * 16 + (lane & 15);
                    int off = r * 128 + ((chunk ^ (r & 7)) << 4);
                    ldsm4(bh, sBh_u + off);
                    ldsm4(bl, sBl_u + off);
                    #pragma unroll
                    for (int mt = 0; mt < 2; mt++) {
                        #pragma unroll
                        for (int nb = 0; nb < 2; nb++) {
                            float* c = acc[mt][2 * ntp + nb];
                            mma16816(c, ah[mt], bh[nb], bh[nb + 2]);
                            mma16816(c, ah[mt], bl[nb], bl[nb + 2]);
                            mma16816(c, al[mt], bh[nb], bh[nb + 2]);
                        }
                    }
                }
            }
        }
        __syncthreads();
    }

    const int q4 = lane & 3;
    #pragma unroll
    for (int nt = 0; nt < 8; nt++) {
        int col = oBase + n_warp * 64 + nt * 8 + q4 * 2;
        float se = 0.f, so = 0.f, qe = 0.f, qo = 0.f;
        #pragma unroll
        for (int mt = 0; mt < 2; mt++) {
            float* c = acc[mt][nt];
            int r0 = mBase + m_warp * 32 + mt * 16 + (lane >> 2);
            *(float2*)(Y + (size_t)r0 * Cout + col)       = make_float2(c[0], c[1]);
            *(float2*)(Y + (size_t)(r0 + 8) * Cout + col) = make_float2(c[2], c[3]);
            se += c[0] + c[2];  so += c[1] + c[3];
            qe += c[0]*c[0] + c[2]*c[2];
            qo += c[1]*c[1] + c[3]*c[3];
        }
        #pragma unroll
        for (int off = 16; off >= 4; off >>= 1) {
            se += __shfl_down_sync(0xffffffffu, se, off);
            so += __shfl_down_sync(0xffffffffu, so, off);
            qe += __shfl_down_sync(0xffffffffu, qe, off);
            qo += __shfl_down_sync(0xffffffffu, qo, off);
        }
        if (lane < 4) {
            int chl = n_warp * 64 + nt * 8 + lane * 2;
            sS[m_warp * 256 + chl]     = se;
            sS[m_warp * 256 + chl + 1] = so;
            sQ[m_warp * 256 + chl]     = qe;
            sQ[m_warp * 256 + chl + 1] = qo;
        }
    }
    __syncthreads();
    if (tid < 256) {
        float s = 0.f, q = 0.f;
        #pragma unroll
        for (int w = 0; w < 4; w++) { s += sS[w * 256 + tid]; q += sQ[w * 256 + tid]; }
        atomicAdd(&accS[oBase + tid], s);
        atomicAdd(&accQ[oBase + tid], q);
    }
}

// ---------------- output transpose + inline affine5 --------------------------
__global__ void out_t(const float* __restrict__ y5,
                      const float* __restrict__ accS, const float* __restrict__ accQ,
                      const float* __restrict__ g, const float* __restrict__ bta,
                      float* __restrict__ out)
{
    __shared__ float ts[32][33];
    int tx = threadIdx.x, ty = threadIdx.y;
    int n0 = blockIdx.x * 32, ch0 = blockIdx.y * 32, b = blockIdx.z;
    int ch = ch0 + tx;
    float s, t;
    bn_affine(accS[ch], accQ[ch], g[ch], bta[ch], INV_MSML, s, t);
    #pragma unroll
    for (int r = 0; r < 4; r++) {
        int nl = ty * 4 + r;
        int m = b * NPTS + n0 + nl;
        float v = y5[(size_t)m * 512 + ch];
        ts[nl][tx] = fmaxf(fmaf(v, s, t), 0.f);
    }
    __syncthreads();
    #pragma unroll
    for (int r = 0; r < 4; r++) {
        int chl = ty * 4 + r;
        out[(size_t)b * (512 * NPTS) + (size_t)(ch0 + chl) * NPTS + n0 + tx] = ts[tx][chl];
    }
}

// ---------------- launcher ----------------
extern "C" void kernel_launch(void* const* d_in, const int* in_sizes, int n_in,
                              void* d_out, int out_size)
{
    const float* x  = (const float*)d_in[0];
    const float* W1 = (const float*)d_in[1];
    const float* g1 = (const float*)d_in[2];
    const float* b1 = (const float*)d_in[3];
    const float* W2 = (const float*)d_in[4];
    const float* g2 = (const float*)d_in[5];
    const float* b2 = (const float*)d_in[6];
    const float* W3 = (const float*)d_in[7];
    const float* g3 = (const float*)d_in[8];
    const float* b3 = (const float*)d_in[9];
    const float* W4 = (const float*)d_in[10];
    const float* g4 = (const float*)d_in[11];
    const float* b4 = (const float*)d_in[12];
    const float* W5 = (const float*)d_in[13];
    const float* g5 = (const float*)d_in[14];
    const float* b5 = (const float*)d_in[15];

    float* out    = (float*)d_out;
    float* outIdx = out + IDX_OFF;
    float* outNbr = out + NBR_OFF;

    float *feat, *y2, *y3, *cat, *y5, *accS, *accQ, *gM;
    __nv_bfloat16 *w2h, *w2l, *w3h, *w3l, *w4h, *w4l, *w5h, *w5l;
    cudaGetSymbolAddress((void**)&feat, g_feat);
    cudaGetSymbolAddress((void**)&y2,   g_y2);
    cudaGetSymbolAddress((void**)&y3,   g_y3);
    cudaGetSymbolAddress((void**)&cat,  g_cat);
    cudaGetSymbolAddress((void**)&y5,   g_y5);
    cudaGetSymbolAddress((void**)&w2h,  g_w2h);
    cudaGetSymbolAddress((void**)&w2l,  g_w2l);
    cudaGetSymbolAddress((void**)&w3h,  g_w3h);
    cudaGetSymbolAddress((void**)&w3l,  g_w3l);
    cudaGetSymbolAddress((void**)&w4h,  g_w4h);
    cudaGetSymbolAddress((void**)&w4l,  g_w4l);
    cudaGetSymbolAddress((void**)&w5h,  g_w5h);
    cudaGetSymbolAddress((void**)&w5l,  g_w5l);
    cudaGetSymbolAddress((void**)&accS, g_accS);
    cudaGetSymbolAddress((void**)&accQ, g_accQ);
    cudaGetSymbolAddress((void**)&gM,   g_M);

    auto* p2 = pg_k<1, 64,  true,  false, true,  false, true >;
    auto* p3 = pg_k<2, 64,  false, true,  true,  false, true >;
    auto* p4 = pg_k<4, 128, false, true,  true,  true,  false>;
    const int SM2 = 54272, SM3 = 71168, SM4 = 207872;
    cudaFuncSetAttribute(knn_kernel, cudaFuncAttributeMaxDynamicSharedMemorySize, KNN_SMEM);
    cudaFuncSetAttribute(p2, cudaFuncAttributeMaxDynamicSharedMemorySize, SM2);
    cudaFuncSetAttribute(p3, cudaFuncAttributeMaxDynamicSharedMemorySize, SM3);
    cudaFuncSetAttribute(p4, cudaFuncAttributeMaxDynamicSharedMemorySize, SM4);
    cudaFuncSetAttribute(conv5_k, cudaFuncAttributeMaxDynamicSharedMemorySize, G512_SMEM);

    // launch 0: weight convert (w2,w3) + zero accumulators
    wconvA_zero_k<<<(12288 + 255) / 256, 256>>>(W2, W3, w2h, w2l, w3h, w3l,
                                                accS, accQ, gM);
    // launch 1: kNN (+ moments)
    knn_kernel<<<2048, 256, KNN_SMEM>>>(x, outIdx, outNbr, feat, gM);
    // launch 2: weight convert (w4,w5)
    wconvB_k<<<(294912 + 255) / 256, 256>>>(W4, W5, w4h, w4l, w5h, w5l);

    // launch 3 (profiled by ncu): conv2 persistent
    p2<<<592, 128, SM2>>>(w2h, w2l, feat, W1, gM,
                          nullptr, nullptr, g1, b1,
                          y2, cat + 0, nullptr, accS + 64, accQ + 64);

    // conv3 (persistent)
    p3<<<296, 256, SM3>>>(w3h, w3l, y2, nullptr, nullptr,
                          accS + 64, accQ + 64, g2, b2,
                          y3, cat + 64, nullptr, accS + 128, accQ + 128);

    // conv4 (persistent)
    p4<<<148, 512, SM4>>>(w4h, w4l, y3, nullptr, nullptr,
                          accS + 128, accQ + 128, g3, b3,
                          nullptr, cat + 128, cat + 256, accS + 256, accQ + 256);

    // conv5 (streaming, mixed affine4 on x4 half)
    conv5_k<<<dim3(2, MSML / 128), 512, G512_SMEM>>>(
        w5h, w5l, cat, accS + 256, accQ + 256, g4, b4,
        y5, accS + 512, accQ + 512);

    out_t<<<dim3(NPTS / 32, 16, BATCH), dim3(32, 8)>>>(
        y5, accS + 512, accQ + 512, g5, b5, out);
}